// round 2
// baseline (speedup 1.0000x reference)
#include <cuda_runtime.h>
#include <math.h>

// Problem constants
#define BB   8
#define TT   10
#define HH   64
#define WW   64
#define HID  64
#define PRED 10
#define PIX  (HH*WW)            // 4096
#define NST  (BB*HID*PIX)       // 2,097,152 floats per state buffer

// ---------------------------------------------------------------------------
// Scratch (device globals; no runtime allocation allowed)
// ---------------------------------------------------------------------------
__device__ float g_eh0[2*NST];
__device__ float g_ec0[NST];
__device__ float g_eh1[2*NST];
__device__ float g_ec1[NST];
__device__ float g_dh0[2*NST];
__device__ float g_dc0[NST];
__device__ float g_dh1[2*NST];
__device__ float g_dc1[NST];

#define WT_BIG (HID*HID*9*4)    // 147456
__device__ __align__(16) float g_wt_e0x[HID*1*9*4];
__device__ __align__(16) float g_wt_e0h[WT_BIG];
__device__ __align__(16) float g_wt_e1x[WT_BIG];
__device__ __align__(16) float g_wt_e1h[WT_BIG];
__device__ __align__(16) float g_wt_d0x[WT_BIG];
__device__ __align__(16) float g_wt_d0h[WT_BIG];
__device__ __align__(16) float g_wt_d1x[WT_BIG];
__device__ __align__(16) float g_wt_d1h[WT_BIG];

// ---------------------------------------------------------------------------
// Weight transform: (4*HID, Cin, 3, 3) -> [co][cin][tap][gate] (gate innermost,
// 16B groups so the cell kernel fetches 4 gate weights as one LDG.128 that is
// directly usable as two packed f32x2 operands)
// ---------------------------------------------------------------------------
__global__ void transform_w_kernel(const float* __restrict__ w,
                                   float* __restrict__ wt, int cin)
{
    int i = blockIdx.x * blockDim.x + threadIdx.x;
    int n = HID * cin * 9 * 4;
    if (i >= n) return;
    int gate = i & 3;
    int rest = i >> 2;
    int tap  = rest % 9;
    int rc   = rest / 9;
    int cc   = rc % cin;
    int co   = rc / cin;
    wt[i] = w[((gate*HID + co)*cin + cc)*9 + tap];
}

__device__ __forceinline__ float sigf(float x) { return 1.f / (1.f + expf(-x)); }

// ---- packed fp32x2 helpers (Blackwell f32x2 pipe; ptxas never auto-emits) ----
__device__ __forceinline__ unsigned long long packdup(float a) {
    unsigned long long r;
    asm("mov.b64 %0, {%1, %1};" : "=l"(r) : "f"(a));
    return r;
}
__device__ __forceinline__ void unpack2(unsigned long long v, float& lo, float& hi) {
    asm("mov.b64 {%0, %1}, %2;" : "=f"(lo), "=f"(hi) : "l"(v));
}
__device__ __forceinline__ void fma2(unsigned long long& d,
                                     unsigned long long a, unsigned long long b) {
    asm("fma.rn.f32x2 %0, %1, %2, %0;" : "+l"(d) : "l"(a), "l"(b));
}

// ---------------------------------------------------------------------------
// Fused ConvLSTM cell using packed f32x2 FMAs.
// Block: 128 threads. Tile: 32 wide x 16 tall. Thread: 4 rows x 4 co x 4 gates
// (accumulated as 4co x 2 gate-pairs x 4 rows of f32x2).
// gridDim = (8 tiles, B, HID/4). Double-buffered smem input tile.
// ---------------------------------------------------------------------------
template<int CIN>
__global__ void __launch_bounds__(128)
cell_kernel(const float* __restrict__ xin, int xbs,
            const float* __restrict__ wxt,
            const float* __restrict__ hin,
            const float* __restrict__ wht,
            const float* __restrict__ Wc,
            const float* __restrict__ bias,
            const float* __restrict__ cst,
            float* __restrict__ hout,
            float* __restrict__ cout)
{
    const int tid  = threadIdx.x;
    const int tx   = tid & 31;        // 0..31 (x within tile)
    const int tyq  = tid >> 5;        // 0..3  (row-quad)
    const int tile = blockIdx.x;      // 0..7
    const int x0   = (tile & 1) * 32;
    const int y0   = (tile >> 1) * 16;
    const int b    = blockIdx.y;
    const int co0  = blockIdx.z * 4;

    __shared__ float s_in[2][18][34];  // double-buffered halo tile

    const int NCH = CIN + HID;
    const float* xb = xin + (size_t)b * xbs;
    const float* hb = hin + (size_t)b * (HID * PIX);
    const ulonglong2* wx2 = (const ulonglong2*)wxt;
    const ulonglong2* wh2 = (const ulonglong2*)wht;

    // acc[co][gatepair][row]: f32x2 = (gate_lo, gate_hi)
    unsigned long long acc[4][2][4];
    #pragma unroll
    for (int a = 0; a < 4; a++)
        #pragma unroll
        for (int p = 0; p < 2; p++)
            #pragma unroll
            for (int r = 0; r < 4; r++) acc[a][p][r] = 0ull;

    // tile fill helper (lambda to keep registers scoped)
    auto fill = [&](int buf, int c) {
        const float* plane = (c < CIN) ? (xb + c * PIX) : (hb + (c - CIN) * PIX);
        #pragma unroll
        for (int it = 0; it < 5; it++) {
            int idx = tid + it * 128;
            if (idx < 18 * 34) {
                int ry = idx / 34, rx = idx - ry * 34;
                int gy = y0 + ry - 1, gx = x0 + rx - 1;
                float v = 0.f;
                if ((unsigned)gy < (unsigned)HH && (unsigned)gx < (unsigned)WW)
                    v = plane[gy * WW + gx];
                s_in[buf][ry][rx] = v;
            }
        }
    };

    fill(0, 0);

    for (int c = 0; c < NCH; c++) {
        __syncthreads();                       // fill(c) visible; compute(c-1) done
        if (c + 1 < NCH) fill((c + 1) & 1, c + 1);

        const ulonglong2* wp;
        size_t stride;
        if (c < CIN) { wp = wx2 + ((size_t)co0 * CIN + c) * 9; stride = (size_t)CIN * 9; }
        else         { wp = wh2 + ((size_t)co0 * HID + (c - CIN)) * 9; stride = (size_t)HID * 9; }

        const float (*buf)[34] = s_in[c & 1];

        #pragma unroll
        for (int tap = 0; tap < 9; tap++) {
            const int dy = tap / 3, dx = tap - dy * 3;
            ulonglong2 w0 = __ldg(wp + tap);
            ulonglong2 w1 = __ldg(wp + stride + tap);
            ulonglong2 w2 = __ldg(wp + 2 * stride + tap);
            ulonglong2 w3 = __ldg(wp + 3 * stride + tap);
            #pragma unroll
            for (int r = 0; r < 4; r++) {
                unsigned long long vv = packdup(buf[tyq * 4 + r + dy][tx + dx]);
                fma2(acc[0][0][r], vv, w0.x);
                fma2(acc[0][1][r], vv, w0.y);
                fma2(acc[1][0][r], vv, w1.x);
                fma2(acc[1][1][r], vv, w1.y);
                fma2(acc[2][0][r], vv, w2.x);
                fma2(acc[2][1][r], vv, w2.y);
                fma2(acc[3][0][r], vv, w3.x);
                fma2(acc[3][1][r], vv, w3.y);
            }
        }
    }

    // LSTM pointwise epilogue
    #pragma unroll
    for (int ci = 0; ci < 4; ci++) {
        const int co = co0 + ci;
        #pragma unroll
        for (int r = 0; r < 4; r++) {
            int y = y0 + tyq * 4 + r;
            int x = x0 + tx;
            int base = co * PIX + y * WW + x;    // within (HID,H,W)
            int bb   = b * HID * PIX + base;     // within (B,HID,H,W)
            float cold = cst[bb];
            float a_i, a_f, a_g, a_o;
            unpack2(acc[ci][0][r], a_i, a_f);
            unpack2(acc[ci][1][r], a_g, a_o);
            float p0 = a_i + Wc[0*HID*PIX + base] * cold + bias[0*HID*PIX + base];
            float p1 = a_f + Wc[1*HID*PIX + base] * cold + bias[1*HID*PIX + base];
            float p2 = a_g + Wc[2*HID*PIX + base] * cold + bias[2*HID*PIX + base];
            float p3 = a_o + Wc[3*HID*PIX + base] * cold + bias[3*HID*PIX + base];
            float ig = sigf(p0);
            float fg = sigf(p1);
            float gg = tanhf(p2);
            float og = sigf(p3);
            float cn = fg * cold + ig * gg;
            cout[bb] = cn;
            hout[bb] = og * tanhf(cn);
        }
    }
}

// ---------------------------------------------------------------------------
// Final 3x3 conv (HID->1) + bias + sigmoid, per decoded frame
// out layout: (B, PRED, 1, H, W)
// ---------------------------------------------------------------------------
__global__ void __launch_bounds__(256)
final_conv_kernel(const float* __restrict__ h1,
                  const float* __restrict__ fw,
                  const float* __restrict__ fb,
                  float* __restrict__ out, int t)
{
    __shared__ float s_w[HID * 9];
    int tid = threadIdx.x;
    for (int i = tid; i < HID * 9; i += 256) s_w[i] = fw[i];
    __syncthreads();

    int pix = blockIdx.x * 256 + tid;   // 0..4095
    int b   = blockIdx.y;
    int y = pix >> 6, x = pix & 63;
    const float* hb = h1 + (size_t)b * HID * PIX;
    float sum = fb[0];
    for (int c = 0; c < HID; c++) {
        const float* plane = hb + c * PIX;
        #pragma unroll
        for (int tap = 0; tap < 9; tap++) {
            int dy = tap / 3 - 1, dx = tap % 3 - 1;
            int gy = y + dy, gx = x + dx;
            if ((unsigned)gy < 64u && (unsigned)gx < 64u)
                sum += s_w[c * 9 + tap] * plane[gy * 64 + gx];
        }
    }
    out[(size_t)b * (PRED * PIX) + t * PIX + pix] = 1.f / (1.f + expf(-sum));
}

// ---------------------------------------------------------------------------
// Launch: fully static sequence of kernels; graph-capturable, alloc-free.
// ---------------------------------------------------------------------------
extern "C" void kernel_launch(void* const* d_in, const int* in_sizes, int n_in,
                              void* d_out, int out_size)
{
    const float* x    = (const float*)d_in[0];
    const float* e0Wx = (const float*)d_in[1];
    const float* e0Wh = (const float*)d_in[2];
    const float* e0Wc = (const float*)d_in[3];
    const float* e0b  = (const float*)d_in[4];
    const float* e1Wx = (const float*)d_in[5];
    const float* e1Wh = (const float*)d_in[6];
    const float* e1Wc = (const float*)d_in[7];
    const float* e1b  = (const float*)d_in[8];
    const float* d0Wx = (const float*)d_in[9];
    const float* d0Wh = (const float*)d_in[10];
    const float* d0Wc = (const float*)d_in[11];
    const float* d0b  = (const float*)d_in[12];
    const float* d1Wx = (const float*)d_in[13];
    const float* d1Wh = (const float*)d_in[14];
    const float* d1Wc = (const float*)d_in[15];
    const float* d1b  = (const float*)d_in[16];
    const float* finw = (const float*)d_in[17];
    const float* finb = (const float*)d_in[18];
    float* out = (float*)d_out;

    float *eh0, *ec0, *eh1, *ec1, *dh0, *dc0, *dh1, *dc1;
    cudaGetSymbolAddress((void**)&eh0, g_eh0);
    cudaGetSymbolAddress((void**)&ec0, g_ec0);
    cudaGetSymbolAddress((void**)&eh1, g_eh1);
    cudaGetSymbolAddress((void**)&ec1, g_ec1);
    cudaGetSymbolAddress((void**)&dh0, g_dh0);
    cudaGetSymbolAddress((void**)&dc0, g_dc0);
    cudaGetSymbolAddress((void**)&dh1, g_dh1);
    cudaGetSymbolAddress((void**)&dc1, g_dc1);

    float *wte0x, *wte0h, *wte1x, *wte1h, *wtd0x, *wtd0h, *wtd1x, *wtd1h;
    cudaGetSymbolAddress((void**)&wte0x, g_wt_e0x);
    cudaGetSymbolAddress((void**)&wte0h, g_wt_e0h);
    cudaGetSymbolAddress((void**)&wte1x, g_wt_e1x);
    cudaGetSymbolAddress((void**)&wte1h, g_wt_e1h);
    cudaGetSymbolAddress((void**)&wtd0x, g_wt_d0x);
    cudaGetSymbolAddress((void**)&wtd0h, g_wt_d0h);
    cudaGetSymbolAddress((void**)&wtd1x, g_wt_d1x);
    cudaGetSymbolAddress((void**)&wtd1h, g_wt_d1h);

    // Weight transforms (cheap, once per replay)
    const int nsmall = HID * 1 * 9 * 4;
    transform_w_kernel<<<(nsmall + 255) / 256, 256>>>(e0Wx, wte0x, 1);
    transform_w_kernel<<<(WT_BIG + 255) / 256, 256>>>(e0Wh, wte0h, HID);
    transform_w_kernel<<<(WT_BIG + 255) / 256, 256>>>(e1Wx, wte1x, HID);
    transform_w_kernel<<<(WT_BIG + 255) / 256, 256>>>(e1Wh, wte1h, HID);
    transform_w_kernel<<<(WT_BIG + 255) / 256, 256>>>(d0Wx, wtd0x, HID);
    transform_w_kernel<<<(WT_BIG + 255) / 256, 256>>>(d0Wh, wtd0h, HID);
    transform_w_kernel<<<(WT_BIG + 255) / 256, 256>>>(d1Wx, wtd1x, HID);
    transform_w_kernel<<<(WT_BIG + 255) / 256, 256>>>(d1Wh, wtd1h, HID);

    // Zero initial states
    size_t sb = (size_t)NST * sizeof(float);
    cudaMemsetAsync(eh0, 0, sb);
    cudaMemsetAsync(ec0, 0, sb);
    cudaMemsetAsync(eh1, 0, sb);
    cudaMemsetAsync(ec1, 0, sb);
    cudaMemsetAsync(dh0, 0, sb);
    cudaMemsetAsync(dc0, 0, sb);
    cudaMemsetAsync(dh1, 0, sb);
    cudaMemsetAsync(dc1, 0, sb);

    dim3 grid(8, BB, HID / 4), blk(128);

    // Encoder: 10 steps, 2 layers
    for (int t = 0; t < TT; t++) {
        int r = t & 1, w = r ^ 1;
        cell_kernel<1><<<grid, blk>>>(x + t * PIX, TT * PIX, wte0x,
                                      eh0 + r * NST, wte0h,
                                      e0Wc, e0b, ec0,
                                      eh0 + w * NST, ec0);
        cell_kernel<HID><<<grid, blk>>>(eh0 + w * NST, HID * PIX, wte1x,
                                        eh1 + r * NST, wte1h,
                                        e1Wc, e1b, ec1,
                                        eh1 + w * NST, ec1);
    }
    // After t=9 (r=1,w=0): final encoder h1 lives in eh1[0]

    // Decoder: 10 steps, 2 layers + final conv per step
    for (int t = 0; t < PRED; t++) {
        int r = t & 1, w = r ^ 1;
        const float* s = (t == 0) ? eh1 : (dh1 + r * NST);
        cell_kernel<HID><<<grid, blk>>>(s, HID * PIX, wtd0x,
                                        dh0 + r * NST, wtd0h,
                                        d0Wc, d0b, dc0,
                                        dh0 + w * NST, dc0);
        cell_kernel<HID><<<grid, blk>>>(dh0 + w * NST, HID * PIX, wtd1x,
                                        dh1 + r * NST, wtd1h,
                                        d1Wc, d1b, dc1,
                                        dh1 + w * NST, dc1);
        final_conv_kernel<<<dim3(16, BB), 256>>>(dh1 + w * NST, finw, finb, out, t);
    }
}

// round 4
// speedup vs baseline: 3.3664x; 3.3664x over previous
#include <cuda_runtime.h>
#include <cuda_bf16.h>
#include <math.h>

// Problem constants
#define BB   8
#define TT   10
#define HH   64
#define WW   64
#define HID  64
#define PRED 10
#define PIX  (HH*WW)              // 4096
#define NST  (BB*HID*PIX)         // 2,097,152 floats per state tensor
#define NPX  (BB*PIX)             // 32768 pixels total
#define TROW 66                   // padded row (1px halo each side)
#define TSZ  (BB*TROW*TROW*HID)   // elems in one padded transposed tensor (hi or lo)
#define WSZ  (9*256*64)           // elems per split-half of a transformed weight

// ---------------------------------------------------------------------------
// Static scratch (no runtime allocation allowed)
// ---------------------------------------------------------------------------
__device__ float g_h[4][NST];     // eh0, eh1, dh0, dh1
__device__ float g_c[4][NST];     // ec0, ec1, dc0, dc1
__device__ float g_G[256 * NPX];  // gate pre-activations for current cell
__device__ __align__(16) __nv_bfloat16 g_T[4][2 * TSZ];   // transposed+split h (hi, lo)
__device__ __align__(16) __nv_bfloat16 g_W[7][2 * WSZ];   // split weights [hi|lo][tap][m][k]

// ---------------------------------------------------------------------------
// Weight transform+split: w (256, 64, 3, 3) -> wt[{hi,lo}][tap][m][k] bf16
// ---------------------------------------------------------------------------
__global__ void wsplit_kernel(const float* __restrict__ w, __nv_bfloat16* __restrict__ wt)
{
    int i = blockIdx.x * blockDim.x + threadIdx.x;   // over 9*256*64
    if (i >= WSZ) return;
    int c   = i & 63;
    int m   = (i >> 6) & 255;
    int tap = i >> 14;
    float v = w[(m * 64 + c) * 9 + tap];
    __nv_bfloat16 hi = __float2bfloat16(v);
    __nv_bfloat16 lo = __float2bfloat16(v - __bfloat162float(hi));
    wt[i] = hi;
    wt[WSZ + i] = lo;
}

// ---------------------------------------------------------------------------
// Transpose + split: h fp32 (B,64,64,64) -> T bf16 [b][py][px][c] padded 66x66
// (halos stay zero: buffers are memset at replay start, only interior written)
// ---------------------------------------------------------------------------
__global__ void __launch_bounds__(256)
transpose_split_kernel(const float* __restrict__ h, __nv_bfloat16* __restrict__ T)
{
    __shared__ float s[64][65];
    int y = blockIdx.x, b = blockIdx.y, tid = threadIdx.x;
    for (int i = tid; i < 4096; i += 256) {
        int c = i >> 6, x = i & 63;
        s[c][x] = h[((b * 64 + c) << 12) + (y << 6) + x];
    }
    __syncthreads();
    size_t rowbase = (((size_t)b * TROW + (y + 1)) * TROW + 1) * 64;
    for (int i = tid; i < 4096; i += 256) {
        int c = i & 63, x = i >> 6;
        float v = s[c][x];
        __nv_bfloat16 hi = __float2bfloat16(v);
        __nv_bfloat16 lo = __float2bfloat16(v - __bfloat162float(hi));
        T[rowbase + (size_t)x * 64 + c] = hi;
        T[TSZ + rowbase + (size_t)x * 64 + c] = lo;
    }
}

// ---------------------------------------------------------------------------
// bf16 m16n8k16 mma wrapper
// ---------------------------------------------------------------------------
__device__ __forceinline__ void mma16816(float* d, const unsigned* a,
                                         unsigned b0, unsigned b1)
{
    asm("mma.sync.aligned.m16n8k16.row.col.f32.bf16.bf16.f32 "
        "{%0,%1,%2,%3}, {%4,%5,%6,%7}, {%8,%9}, {%0,%1,%2,%3};"
        : "+f"(d[0]), "+f"(d[1]), "+f"(d[2]), "+f"(d[3])
        : "r"(a[0]), "r"(a[1]), "r"(a[2]), "r"(a[3]), "r"(b0), "r"(b1));
}

// SMEM layout (bf16 units); stride 72 avoids bank conflicts, keeps 16B align.
#define BSTR 72
#define BROWS (6*TROW)            // 396 padded pixels (6 rows x 66)
#define SB_HALF (BROWS*BSTR)
#define SA_HALF (128*BSTR)
#define SMEM_ELEMS (2*SB_HALF + 2*SA_HALF)
#define SMEM_BYTES (SMEM_ELEMS*2)

// ---------------------------------------------------------------------------
// Conv-as-GEMM via tensor cores. Per CTA: M=128 (of 256 gate-channels),
// N=256 (4 image rows of one batch). K = nsrc x 9 taps x 64 cin, bf16 2-term
// split -> 3 mma products per k-chunk.
// grid (128 Ntiles, 2 Mtiles), 512 threads (16 warps: 2 M x 8 N).
// ---------------------------------------------------------------------------
__global__ void __launch_bounds__(512)
conv_mma_kernel(const __nv_bfloat16* __restrict__ T0,
                const __nv_bfloat16* __restrict__ W0,
                const __nv_bfloat16* __restrict__ T1,
                const __nv_bfloat16* __restrict__ W1,
                int nsrc,
                float* __restrict__ G)
{
    extern __shared__ __align__(16) __nv_bfloat16 sm[];
    __nv_bfloat16* sB = sm;                 // [2][396][72]
    __nv_bfloat16* sA = sm + 2 * SB_HALF;   // [2][128][72]

    const int tid  = threadIdx.x;
    const int lane = tid & 31;
    const int warp = tid >> 5;
    const int wm   = warp >> 3;       // 0..1 -> m_warp = wm*64
    const int wn   = warp & 7;        // 0..7
    const int gr   = lane >> 2;       // 0..7
    const int ci   = lane & 3;        // 0..3
    const int nt   = blockIdx.x;      // 0..127
    const int mt   = blockIdx.y;      // 0..1
    const int b    = nt >> 4;
    const int y0   = (nt & 15) << 2;  // first of 4 output rows

    float acc[4][4][4];
    #pragma unroll
    for (int mi = 0; mi < 4; mi++)
        #pragma unroll
        for (int ni = 0; ni < 4; ni++)
            #pragma unroll
            for (int r = 0; r < 4; r++) acc[mi][ni][r] = 0.f;

    for (int s = 0; s < nsrc; s++) {
        const __nv_bfloat16* T = s ? T1 : T0;
        const __nv_bfloat16* W = s ? W1 : W0;

        __syncthreads();   // prior mma reads of sB done
        // fill B tile: 6 padded rows x 66 px x 64 ch, hi & lo halves
        for (int i = tid; i < BROWS * 8 * 2; i += 512) {
            int h = i / (BROWS * 8);
            int j = i % (BROWS * 8);
            int p = j >> 3, v = j & 7;
            int r = p / TROW, px = p % TROW;
            const __nv_bfloat16* src =
                T + (size_t)h * TSZ + ((((size_t)b * TROW) + (y0 + r)) * TROW + px) * 64 + v * 8;
            *(uint4*)(sB + h * SB_HALF + p * BSTR + v * 8) = *(const uint4*)src;
        }

        for (int tap = 0; tap < 9; tap++) {
            const int dy = tap / 3, dx = tap - dy * 3;
            __syncthreads();   // prior tap's mma reads of sA done; B visible
            // fill A tile: 2 halves x 128 m x 64 k  (= 2048 uint4 vectors)
            for (int i = tid; i < 2048; i += 512) {
                int h = i >> 10, j = i & 1023;
                int m = j >> 3, v = j & 7;
                const __nv_bfloat16* src =
                    W + ((size_t)(h * 9 + tap) * 256 + mt * 128 + m) * 64 + v * 8;
                *(uint4*)(sA + h * SA_HALF + m * BSTR + v * 8) = *(const uint4*)src;
            }
            __syncthreads();

            const int ylocal = wn >> 1;
            const int xlocal = (wn & 1) * 32;
            const int prow   = (ylocal + dy) * TROW + xlocal + dx;

            #pragma unroll
            for (int prod = 0; prod < 3; prod++) {
                const __nv_bfloat16* pA = sA + (prod == 2 ? SA_HALF : 0);
                const __nv_bfloat16* pB = sB + (prod == 1 ? SB_HALF : 0);
                #pragma unroll
                for (int ks = 0; ks < 4; ks++) {
                    const int k0 = ks * 16 + 2 * ci;
                    unsigned a[4][4];
                    #pragma unroll
                    for (int mi = 0; mi < 4; mi++) {
                        const __nv_bfloat16* base =
                            pA + (wm * 64 + mi * 16 + gr) * BSTR + k0;
                        a[mi][0] = *(const unsigned*)(base);
                        a[mi][1] = *(const unsigned*)(base + 8 * BSTR);
                        a[mi][2] = *(const unsigned*)(base + 8);
                        a[mi][3] = *(const unsigned*)(base + 8 * BSTR + 8);
                    }
                    #pragma unroll
                    for (int ni = 0; ni < 4; ni++) {
                        const __nv_bfloat16* bb =
                            pB + (prow + ni * 8 + gr) * BSTR + k0;
                        unsigned b0 = *(const unsigned*)(bb);
                        unsigned b1 = *(const unsigned*)(bb + 8);
                        #pragma unroll
                        for (int mi = 0; mi < 4; mi++)
                            mma16816(acc[mi][ni], a[mi], b0, b1);
                    }
                }
            }
        }
    }

    // store pre-activations to G [m=256][n=32768]
    const int nb = b * 4096 + y0 * 64 + wn * 32;
    #pragma unroll
    for (int mi = 0; mi < 4; mi++) {
        #pragma unroll
        for (int ni = 0; ni < 4; ni++) {
            int m0 = mt * 128 + wm * 64 + mi * 16 + gr;
            int n0 = nb + ni * 8 + 2 * ci;
            float2 v01 = make_float2(acc[mi][ni][0], acc[mi][ni][1]);
            float2 v23 = make_float2(acc[mi][ni][2], acc[mi][ni][3]);
            *(float2*)&G[(size_t)m0 * NPX + n0] = v01;
            *(float2*)&G[(size_t)(m0 + 8) * NPX + n0] = v23;
        }
    }
}

// ---------------------------------------------------------------------------
// Pointwise LSTM update: pre = G + Wc*c + b (+ optional cin=1 x-conv for enc0)
// ---------------------------------------------------------------------------
__device__ __forceinline__ float sigf(float x) { return 1.f / (1.f + expf(-x)); }

__global__ void __launch_bounds__(256)
pointwise_kernel(const float* __restrict__ G,
                 const float* __restrict__ Wc,
                 const float* __restrict__ bias,
                 const float* __restrict__ cin_,
                 float* __restrict__ hout,
                 float* __restrict__ cout,
                 const float* __restrict__ x,     // nullable (enc0 only)
                 const float* __restrict__ wx9,   // (256,1,3,3) raw, enc0 only
                 int t)
{
    int pix = blockIdx.x * 256 + threadIdx.x;
    int co  = blockIdx.y;
    int b   = blockIdx.z;
    int n   = b * 4096 + pix;
    int bb  = (b * 64 + co) * 4096 + pix;
    float cold = cin_[bb];

    float pre[4];
    #pragma unroll
    for (int g = 0; g < 4; g++) {
        int base = (g * 64 + co) * 4096 + pix;
        pre[g] = G[(size_t)(g * 64 + co) * NPX + n] + Wc[base] * cold + bias[base];
    }

    if (x) {
        int y = pix >> 6, xx = pix & 63;
        float xv[9];
        #pragma unroll
        for (int tap = 0; tap < 9; tap++) {
            int gy = y + tap / 3 - 1, gx = xx + tap % 3 - 1;
            xv[tap] = ((unsigned)gy < 64u && (unsigned)gx < 64u)
                      ? x[((size_t)b * TT + t) * 4096 + gy * 64 + gx] : 0.f;
        }
        #pragma unroll
        for (int g = 0; g < 4; g++) {
            const float* w9 = wx9 + (size_t)(g * 64 + co) * 9;
            float s0 = 0.f;
            #pragma unroll
            for (int tap = 0; tap < 9; tap++) s0 += __ldg(w9 + tap) * xv[tap];
            pre[g] += s0;
        }
    }

    float ig = sigf(pre[0]);
    float fg = sigf(pre[1]);
    float gg = tanhf(pre[2]);
    float og = sigf(pre[3]);
    float cn = fg * cold + ig * gg;
    cout[bb] = cn;
    hout[bb] = og * tanhf(cn);
}

// ---------------------------------------------------------------------------
// Final 3x3 conv (HID->1) + bias + sigmoid
// ---------------------------------------------------------------------------
__global__ void __launch_bounds__(256)
final_conv_kernel(const float* __restrict__ h1,
                  const float* __restrict__ fw,
                  const float* __restrict__ fb,
                  float* __restrict__ out, int t)
{
    __shared__ float s_w[HID * 9];
    int tid = threadIdx.x;
    for (int i = tid; i < HID * 9; i += 256) s_w[i] = fw[i];
    __syncthreads();

    int pix = blockIdx.x * 256 + tid;
    int b   = blockIdx.y;
    int y = pix >> 6, x = pix & 63;
    const float* hb = h1 + (size_t)b * HID * PIX;
    float sum = fb[0];
    for (int c = 0; c < HID; c++) {
        const float* plane = hb + c * PIX;
        #pragma unroll
        for (int tap = 0; tap < 9; tap++) {
            int dy = tap / 3 - 1, dx = tap % 3 - 1;
            int gy = y + dy, gx = x + dx;
            if ((unsigned)gy < 64u && (unsigned)gx < 64u)
                sum += s_w[c * 9 + tap] * plane[gy * 64 + gx];
        }
    }
    out[(size_t)b * (PRED * PIX) + t * PIX + pix] = 1.f / (1.f + expf(-sum));
}

// ---------------------------------------------------------------------------
extern "C" void kernel_launch(void* const* d_in, const int* in_sizes, int n_in,
                              void* d_out, int out_size)
{
    const float* x    = (const float*)d_in[0];
    const float* e0Wx = (const float*)d_in[1];
    const float* e0Wh = (const float*)d_in[2];
    const float* e0Wc = (const float*)d_in[3];
    const float* e0b  = (const float*)d_in[4];
    const float* e1Wx = (const float*)d_in[5];
    const float* e1Wh = (const float*)d_in[6];
    const float* e1Wc = (const float*)d_in[7];
    const float* e1b  = (const float*)d_in[8];
    const float* d0Wx = (const float*)d_in[9];
    const float* d0Wh = (const float*)d_in[10];
    const float* d0Wc = (const float*)d_in[11];
    const float* d0b  = (const float*)d_in[12];
    const float* d1Wx = (const float*)d_in[13];
    const float* d1Wh = (const float*)d_in[14];
    const float* d1Wc = (const float*)d_in[15];
    const float* d1b  = (const float*)d_in[16];
    const float* finw = (const float*)d_in[17];
    const float* finb = (const float*)d_in[18];
    float* out = (float*)d_out;

    cudaFuncSetAttribute(conv_mma_kernel,
                         cudaFuncAttributeMaxDynamicSharedMemorySize, SMEM_BYTES);

    float *hbuf, *cbuf, *G;
    __nv_bfloat16 *Tbuf, *Wbuf;
    cudaGetSymbolAddress((void**)&hbuf, g_h);
    cudaGetSymbolAddress((void**)&cbuf, g_c);
    cudaGetSymbolAddress((void**)&G,    g_G);
    cudaGetSymbolAddress((void**)&Tbuf, g_T);
    cudaGetSymbolAddress((void**)&Wbuf, g_W);

    float* eh0 = hbuf + 0 * (size_t)NST; float* ec0 = cbuf + 0 * (size_t)NST;
    float* eh1 = hbuf + 1 * (size_t)NST; float* ec1 = cbuf + 1 * (size_t)NST;
    float* dh0 = hbuf + 2 * (size_t)NST; float* dc0 = cbuf + 2 * (size_t)NST;
    float* dh1 = hbuf + 3 * (size_t)NST; float* dc1 = cbuf + 3 * (size_t)NST;
    __nv_bfloat16* Teh0 = Tbuf + 0 * (size_t)(2 * TSZ);
    __nv_bfloat16* Teh1 = Tbuf + 1 * (size_t)(2 * TSZ);
    __nv_bfloat16* Tdh0 = Tbuf + 2 * (size_t)(2 * TSZ);
    __nv_bfloat16* Tdh1 = Tbuf + 3 * (size_t)(2 * TSZ);
    __nv_bfloat16* W_e0h = Wbuf + 0 * (size_t)(2 * WSZ);
    __nv_bfloat16* W_e1x = Wbuf + 1 * (size_t)(2 * WSZ);
    __nv_bfloat16* W_e1h = Wbuf + 2 * (size_t)(2 * WSZ);
    __nv_bfloat16* W_d0x = Wbuf + 3 * (size_t)(2 * WSZ);
    __nv_bfloat16* W_d0h = Wbuf + 4 * (size_t)(2 * WSZ);
    __nv_bfloat16* W_d1x = Wbuf + 5 * (size_t)(2 * WSZ);
    __nv_bfloat16* W_d1h = Wbuf + 6 * (size_t)(2 * WSZ);

    // weight transforms
    int wg = (WSZ + 255) / 256;
    wsplit_kernel<<<wg, 256>>>(e0Wh, W_e0h);
    wsplit_kernel<<<wg, 256>>>(e1Wx, W_e1x);
    wsplit_kernel<<<wg, 256>>>(e1Wh, W_e1h);
    wsplit_kernel<<<wg, 256>>>(d0Wx, W_d0x);
    wsplit_kernel<<<wg, 256>>>(d0Wh, W_d0h);
    wsplit_kernel<<<wg, 256>>>(d1Wx, W_d1x);
    wsplit_kernel<<<wg, 256>>>(d1Wh, W_d1h);

    // zero initial c states and transposed-h buffers (halos included)
    cudaMemsetAsync(cbuf, 0, (size_t)4 * NST * sizeof(float));
    cudaMemsetAsync(Tbuf, 0, (size_t)4 * 2 * TSZ * sizeof(__nv_bfloat16));

    dim3 mgrid(128, 2), mblk(512);
    dim3 pgrid(16, 64, 8), pblk(256);
    dim3 tgrid(64, 8), tblk(256);

    // Encoder
    for (int t = 0; t < TT; t++) {
        // enc0: h-conv via mma (single source), x-conv (cin=1) in pointwise
        conv_mma_kernel<<<mgrid, mblk, SMEM_BYTES>>>(Teh0, W_e0h, Teh0, W_e0h, 1, G);
        pointwise_kernel<<<pgrid, pblk>>>(G, e0Wc, e0b, ec0, eh0, ec0, x, e0Wx, t);
        transpose_split_kernel<<<tgrid, tblk>>>(eh0, Teh0);
        // enc1: x-src = new eh0, h-src = old eh1
        conv_mma_kernel<<<mgrid, mblk, SMEM_BYTES>>>(Teh0, W_e1x, Teh1, W_e1h, 2, G);
        pointwise_kernel<<<pgrid, pblk>>>(G, e1Wc, e1b, ec1, eh1, ec1, nullptr, nullptr, 0);
        transpose_split_kernel<<<tgrid, tblk>>>(eh1, Teh1);
    }

    // Decoder
    for (int t = 0; t < PRED; t++) {
        const __nv_bfloat16* Ts = (t == 0) ? Teh1 : Tdh1;
        conv_mma_kernel<<<mgrid, mblk, SMEM_BYTES>>>(Ts, W_d0x, Tdh0, W_d0h, 2, G);
        pointwise_kernel<<<pgrid, pblk>>>(G, d0Wc, d0b, dc0, dh0, dc0, nullptr, nullptr, 0);
        transpose_split_kernel<<<tgrid, tblk>>>(dh0, Tdh0);

        conv_mma_kernel<<<mgrid, mblk, SMEM_BYTES>>>(Tdh0, W_d1x, Tdh1, W_d1h, 2, G);
        pointwise_kernel<<<pgrid, pblk>>>(G, d1Wc, d1b, dc1, dh1, dc1, nullptr, nullptr, 0);
        transpose_split_kernel<<<tgrid, tblk>>>(dh1, Tdh1);

        final_conv_kernel<<<dim3(16, BB), 256>>>(dh1, finw, finb, out, t);
    }
}

// round 6
// speedup vs baseline: 4.1656x; 1.2374x over previous
#include <cuda_runtime.h>
#include <cuda_bf16.h>
#include <math.h>
#include <stdint.h>

// Problem constants
#define BB   8
#define TT   10
#define HH   64
#define WW   64
#define HID  64
#define PRED 10
#define PIX  (HH*WW)              // 4096
#define NST  (BB*HID*PIX)
#define TROW 66
#define TSZ  ((size_t)BB*TROW*TROW*HID)
#define WSZ  (9*256*64)           // per split-half of a transformed weight

// ---------------------------------------------------------------------------
// Static scratch
// ---------------------------------------------------------------------------
__device__ float g_h[4][NST];
__device__ float g_c[4][NST];
__device__ __align__(16) __nv_bfloat16 g_T[4][2 * (BB*TROW*TROW*HID)];
__device__ __align__(16) __nv_bfloat16 g_W[7][2 * WSZ];

// ---------------------------------------------------------------------------
// Weight transform+split: w (256,64,3,3) -> wt[{hi,lo}][tap][m][k] bf16 with
// row reorder m = co*4 + g (gates of a channel adjacent, for fused epilogue)
// ---------------------------------------------------------------------------
__global__ void wsplit_kernel(const float* __restrict__ w, __nv_bfloat16* __restrict__ wt)
{
    int i = blockIdx.x * blockDim.x + threadIdx.x;
    if (i >= WSZ) return;
    int c   = i & 63;
    int m   = (i >> 6) & 255;     // new row index = co*4+g
    int tap = i >> 14;
    int co = m >> 2, g = m & 3;
    float v = w[((g * 64 + co) * 64 + c) * 9 + tap];
    __nv_bfloat16 hi = __float2bfloat16(v);
    __nv_bfloat16 lo = __float2bfloat16(v - __bfloat162float(hi));
    wt[i] = hi;
    wt[WSZ + i] = lo;
}

// ---------------------------------------------------------------------------
// Transpose + split: h fp32 (B,64,64,64) -> T bf16 [b][py][px][c] padded 66x66
// ---------------------------------------------------------------------------
__global__ void __launch_bounds__(256)
transpose_split_kernel(const float* __restrict__ h, __nv_bfloat16* __restrict__ T)
{
    __shared__ float s[64][65];
    int y = blockIdx.x, b = blockIdx.y, tid = threadIdx.x;
    for (int i = tid; i < 4096; i += 256) {
        int c = i >> 6, x = i & 63;
        s[c][x] = h[((b * 64 + c) << 12) + (y << 6) + x];
    }
    __syncthreads();
    size_t rowbase = (((size_t)b * TROW + (y + 1)) * TROW + 1) * 64;
    for (int i = tid; i < 4096; i += 256) {
        int c = i & 63, x = i >> 6;
        float v = s[c][x];
        __nv_bfloat16 hi = __float2bfloat16(v);
        __nv_bfloat16 lo = __float2bfloat16(v - __bfloat162float(hi));
        T[rowbase + (size_t)x * 64 + c] = hi;
        T[TSZ + rowbase + (size_t)x * 64 + c] = lo;
    }
}

// ---------------------------------------------------------------------------
// low-level helpers
// ---------------------------------------------------------------------------
__device__ __forceinline__ uint32_t smem_u32(const void* p) {
    uint32_t a;
    asm("{ .reg .u64 t; cvta.to.shared.u64 t, %1; cvt.u32.u64 %0, t; }" : "=r"(a) : "l"(p));
    return a;
}
__device__ __forceinline__ void cp16(uint32_t dst, const void* src) {
    asm volatile("cp.async.cg.shared.global [%0], [%1], 16;" :: "r"(dst), "l"(src));
}
#define CP_COMMIT() asm volatile("cp.async.commit_group;" ::: "memory")
#define CP_WAIT0()  asm volatile("cp.async.wait_group 0;" ::: "memory")

__device__ __forceinline__ void ldm_x4(unsigned* r, uint32_t addr) {
    asm volatile("ldmatrix.sync.aligned.m8n8.x4.shared.b16 {%0,%1,%2,%3}, [%4];"
        : "=r"(r[0]), "=r"(r[1]), "=r"(r[2]), "=r"(r[3]) : "r"(addr));
}
__device__ __forceinline__ void mma16816(float* d, const unsigned* a,
                                         unsigned b0, unsigned b1)
{
    asm("mma.sync.aligned.m16n8k16.row.col.f32.bf16.bf16.f32 "
        "{%0,%1,%2,%3}, {%4,%5,%6,%7}, {%8,%9}, {%0,%1,%2,%3};"
        : "+f"(d[0]), "+f"(d[1]), "+f"(d[2]), "+f"(d[3])
        : "r"(a[0]), "r"(a[1]), "r"(a[2]), "r"(a[3]), "r"(b0), "r"(b1));
}

__device__ __forceinline__ float sigf(float v) { return 1.f / (1.f + expf(-v)); }

// SMEM layout (bytes):
//   A tiles: 2 bufs x 2 halves x 128 rows x 72 elems (144B rows)  = 73728
//   B tile : 2 halves x 396 rows x 72 elems                       = 114048
//   w9     : 2304 floats                                          = 9216
// Epilogue staging sE (128 x 264 f32 = 135168) reuses the A+B region.
#define SA_OFF   0
#define SA_BUF   36864
#define SA_HALF  18432
#define SB_OFF   73728
#define SB_HALF  57024
#define SW9_OFF  187776
#define SM_TOTAL (SW9_OFF + 9216)
#define ESTR     264

// ---------------------------------------------------------------------------
// Fused ConvLSTM cell via legacy bf16 mma with ldmatrix + cp.async pipeline.
// CTA: M=128 gate-rows (mt half; rows m=4co+g -> channels mt*32..mt*32+31),
//      N=256 px (4 image rows of one batch).
// 8 warps: wm in {0,1} x wn in {0..3}; warp tile 64m x 64n.
// K loop: nsrc x 9 taps x {AhBh, AhBl, AlBh} x 4 k16 chunks.
// Epilogue: acc -> smem -> full LSTM pointwise (+ inline cin=1 x-conv).
// ---------------------------------------------------------------------------
__global__ void __launch_bounds__(256)
cell_mma_kernel(const __nv_bfloat16* __restrict__ T0,
                const __nv_bfloat16* __restrict__ W0,
                const __nv_bfloat16* __restrict__ T1,
                const __nv_bfloat16* __restrict__ W1,
                int nsrc,
                const float* __restrict__ Wc,
                const float* __restrict__ bias,
                const float* __restrict__ cst,
                float* __restrict__ hout,
                float* __restrict__ cout,
                const float* __restrict__ xp,    // enc0 only
                const float* __restrict__ wx9,   // enc0 only (256,1,3,3)
                int t)
{
    extern __shared__ __align__(16) char smc[];
    const uint32_t smb = smem_u32(smc);
    float* sE   = (float*)smc;
    float* s_w9 = (float*)(smc + SW9_OFF);

    const int tid  = threadIdx.x;
    const int lane = tid & 31;
    const int warp = tid >> 5;
    const int wm   = warp >> 2;
    const int wn   = warp & 3;
    const int nt   = blockIdx.x;     // 0..127
    const int mt   = blockIdx.y;     // 0..1
    const int b    = nt >> 4;
    const int y0   = (nt & 15) << 2; // first of 4 image rows

    // ldmatrix lane-address components
    const int a_row_l = lane & 15;
    const int a_col_l = (lane >> 4) * 8;
    const int b_row_l = (lane & 7) + ((lane >> 4) << 3);
    const int b_col_l = ((lane >> 3) & 1) * 8;

    if (xp) for (int i = tid; i < 2304; i += 256) s_w9[i] = wx9[i];

    float acc[4][8][4];
    #pragma unroll
    for (int mi = 0; mi < 4; mi++)
        #pragma unroll
        for (int ni = 0; ni < 8; ni++)
            #pragma unroll
            for (int r = 0; r < 4; r++) acc[mi][ni][r] = 0.f;

    for (int s = 0; s < nsrc; s++) {
        const __nv_bfloat16* T = s ? T1 : T0;
        const __nv_bfloat16* W = s ? W1 : W0;

        __syncthreads();   // prior source mma reads of B done
        // fill B: 2 halves x 396 rows x 8 vec16
        for (int i = tid; i < 6336; i += 256) {
            int h = i / 3168, j = i - h * 3168;
            int p = j >> 3, v = j & 7;
            int r = p / TROW, px = p - r * TROW;
            const __nv_bfloat16* src =
                T + (size_t)h * TSZ + (((size_t)b * TROW + (y0 + r)) * TROW + px) * 64 + v * 8;
            cp16(smb + SB_OFF + h * SB_HALF + p * 144 + v * 16, src);
        }
        // fill A tap0 into buf0
        for (int i = tid; i < 2048; i += 256) {
            int h = i >> 10, j = i & 1023;
            int m = j >> 3, v = j & 7;
            const __nv_bfloat16* src = W + (size_t)h * WSZ + (mt * 128 + m) * 64 + v * 8;
            cp16(smb + SA_OFF + h * SA_HALF + m * 144 + v * 16, src);
        }
        CP_COMMIT();

        for (int tap = 0; tap < 9; tap++) {
            CP_WAIT0();
            __syncthreads();
            if (tap < 9 - 1) {
                const int nb = (tap + 1) & 1;
                for (int i = tid; i < 2048; i += 256) {
                    int h = i >> 10, j = i & 1023;
                    int m = j >> 3, v = j & 7;
                    const __nv_bfloat16* src =
                        W + (size_t)h * WSZ + (tap + 1) * 16384 + (mt * 128 + m) * 64 + v * 8;
                    cp16(smb + SA_OFF + nb * SA_BUF + h * SA_HALF + m * 144 + v * 16, src);
                }
                CP_COMMIT();
            }

            const int dy = tap / 3, dx = tap - dy * 3;
            const int prow_base = (wn + dy) * TROW + dx;

            #pragma unroll
            for (int prod = 0; prod < 3; prod++) {
                const int Ah = (prod == 2) ? 1 : 0;     // lo weights for prod2
                const int Bh = (prod == 1) ? 1 : 0;     // lo pixels for prod1
                const uint32_t aBase = smb + SA_OFF + (tap & 1) * SA_BUF + Ah * SA_HALF;
                const uint32_t bBase = smb + SB_OFF + Bh * SB_HALF;
                #pragma unroll
                for (int ks = 0; ks < 4; ks++) {
                    unsigned afr[4][4];
                    #pragma unroll
                    for (int mi = 0; mi < 4; mi++)
                        ldm_x4(afr[mi], aBase + (wm * 64 + mi * 16 + a_row_l) * 144
                                              + (a_col_l + ks * 16) * 2);
                    unsigned bfr[4][4];
                    #pragma unroll
                    for (int p2 = 0; p2 < 4; p2++)
                        ldm_x4(bfr[p2], bBase + (prow_base + p2 * 16 + b_row_l) * 144
                                              + (ks * 16 + b_col_l) * 2);
                    #pragma unroll
                    for (int p2 = 0; p2 < 4; p2++)
                        #pragma unroll
                        for (int mi = 0; mi < 4; mi++) {
                            mma16816(acc[mi][2 * p2],     afr[mi], bfr[p2][0], bfr[p2][1]);
                            mma16816(acc[mi][2 * p2 + 1], afr[mi], bfr[p2][2], bfr[p2][3]);
                        }
                }
            }
        }
    }

    // ---- epilogue ----
    __syncthreads();   // all mma done; safe to overwrite A/B smem with sE
    const int gr = lane >> 2, ci = lane & 3;
    #pragma unroll
    for (int mi = 0; mi < 4; mi++)
        #pragma unroll
        for (int ni = 0; ni < 8; ni++) {
            int r0 = wm * 64 + mi * 16 + gr;
            int n  = wn * 64 + ni * 8 + 2 * ci;
            *(float2*)(sE + r0 * ESTR + n)       = make_float2(acc[mi][ni][0], acc[mi][ni][1]);
            *(float2*)(sE + (r0 + 8) * ESTR + n) = make_float2(acc[mi][ni][2], acc[mi][ni][3]);
        }
    __syncthreads();

    // pointwise: warp handles channels (warp + 8*jj), pixels lane + 32*ii
    #pragma unroll 1
    for (int ii = 0; ii < 8; ii++) {
        int pl  = lane + 32 * ii;            // 0..255 within CTA's 4 rows
        int pix = y0 * 64 + pl;
        float xv[9];
        if (xp) {
            int y = pix >> 6, xx = pix & 63;
            #pragma unroll
            for (int tap = 0; tap < 9; tap++) {
                int gy = y + tap / 3 - 1, gx = xx + tap % 3 - 1;
                xv[tap] = ((unsigned)gy < 64u && (unsigned)gx < 64u)
                          ? xp[((size_t)b * TT + t) * 4096 + gy * 64 + gx] : 0.f;
            }
        }
        #pragma unroll 1
        for (int jj = 0; jj < 4; jj++) {
            int col = warp + 8 * jj;         // 0..31 local channel
            int co  = mt * 32 + col;
            int bb  = (b * 64 + co) * 4096 + pix;
            float cold = cst[bb];
            float pre[4];
            #pragma unroll
            for (int g = 0; g < 4; g++) {
                int base = (g * 64 + co) * 4096 + pix;
                pre[g] = sE[(col * 4 + g) * ESTR + pl] + Wc[base] * cold + bias[base];
            }
            if (xp) {
                #pragma unroll
                for (int g = 0; g < 4; g++) {
                    const float* w9 = s_w9 + (g * 64 + co) * 9;
                    float s0 = 0.f;
                    #pragma unroll
                    for (int tap = 0; tap < 9; tap++) s0 += w9[tap] * xv[tap];
                    pre[g] += s0;
                }
            }
            float ig = sigf(pre[0]);
            float fg = sigf(pre[1]);
            float gg = tanhf(pre[2]);
            float og = sigf(pre[3]);
            float cn = fg * cold + ig * gg;
            cout[bb] = cn;
            hout[bb] = og * tanhf(cn);
        }
    }
}

// ---------------------------------------------------------------------------
// Final 3x3 conv (HID->1) + bias + sigmoid
// ---------------------------------------------------------------------------
__global__ void __launch_bounds__(256)
final_conv_kernel(const float* __restrict__ h1,
                  const float* __restrict__ fw,
                  const float* __restrict__ fb,
                  float* __restrict__ out, int t)
{
    __shared__ float s_w[HID * 9];
    int tid = threadIdx.x;
    for (int i = tid; i < HID * 9; i += 256) s_w[i] = fw[i];
    __syncthreads();

    int pix = blockIdx.x * 256 + tid;
    int b   = blockIdx.y;
    int y = pix >> 6, x = pix & 63;
    const float* hb = h1 + (size_t)b * HID * PIX;
    float sum = fb[0];
    for (int c = 0; c < HID; c++) {
        const float* plane = hb + c * PIX;
        #pragma unroll
        for (int tap = 0; tap < 9; tap++) {
            int dy = tap / 3 - 1, dx = tap % 3 - 1;
            int gy = y + dy, gx = x + dx;
            if ((unsigned)gy < 64u && (unsigned)gx < 64u)
                sum += s_w[c * 9 + tap] * plane[gy * 64 + gx];
        }
    }
    out[(size_t)b * (PRED * PIX) + t * PIX + pix] = 1.f / (1.f + expf(-sum));
}

// ---------------------------------------------------------------------------
extern "C" void kernel_launch(void* const* d_in, const int* in_sizes, int n_in,
                              void* d_out, int out_size)
{
    const float* x    = (const float*)d_in[0];
    const float* e0Wx = (const float*)d_in[1];
    const float* e0Wh = (const float*)d_in[2];
    const float* e0Wc = (const float*)d_in[3];
    const float* e0b  = (const float*)d_in[4];
    const float* e1Wx = (const float*)d_in[5];
    const float* e1Wh = (const float*)d_in[6];
    const float* e1Wc = (const float*)d_in[7];
    const float* e1b  = (const float*)d_in[8];
    const float* d0Wx = (const float*)d_in[9];
    const float* d0Wh = (const float*)d_in[10];
    const float* d0Wc = (const float*)d_in[11];
    const float* d0b  = (const float*)d_in[12];
    const float* d1Wx = (const float*)d_in[13];
    const float* d1Wh = (const float*)d_in[14];
    const float* d1Wc = (const float*)d_in[15];
    const float* d1b  = (const float*)d_in[16];
    const float* finw = (const float*)d_in[17];
    const float* finb = (const float*)d_in[18];
    float* out = (float*)d_out;

    cudaFuncSetAttribute(cell_mma_kernel,
                         cudaFuncAttributeMaxDynamicSharedMemorySize, SM_TOTAL);

    float *hbuf, *cbuf;
    __nv_bfloat16 *Tbuf, *Wbuf;
    cudaGetSymbolAddress((void**)&hbuf, g_h);
    cudaGetSymbolAddress((void**)&cbuf, g_c);
    cudaGetSymbolAddress((void**)&Tbuf, g_T);
    cudaGetSymbolAddress((void**)&Wbuf, g_W);

    float* eh0 = hbuf + 0 * (size_t)NST; float* ec0 = cbuf + 0 * (size_t)NST;
    float* eh1 = hbuf + 1 * (size_t)NST; float* ec1 = cbuf + 1 * (size_t)NST;
    float* dh0 = hbuf + 2 * (size_t)NST; float* dc0 = cbuf + 2 * (size_t)NST;
    float* dh1 = hbuf + 3 * (size_t)NST; float* dc1 = cbuf + 3 * (size_t)NST;
    __nv_bfloat16* Teh0 = Tbuf + 0 * (2 * TSZ);
    __nv_bfloat16* Teh1 = Tbuf + 1 * (2 * TSZ);
    __nv_bfloat16* Tdh0 = Tbuf + 2 * (2 * TSZ);
    __nv_bfloat16* Tdh1 = Tbuf + 3 * (2 * TSZ);
    __nv_bfloat16* W_e0h = Wbuf + 0 * (size_t)(2 * WSZ);
    __nv_bfloat16* W_e1x = Wbuf + 1 * (size_t)(2 * WSZ);
    __nv_bfloat16* W_e1h = Wbuf + 2 * (size_t)(2 * WSZ);
    __nv_bfloat16* W_d0x = Wbuf + 3 * (size_t)(2 * WSZ);
    __nv_bfloat16* W_d0h = Wbuf + 4 * (size_t)(2 * WSZ);
    __nv_bfloat16* W_d1x = Wbuf + 5 * (size_t)(2 * WSZ);
    __nv_bfloat16* W_d1h = Wbuf + 6 * (size_t)(2 * WSZ);

    int wg = (WSZ + 255) / 256;
    wsplit_kernel<<<wg, 256>>>(e0Wh, W_e0h);
    wsplit_kernel<<<wg, 256>>>(e1Wx, W_e1x);
    wsplit_kernel<<<wg, 256>>>(e1Wh, W_e1h);
    wsplit_kernel<<<wg, 256>>>(d0Wx, W_d0x);
    wsplit_kernel<<<wg, 256>>>(d0Wh, W_d0h);
    wsplit_kernel<<<wg, 256>>>(d1Wx, W_d1x);
    wsplit_kernel<<<wg, 256>>>(d1Wh, W_d1h);

    cudaMemsetAsync(cbuf, 0, (size_t)4 * NST * sizeof(float));
    cudaMemsetAsync(Tbuf, 0, (size_t)4 * 2 * TSZ * sizeof(__nv_bfloat16));

    dim3 cgrid(128, 2), cblk(256);
    dim3 tgrid(64, 8), tblk(256);

    // Encoder
    for (int t = 0; t < TT; t++) {
        cell_mma_kernel<<<cgrid, cblk, SM_TOTAL>>>(Teh0, W_e0h, Teh0, W_e0h, 1,
                                                   e0Wc, e0b, ec0, eh0, ec0, x, e0Wx, t);
        transpose_split_kernel<<<tgrid, tblk>>>(eh0, Teh0);
        cell_mma_kernel<<<cgrid, cblk, SM_TOTAL>>>(Teh0, W_e1x, Teh1, W_e1h, 2,
                                                   e1Wc, e1b, ec1, eh1, ec1, nullptr, nullptr, 0);
        transpose_split_kernel<<<tgrid, tblk>>>(eh1, Teh1);
    }

    // Decoder
    for (int t = 0; t < PRED; t++) {
        const __nv_bfloat16* Ts = (t == 0) ? Teh1 : Tdh1;
        cell_mma_kernel<<<cgrid, cblk, SM_TOTAL>>>(Ts, W_d0x, Tdh0, W_d0h, 2,
                                                   d0Wc, d0b, dc0, dh0, dc0, nullptr, nullptr, 0);
        transpose_split_kernel<<<tgrid, tblk>>>(dh0, Tdh0);

        cell_mma_kernel<<<cgrid, cblk, SM_TOTAL>>>(Tdh0, W_d1x, Tdh1, W_d1h, 2,
                                                   d1Wc, d1b, dc1, dh1, dc1, nullptr, nullptr, 0);
        transpose_split_kernel<<<tgrid, tblk>>>(dh1, Tdh1);

        final_conv_kernel<<<dim3(16, BB), 256>>>(dh1, finw, finb, out, t);
    }
}

// round 7
// speedup vs baseline: 5.5466x; 1.3315x over previous
#include <cuda_runtime.h>
#include <cuda_fp16.h>
#include <math.h>
#include <stdint.h>

// Problem constants
#define BB   8
#define TT   10
#define HH   64
#define WW   64
#define HID  64
#define PRED 10
#define PIX  (HH*WW)              // 4096
#define NST  (BB*HID*PIX)
#define TROW 66
#define TSZ  ((size_t)BB*TROW*TROW*HID)   // elems of one transposed fp16 tensor
#define WSZ  (9*256*64)           // per split-half of a transformed weight

// ---------------------------------------------------------------------------
// Static scratch
// ---------------------------------------------------------------------------
__device__ float g_h[4][NST];
__device__ float g_c[4][NST];
__device__ __align__(16) __half g_T[4][BB*TROW*TROW*HID];   // fp16 pixels (no split)
__device__ __align__(16) __half g_W[7][2 * WSZ];            // fp16 weights hi|lo

// ---------------------------------------------------------------------------
// Weight transform+split: w (256,64,3,3) -> wt[{hi,lo}][tap][m][k] fp16,
// row reorder m = co*4 + g (gates of a channel adjacent)
// ---------------------------------------------------------------------------
__global__ void wsplit_kernel(const float* __restrict__ w, __half* __restrict__ wt)
{
    int i = blockIdx.x * blockDim.x + threadIdx.x;
    if (i >= WSZ) return;
    int c   = i & 63;
    int m   = (i >> 6) & 255;
    int tap = i >> 14;
    int co = m >> 2, g = m & 3;
    float v = w[((g * 64 + co) * 64 + c) * 9 + tap];
    __half hi = __float2half_rn(v);
    __half lo = __float2half_rn(v - __half2float(hi));
    wt[i] = hi;
    wt[WSZ + i] = lo;
}

// ---------------------------------------------------------------------------
// Transpose: h fp32 (B,64,64,64) -> T fp16 [b][py][px][c] padded 66x66
// ---------------------------------------------------------------------------
__global__ void __launch_bounds__(256)
transpose_split_kernel(const float* __restrict__ h, __half* __restrict__ T)
{
    __shared__ float s[64][65];
    int y = blockIdx.x, b = blockIdx.y, tid = threadIdx.x;
    for (int i = tid; i < 4096; i += 256) {
        int c = i >> 6, x = i & 63;
        s[c][x] = h[((b * 64 + c) << 12) + (y << 6) + x];
    }
    __syncthreads();
    size_t rowbase = (((size_t)b * TROW + (y + 1)) * TROW + 1) * 64;
    for (int i = tid; i < 4096; i += 256) {
        int c = i & 63, x = i >> 6;
        T[rowbase + (size_t)x * 64 + c] = __float2half_rn(s[c][x]);
    }
}

// ---------------------------------------------------------------------------
// low-level helpers
// ---------------------------------------------------------------------------
__device__ __forceinline__ uint32_t smem_u32(const void* p) {
    uint32_t a;
    asm("{ .reg .u64 t; cvta.to.shared.u64 t, %1; cvt.u32.u64 %0, t; }" : "=r"(a) : "l"(p));
    return a;
}
__device__ __forceinline__ void cp16(uint32_t dst, const void* src) {
    asm volatile("cp.async.cg.shared.global [%0], [%1], 16;" :: "r"(dst), "l"(src));
}
#define CP_COMMIT() asm volatile("cp.async.commit_group;" ::: "memory")
#define CP_WAIT0()  asm volatile("cp.async.wait_group 0;" ::: "memory")

__device__ __forceinline__ void ldm_x4(unsigned* r, uint32_t addr) {
    asm volatile("ldmatrix.sync.aligned.m8n8.x4.shared.b16 {%0,%1,%2,%3}, [%4];"
        : "=r"(r[0]), "=r"(r[1]), "=r"(r[2]), "=r"(r[3]) : "r"(addr));
}
__device__ __forceinline__ void mma16816(float* d, const unsigned* a,
                                         unsigned b0, unsigned b1)
{
    asm("mma.sync.aligned.m16n8k16.row.col.f32.f16.f16.f32 "
        "{%0,%1,%2,%3}, {%4,%5,%6,%7}, {%8,%9}, {%0,%1,%2,%3};"
        : "+f"(d[0]), "+f"(d[1]), "+f"(d[2]), "+f"(d[3])
        : "r"(a[0]), "r"(a[1]), "r"(a[2]), "r"(a[3]), "r"(b0), "r"(b1));
}

__device__ __forceinline__ float sigf(float v) { return 1.f / (1.f + expf(-v)); }

// SMEM layout (bytes):
//   A tiles: 2 bufs x 2 halves(w hi/lo) x 128 rows x 144B = 73728
//   B tile : 396 rows x 144B                              = 57024  (single fp16)
//   sE (epilogue staging, 128 x 264 f32 = 135168) overlays A+B
//   w9 after sE region
#define SA_OFF   0
#define SA_BUF   36864
#define SA_HALF  18432
#define SB_OFF   73728
#define SW9_OFF  135168
#define SM_TOTAL (SW9_OFF + 9216)
#define ESTR     264

// ---------------------------------------------------------------------------
// Fused ConvLSTM cell: fp16 mma, 2 products (W_hi*B + W_lo*B).
// CTA: M=128 gate-rows (mt half), N=256 px (4 image rows of one batch).
// 8 warps: wm {0,1} x wn {0..3}; warp tile 64m x 64n.
// ---------------------------------------------------------------------------
__global__ void __launch_bounds__(256)
cell_mma_kernel(const __half* __restrict__ T0,
                const __half* __restrict__ W0,
                const __half* __restrict__ T1,
                const __half* __restrict__ W1,
                int nsrc,
                const float* __restrict__ Wc,
                const float* __restrict__ bias,
                const float* __restrict__ cst,
                float* __restrict__ hout,
                float* __restrict__ cout,
                const float* __restrict__ xp,    // enc0 only
                const float* __restrict__ wx9,   // enc0 only (256,1,3,3)
                int t)
{
    extern __shared__ __align__(16) char smc[];
    const uint32_t smb = smem_u32(smc);
    float* sE   = (float*)smc;
    float* s_w9 = (float*)(smc + SW9_OFF);

    const int tid  = threadIdx.x;
    const int lane = tid & 31;
    const int warp = tid >> 5;
    const int wm   = warp >> 2;
    const int wn   = warp & 3;
    const int nt   = blockIdx.x;     // 0..127
    const int mt   = blockIdx.y;     // 0..1
    const int b    = nt >> 4;
    const int y0   = (nt & 15) << 2;

    const int a_row_l = lane & 15;
    const int a_col_l = (lane >> 4) * 8;
    const int b_row_l = (lane & 7) + ((lane >> 4) << 3);
    const int b_col_l = ((lane >> 3) & 1) * 8;

    if (xp) for (int i = tid; i < 2304; i += 256) s_w9[i] = wx9[i];

    float acc[4][8][4];
    #pragma unroll
    for (int mi = 0; mi < 4; mi++)
        #pragma unroll
        for (int ni = 0; ni < 8; ni++)
            #pragma unroll
            for (int r = 0; r < 4; r++) acc[mi][ni][r] = 0.f;

    for (int s = 0; s < nsrc; s++) {
        const __half* T = s ? T1 : T0;
        const __half* W = s ? W1 : W0;

        __syncthreads();   // prior source mma reads of B done
        // fill B: 396 rows x 8 vec16 (single fp16 tensor)
        for (int i = tid; i < 3168; i += 256) {
            int p = i >> 3, v = i & 7;
            int r = p / TROW, px = p - r * TROW;
            const __half* src =
                T + (((size_t)b * TROW + (y0 + r)) * TROW + px) * 64 + v * 8;
            cp16(smb + SB_OFF + p * 144 + v * 16, src);
        }
        // fill A tap0 into buf0 (hi & lo halves)
        for (int i = tid; i < 2048; i += 256) {
            int h = i >> 10, j = i & 1023;
            int m = j >> 3, v = j & 7;
            const __half* src = W + (size_t)h * WSZ + (mt * 128 + m) * 64 + v * 8;
            cp16(smb + SA_OFF + h * SA_HALF + m * 144 + v * 16, src);
        }
        CP_COMMIT();

        for (int tap = 0; tap < 9; tap++) {
            CP_WAIT0();
            __syncthreads();
            if (tap < 8) {
                const int nb = (tap + 1) & 1;
                for (int i = tid; i < 2048; i += 256) {
                    int h = i >> 10, j = i & 1023;
                    int m = j >> 3, v = j & 7;
                    const __half* src =
                        W + (size_t)h * WSZ + (tap + 1) * 16384 + (mt * 128 + m) * 64 + v * 8;
                    cp16(smb + SA_OFF + nb * SA_BUF + h * SA_HALF + m * 144 + v * 16, src);
                }
                CP_COMMIT();
            }

            const int dy = tap / 3, dx = tap - dy * 3;
            const int prow_base = (wn + dy) * TROW + dx;
            const uint32_t bBase = smb + SB_OFF;

            #pragma unroll
            for (int ks = 0; ks < 4; ks++) {
                unsigned bfr[4][4];
                #pragma unroll
                for (int p2 = 0; p2 < 4; p2++)
                    ldm_x4(bfr[p2], bBase + (prow_base + p2 * 16 + b_row_l) * 144
                                          + (ks * 16 + b_col_l) * 2);
                #pragma unroll
                for (int prod = 0; prod < 2; prod++) {
                    const uint32_t aBase = smb + SA_OFF + (tap & 1) * SA_BUF + prod * SA_HALF;
                    unsigned afr[4][4];
                    #pragma unroll
                    for (int mi = 0; mi < 4; mi++)
                        ldm_x4(afr[mi], aBase + (wm * 64 + mi * 16 + a_row_l) * 144
                                              + (a_col_l + ks * 16) * 2);
                    #pragma unroll
                    for (int p2 = 0; p2 < 4; p2++)
                        #pragma unroll
                        for (int mi = 0; mi < 4; mi++) {
                            mma16816(acc[mi][2 * p2],     afr[mi], bfr[p2][0], bfr[p2][1]);
                            mma16816(acc[mi][2 * p2 + 1], afr[mi], bfr[p2][2], bfr[p2][3]);
                        }
                }
            }
        }
    }

    // ---- epilogue ----
    __syncthreads();
    const int gr = lane >> 2, ci = lane & 3;
    #pragma unroll
    for (int mi = 0; mi < 4; mi++)
        #pragma unroll
        for (int ni = 0; ni < 8; ni++) {
            int r0 = wm * 64 + mi * 16 + gr;
            int n  = wn * 64 + ni * 8 + 2 * ci;
            *(float2*)(sE + r0 * ESTR + n)       = make_float2(acc[mi][ni][0], acc[mi][ni][1]);
            *(float2*)(sE + (r0 + 8) * ESTR + n) = make_float2(acc[mi][ni][2], acc[mi][ni][3]);
        }
    __syncthreads();

    #pragma unroll 1
    for (int ii = 0; ii < 8; ii++) {
        int pl  = lane + 32 * ii;
        int pix = y0 * 64 + pl;
        float xv[9];
        if (xp) {
            int y = pix >> 6, xx = pix & 63;
            #pragma unroll
            for (int tap = 0; tap < 9; tap++) {
                int gy = y + tap / 3 - 1, gx = xx + tap % 3 - 1;
                xv[tap] = ((unsigned)gy < 64u && (unsigned)gx < 64u)
                          ? xp[((size_t)b * TT + t) * 4096 + gy * 64 + gx] : 0.f;
            }
        }
        #pragma unroll 1
        for (int jj = 0; jj < 4; jj++) {
            int col = warp + 8 * jj;
            int co  = mt * 32 + col;
            int bb  = (b * 64 + co) * 4096 + pix;
            float cold = cst[bb];
            float pre[4];
            #pragma unroll
            for (int g = 0; g < 4; g++) {
                int base = (g * 64 + co) * 4096 + pix;
                pre[g] = sE[(col * 4 + g) * ESTR + pl] + Wc[base] * cold + bias[base];
            }
            if (xp) {
                #pragma unroll
                for (int g = 0; g < 4; g++) {
                    const float* w9 = s_w9 + (g * 64 + co) * 9;
                    float s0 = 0.f;
                    #pragma unroll
                    for (int tap = 0; tap < 9; tap++) s0 += w9[tap] * xv[tap];
                    pre[g] += s0;
                }
            }
            float ig = sigf(pre[0]);
            float fg = sigf(pre[1]);
            float gg = tanhf(pre[2]);
            float og = sigf(pre[3]);
            float cn = fg * cold + ig * gg;
            cout[bb] = cn;
            hout[bb] = og * tanhf(cn);
        }
    }
}

// ---------------------------------------------------------------------------
// Final 3x3 conv (HID->1) + bias + sigmoid
// ---------------------------------------------------------------------------
__global__ void __launch_bounds__(256)
final_conv_kernel(const float* __restrict__ h1,
                  const float* __restrict__ fw,
                  const float* __restrict__ fb,
                  float* __restrict__ out, int t)
{
    __shared__ float s_w[HID * 9];
    int tid = threadIdx.x;
    for (int i = tid; i < HID * 9; i += 256) s_w[i] = fw[i];
    __syncthreads();

    int pix = blockIdx.x * 256 + tid;
    int b   = blockIdx.y;
    int y = pix >> 6, x = pix & 63;
    const float* hb = h1 + (size_t)b * HID * PIX;
    float sum = fb[0];
    for (int c = 0; c < HID; c++) {
        const float* plane = hb + c * PIX;
        #pragma unroll
        for (int tap = 0; tap < 9; tap++) {
            int dy = tap / 3 - 1, dx = tap % 3 - 1;
            int gy = y + dy, gx = x + dx;
            if ((unsigned)gy < 64u && (unsigned)gx < 64u)
                sum += s_w[c * 9 + tap] * plane[gy * 64 + gx];
        }
    }
    out[(size_t)b * (PRED * PIX) + t * PIX + pix] = 1.f / (1.f + expf(-sum));
}

// ---------------------------------------------------------------------------
extern "C" void kernel_launch(void* const* d_in, const int* in_sizes, int n_in,
                              void* d_out, int out_size)
{
    const float* x    = (const float*)d_in[0];
    const float* e0Wx = (const float*)d_in[1];
    const float* e0Wh = (const float*)d_in[2];
    const float* e0Wc = (const float*)d_in[3];
    const float* e0b  = (const float*)d_in[4];
    const float* e1Wx = (const float*)d_in[5];
    const float* e1Wh = (const float*)d_in[6];
    const float* e1Wc = (const float*)d_in[7];
    const float* e1b  = (const float*)d_in[8];
    const float* d0Wx = (const float*)d_in[9];
    const float* d0Wh = (const float*)d_in[10];
    const float* d0Wc = (const float*)d_in[11];
    const float* d0b  = (const float*)d_in[12];
    const float* d1Wx = (const float*)d_in[13];
    const float* d1Wh = (const float*)d_in[14];
    const float* d1Wc = (const float*)d_in[15];
    const float* d1b  = (const float*)d_in[16];
    const float* finw = (const float*)d_in[17];
    const float* finb = (const float*)d_in[18];
    float* out = (float*)d_out;

    cudaFuncSetAttribute(cell_mma_kernel,
                         cudaFuncAttributeMaxDynamicSharedMemorySize, SM_TOTAL);

    float *hbuf, *cbuf;
    __half *Tbuf, *Wbuf;
    cudaGetSymbolAddress((void**)&hbuf, g_h);
    cudaGetSymbolAddress((void**)&cbuf, g_c);
    cudaGetSymbolAddress((void**)&Tbuf, g_T);
    cudaGetSymbolAddress((void**)&Wbuf, g_W);

    float* eh0 = hbuf + 0 * (size_t)NST; float* ec0 = cbuf + 0 * (size_t)NST;
    float* eh1 = hbuf + 1 * (size_t)NST; float* ec1 = cbuf + 1 * (size_t)NST;
    float* dh0 = hbuf + 2 * (size_t)NST; float* dc0 = cbuf + 2 * (size_t)NST;
    float* dh1 = hbuf + 3 * (size_t)NST; float* dc1 = cbuf + 3 * (size_t)NST;
    __half* Teh0 = Tbuf + 0 * TSZ;
    __half* Teh1 = Tbuf + 1 * TSZ;
    __half* Tdh0 = Tbuf + 2 * TSZ;
    __half* Tdh1 = Tbuf + 3 * TSZ;
    __half* W_e0h = Wbuf + 0 * (size_t)(2 * WSZ);
    __half* W_e1x = Wbuf + 1 * (size_t)(2 * WSZ);
    __half* W_e1h = Wbuf + 2 * (size_t)(2 * WSZ);
    __half* W_d0x = Wbuf + 3 * (size_t)(2 * WSZ);
    __half* W_d0h = Wbuf + 4 * (size_t)(2 * WSZ);
    __half* W_d1x = Wbuf + 5 * (size_t)(2 * WSZ);
    __half* W_d1h = Wbuf + 6 * (size_t)(2 * WSZ);

    int wg = (WSZ + 255) / 256;
    wsplit_kernel<<<wg, 256>>>(e0Wh, W_e0h);
    wsplit_kernel<<<wg, 256>>>(e1Wx, W_e1x);
    wsplit_kernel<<<wg, 256>>>(e1Wh, W_e1h);
    wsplit_kernel<<<wg, 256>>>(d0Wx, W_d0x);
    wsplit_kernel<<<wg, 256>>>(d0Wh, W_d0h);
    wsplit_kernel<<<wg, 256>>>(d1Wx, W_d1x);
    wsplit_kernel<<<wg, 256>>>(d1Wh, W_d1h);

    cudaMemsetAsync(cbuf, 0, (size_t)4 * NST * sizeof(float));
    cudaMemsetAsync(Tbuf, 0, (size_t)4 * TSZ * sizeof(__half));

    dim3 cgrid(128, 2), cblk(256);
    dim3 tgrid(64, 8), tblk(256);

    // Encoder
    for (int t = 0; t < TT; t++) {
        cell_mma_kernel<<<cgrid, cblk, SM_TOTAL>>>(Teh0, W_e0h, Teh0, W_e0h, 1,
                                                   e0Wc, e0b, ec0, eh0, ec0, x, e0Wx, t);
        transpose_split_kernel<<<tgrid, tblk>>>(eh0, Teh0);
        cell_mma_kernel<<<cgrid, cblk, SM_TOTAL>>>(Teh0, W_e1x, Teh1, W_e1h, 2,
                                                   e1Wc, e1b, ec1, eh1, ec1, nullptr, nullptr, 0);
        transpose_split_kernel<<<tgrid, tblk>>>(eh1, Teh1);
    }

    // Decoder
    for (int t = 0; t < PRED; t++) {
        const __half* Ts = (t == 0) ? Teh1 : Tdh1;
        cell_mma_kernel<<<cgrid, cblk, SM_TOTAL>>>(Ts, W_d0x, Tdh0, W_d0h, 2,
                                                   d0Wc, d0b, dc0, dh0, dc0, nullptr, nullptr, 0);
        transpose_split_kernel<<<tgrid, tblk>>>(dh0, Tdh0);

        cell_mma_kernel<<<cgrid, cblk, SM_TOTAL>>>(Tdh0, W_d1x, Tdh1, W_d1h, 2,
                                                   d1Wc, d1b, dc1, dh1, dc1, nullptr, nullptr, 0);
        transpose_split_kernel<<<tgrid, tblk>>>(dh1, Tdh1);

        final_conv_kernel<<<dim3(16, BB), 256>>>(dh1, finw, finb, out, t);
    }
}

// round 8
// speedup vs baseline: 9.1047x; 1.6415x over previous
#include <cuda_runtime.h>
#include <cuda_fp16.h>
#include <math.h>
#include <stdint.h>

// Problem constants
#define BB   8
#define TT   10
#define HH   64
#define WW   64
#define HID  64
#define PRED 10
#define PIX  (HH*WW)              // 4096
#define NST  (BB*HID*PIX)
#define TROW 66
#define TSZ  ((size_t)BB*TROW*TROW*HID)   // elems of one transposed fp16 tensor
#define WSZ  (9*256*64)           // fp16 weights per tensor (single version)

// ---------------------------------------------------------------------------
// Static scratch
// ---------------------------------------------------------------------------
__device__ float g_c[4][NST];                                   // c states
__device__ __align__(16) __half g_T[4][2 * BB*TROW*TROW*HID];   // h, ping-pong
__device__ __align__(16) __half g_W[7][WSZ];

// ---------------------------------------------------------------------------
// Weight transform: w (256,64,3,3) -> wt[tap][m][k] fp16, m = co*4 + g
// ---------------------------------------------------------------------------
__global__ void wsplit_kernel(const float* __restrict__ w, __half* __restrict__ wt)
{
    int i = blockIdx.x * blockDim.x + threadIdx.x;
    if (i >= WSZ) return;
    int c   = i & 63;
    int m   = (i >> 6) & 255;
    int tap = i >> 14;
    int co = m >> 2, g = m & 3;
    wt[i] = __float2half_rn(w[((g * 64 + co) * 64 + c) * 9 + tap]);
}

// ---------------------------------------------------------------------------
// low-level helpers
// ---------------------------------------------------------------------------
__device__ __forceinline__ uint32_t smem_u32(const void* p) {
    uint32_t a;
    asm("{ .reg .u64 t; cvta.to.shared.u64 t, %1; cvt.u32.u64 %0, t; }" : "=r"(a) : "l"(p));
    return a;
}
__device__ __forceinline__ void cp16(uint32_t dst, const void* src) {
    asm volatile("cp.async.cg.shared.global [%0], [%1], 16;" :: "r"(dst), "l"(src));
}
#define CP_COMMIT() asm volatile("cp.async.commit_group;" ::: "memory")
#define CP_WAIT0()  asm volatile("cp.async.wait_group 0;" ::: "memory")

__device__ __forceinline__ void ldm_x4(unsigned* r, uint32_t addr) {
    asm volatile("ldmatrix.sync.aligned.m8n8.x4.shared.b16 {%0,%1,%2,%3}, [%4];"
        : "=r"(r[0]), "=r"(r[1]), "=r"(r[2]), "=r"(r[3]) : "r"(addr));
}
__device__ __forceinline__ void mma16816(float* d, const unsigned* a,
                                         unsigned b0, unsigned b1)
{
    asm("mma.sync.aligned.m16n8k16.row.col.f32.f16.f16.f32 "
        "{%0,%1,%2,%3}, {%4,%5,%6,%7}, {%8,%9}, {%0,%1,%2,%3};"
        : "+f"(d[0]), "+f"(d[1]), "+f"(d[2]), "+f"(d[3])
        : "r"(a[0]), "r"(a[1]), "r"(a[2]), "r"(a[3]), "r"(b0), "r"(b1));
}

__device__ __forceinline__ float sigf(float v) { return 1.f / (1.f + expf(-v)); }

// SMEM layout (bytes):
//   A tiles: 2 bufs x 128 rows x 144B = 36864
//   B tile : 396 rows x 144B         = 57024      (mma region total 93888)
//   sE (epilogue gates, 128 x 264 f32 = 135168) overlays the mma region
//   sH (epilogue h staging, 256 px x 40 fp16 = 20480) after sE
//   w9 (enc0 x-conv weights) after sH
#define SA_OFF   0
#define SA_BUF   18432
#define SB_OFF   36864
#define SE_END   135168
#define SH_OFF   135168
#define SW9_OFF  155648
#define SM_TOTAL (SW9_OFF + 9216)
#define ESTR     264
#define HSTR     40

// ---------------------------------------------------------------------------
// Fused ConvLSTM cell: fp16 mma, single product, fused transpose-out.
// CTA: M=128 gate-rows (mt half -> channels mt*32..mt*32+31), N=256 px.
// 8 warps: wm {0,1} x wn {0..3}; warp tile 64m x 64n.
// ---------------------------------------------------------------------------
__global__ void __launch_bounds__(256)
cell_mma_kernel(const __half* __restrict__ T0,   // x-src pixels
                const __half* __restrict__ W0,   // x weights
                const __half* __restrict__ T1,   // h-src pixels
                const __half* __restrict__ W1,   // h weights
                int nsrc,
                const float* __restrict__ Wc,
                const float* __restrict__ bias,
                float* __restrict__ cbuf,        // c state (in/out)
                __half* __restrict__ Tout,       // new h, transposed fp16
                const float* __restrict__ xp,    // enc0 only
                const float* __restrict__ wx9,   // enc0 only (256,1,3,3)
                int t)
{
    extern __shared__ __align__(16) char smc[];
    const uint32_t smb = smem_u32(smc);
    float*  sE   = (float*)smc;
    __half* sH   = (__half*)(smc + SH_OFF);
    float*  s_w9 = (float*)(smc + SW9_OFF);

    const int tid  = threadIdx.x;
    const int lane = tid & 31;
    const int warp = tid >> 5;
    const int wm   = warp >> 2;
    const int wn   = warp & 3;
    const int nt   = blockIdx.x;     // 0..127
    const int mt   = blockIdx.y;     // 0..1
    const int b    = nt >> 4;
    const int y0   = (nt & 15) << 2;

    const int a_row_l = lane & 15;
    const int a_col_l = (lane >> 4) * 8;
    const int b_row_l = (lane & 7) + ((lane >> 4) << 3);
    const int b_col_l = ((lane >> 3) & 1) * 8;

    if (xp) for (int i = tid; i < 2304; i += 256) s_w9[i] = wx9[i];

    float acc[4][8][4];
    #pragma unroll
    for (int mi = 0; mi < 4; mi++)
        #pragma unroll
        for (int ni = 0; ni < 8; ni++)
            #pragma unroll
            for (int r = 0; r < 4; r++) acc[mi][ni][r] = 0.f;

    for (int s = 0; s < nsrc; s++) {
        const __half* T = s ? T1 : T0;
        const __half* W = s ? W1 : W0;

        __syncthreads();
        // fill B: 396 rows x 8 vec16
        for (int i = tid; i < 3168; i += 256) {
            int p = i >> 3, v = i & 7;
            int r = p / TROW, px = p - r * TROW;
            const __half* src =
                T + (((size_t)b * TROW + (y0 + r)) * TROW + px) * 64 + v * 8;
            cp16(smb + SB_OFF + p * 144 + v * 16, src);
        }
        // fill A tap0
        for (int i = tid; i < 1024; i += 256) {
            int m = i >> 3, v = i & 7;
            const __half* src = W + (mt * 128 + m) * 64 + v * 8;
            cp16(smb + SA_OFF + m * 144 + v * 16, src);
        }
        CP_COMMIT();

        for (int tap = 0; tap < 9; tap++) {
            CP_WAIT0();
            __syncthreads();
            if (tap < 8) {
                const int nb = (tap + 1) & 1;
                for (int i = tid; i < 1024; i += 256) {
                    int m = i >> 3, v = i & 7;
                    const __half* src = W + (tap + 1) * 16384 + (mt * 128 + m) * 64 + v * 8;
                    cp16(smb + SA_OFF + nb * SA_BUF + m * 144 + v * 16, src);
                }
                CP_COMMIT();
            }

            const int dy = tap / 3, dx = tap - dy * 3;
            const int prow_base = (wn + dy) * TROW + dx;
            const uint32_t aBase = smb + SA_OFF + (tap & 1) * SA_BUF;
            const uint32_t bBase = smb + SB_OFF;

            #pragma unroll
            for (int ks = 0; ks < 4; ks++) {
                unsigned bfr[4][4];
                #pragma unroll
                for (int p2 = 0; p2 < 4; p2++)
                    ldm_x4(bfr[p2], bBase + (prow_base + p2 * 16 + b_row_l) * 144
                                          + (ks * 16 + b_col_l) * 2);
                unsigned afr[4][4];
                #pragma unroll
                for (int mi = 0; mi < 4; mi++)
                    ldm_x4(afr[mi], aBase + (wm * 64 + mi * 16 + a_row_l) * 144
                                          + (a_col_l + ks * 16) * 2);
                #pragma unroll
                for (int p2 = 0; p2 < 4; p2++)
                    #pragma unroll
                    for (int mi = 0; mi < 4; mi++) {
                        mma16816(acc[mi][2 * p2],     afr[mi], bfr[p2][0], bfr[p2][1]);
                        mma16816(acc[mi][2 * p2 + 1], afr[mi], bfr[p2][2], bfr[p2][3]);
                    }
            }
        }
    }

    // ---- epilogue ----
    __syncthreads();
    const int gr = lane >> 2, ci = lane & 3;
    #pragma unroll
    for (int mi = 0; mi < 4; mi++)
        #pragma unroll
        for (int ni = 0; ni < 8; ni++) {
            int r0 = wm * 64 + mi * 16 + gr;
            int n  = wn * 64 + ni * 8 + 2 * ci;
            *(float2*)(sE + r0 * ESTR + n)       = make_float2(acc[mi][ni][0], acc[mi][ni][1]);
            *(float2*)(sE + (r0 + 8) * ESTR + n) = make_float2(acc[mi][ni][2], acc[mi][ni][3]);
        }
    __syncthreads();

    #pragma unroll 1
    for (int ii = 0; ii < 8; ii++) {
        int pl  = lane + 32 * ii;
        int pix = y0 * 64 + pl;
        float xv[9];
        if (xp) {
            int y = pix >> 6, xx = pix & 63;
            #pragma unroll
            for (int tap = 0; tap < 9; tap++) {
                int gy = y + tap / 3 - 1, gx = xx + tap % 3 - 1;
                xv[tap] = ((unsigned)gy < 64u && (unsigned)gx < 64u)
                          ? xp[((size_t)b * TT + t) * 4096 + gy * 64 + gx] : 0.f;
            }
        }
        #pragma unroll 1
        for (int jj = 0; jj < 4; jj++) {
            int col = warp + 8 * jj;          // 0..31 local channel
            int co  = mt * 32 + col;
            int bb  = (b * 64 + co) * 4096 + pix;
            float cold = cbuf[bb];
            float pre[4];
            #pragma unroll
            for (int g = 0; g < 4; g++) {
                int base = (g * 64 + co) * 4096 + pix;
                pre[g] = sE[(col * 4 + g) * ESTR + pl] + Wc[base] * cold + bias[base];
            }
            if (xp) {
                #pragma unroll
                for (int g = 0; g < 4; g++) {
                    const float* w9 = s_w9 + (g * 64 + co) * 9;
                    float s0 = 0.f;
                    #pragma unroll
                    for (int tap = 0; tap < 9; tap++) s0 += w9[tap] * xv[tap];
                    pre[g] += s0;
                }
            }
            float ig = sigf(pre[0]);
            float fg = sigf(pre[1]);
            float gg = tanhf(pre[2]);
            float og = sigf(pre[3]);
            float cn = fg * cold + ig * gg;
            cbuf[bb] = cn;
            sH[pl * HSTR + col] = __float2half_rn(og * tanhf(cn));
        }
    }
    __syncthreads();

    // coalesced copy-out: sH [256 px][32 ch] -> Tout (padded transposed layout)
    for (int i = tid; i < 1024; i += 256) {
        int px = i >> 2, q = i & 3;
        int pix = y0 * 64 + px;
        int y = pix >> 6, x = pix & 63;
        __half* dst = Tout + (((size_t)b * TROW + (y + 1)) * TROW + (x + 1)) * 64
                      + mt * 32 + q * 8;
        *(uint4*)dst = *(const uint4*)(sH + px * HSTR + q * 8);
    }
}

// ---------------------------------------------------------------------------
// Final 3x3 conv (HID->1) + bias + sigmoid, reading haloed fp16 T
// ---------------------------------------------------------------------------
__global__ void __launch_bounds__(256)
final_conv_kernel(const __half* __restrict__ T,
                  const float* __restrict__ fw,
                  const float* __restrict__ fb,
                  float* __restrict__ out, int t)
{
    __shared__ float s_w[9 * 64];   // [tap][c]
    int tid = threadIdx.x;
    for (int i = tid; i < 576; i += 256) {
        int tap = i >> 6, c = i & 63;
        s_w[tap * 64 + c] = fw[c * 9 + tap];
    }
    __syncthreads();

    int pix = blockIdx.x * 256 + tid;
    int b   = blockIdx.y;
    int y = pix >> 6, x = pix & 63;
    float sum = fb[0];
    #pragma unroll
    for (int tap = 0; tap < 9; tap++) {
        int dy = tap / 3, dx = tap % 3;
        const __half* row =
            T + (((size_t)b * TROW + (y + dy)) * TROW + (x + dx)) * 64;
        const float* wt = s_w + tap * 64;
        #pragma unroll
        for (int c8 = 0; c8 < 8; c8++) {
            uint4 v = *(const uint4*)(row + c8 * 8);
            const __half* hv = (const __half*)&v;
            #pragma unroll
            for (int k = 0; k < 8; k++)
                sum += wt[c8 * 8 + k] * __half2float(hv[k]);
        }
    }
    out[(size_t)b * (PRED * PIX) + t * PIX + pix] = 1.f / (1.f + expf(-sum));
}

// ---------------------------------------------------------------------------
extern "C" void kernel_launch(void* const* d_in, const int* in_sizes, int n_in,
                              void* d_out, int out_size)
{
    const float* x    = (const float*)d_in[0];
    const float* e0Wx = (const float*)d_in[1];
    const float* e0Wh = (const float*)d_in[2];
    const float* e0Wc = (const float*)d_in[3];
    const float* e0b  = (const float*)d_in[4];
    const float* e1Wx = (const float*)d_in[5];
    const float* e1Wh = (const float*)d_in[6];
    const float* e1Wc = (const float*)d_in[7];
    const float* e1b  = (const float*)d_in[8];
    const float* d0Wx = (const float*)d_in[9];
    const float* d0Wh = (const float*)d_in[10];
    const float* d0Wc = (const float*)d_in[11];
    const float* d0b  = (const float*)d_in[12];
    const float* d1Wx = (const float*)d_in[13];
    const float* d1Wh = (const float*)d_in[14];
    const float* d1Wc = (const float*)d_in[15];
    const float* d1b  = (const float*)d_in[16];
    const float* finw = (const float*)d_in[17];
    const float* finb = (const float*)d_in[18];
    float* out = (float*)d_out;

    cudaFuncSetAttribute(cell_mma_kernel,
                         cudaFuncAttributeMaxDynamicSharedMemorySize, SM_TOTAL);

    float* cbuf;
    __half *Tbuf, *Wbuf;
    cudaGetSymbolAddress((void**)&cbuf, g_c);
    cudaGetSymbolAddress((void**)&Tbuf, g_T);
    cudaGetSymbolAddress((void**)&Wbuf, g_W);

    float* ec0 = cbuf + 0 * (size_t)NST;
    float* ec1 = cbuf + 1 * (size_t)NST;
    float* dc0 = cbuf + 2 * (size_t)NST;
    float* dc1 = cbuf + 3 * (size_t)NST;
    // T slots: state s, slot k -> Tbuf + (2*s + k) * TSZ
    __half* Te0[2] = { Tbuf + 0 * TSZ, Tbuf + 1 * TSZ };
    __half* Te1[2] = { Tbuf + 2 * TSZ, Tbuf + 3 * TSZ };
    __half* Td0[2] = { Tbuf + 4 * TSZ, Tbuf + 5 * TSZ };
    __half* Td1[2] = { Tbuf + 6 * TSZ, Tbuf + 7 * TSZ };
    __half* W_e0h = Wbuf + 0 * (size_t)WSZ;
    __half* W_e1x = Wbuf + 1 * (size_t)WSZ;
    __half* W_e1h = Wbuf + 2 * (size_t)WSZ;
    __half* W_d0x = Wbuf + 3 * (size_t)WSZ;
    __half* W_d0h = Wbuf + 4 * (size_t)WSZ;
    __half* W_d1x = Wbuf + 5 * (size_t)WSZ;
    __half* W_d1h = Wbuf + 6 * (size_t)WSZ;

    int wg = (WSZ + 255) / 256;
    wsplit_kernel<<<wg, 256>>>(e0Wh, W_e0h);
    wsplit_kernel<<<wg, 256>>>(e1Wx, W_e1x);
    wsplit_kernel<<<wg, 256>>>(e1Wh, W_e1h);
    wsplit_kernel<<<wg, 256>>>(d0Wx, W_d0x);
    wsplit_kernel<<<wg, 256>>>(d0Wh, W_d0h);
    wsplit_kernel<<<wg, 256>>>(d1Wx, W_d1x);
    wsplit_kernel<<<wg, 256>>>(d1Wh, W_d1h);

    cudaMemsetAsync(cbuf, 0, (size_t)4 * NST * sizeof(float));
    cudaMemsetAsync(Tbuf, 0, (size_t)8 * TSZ * sizeof(__half));

    dim3 cgrid(128, 2), cblk(256);

    // Encoder
    for (int t = 0; t < TT; t++) {
        int r = t & 1, w = r ^ 1;
        cell_mma_kernel<<<cgrid, cblk, SM_TOTAL>>>(Te0[r], W_e0h, Te0[r], W_e0h, 1,
                                                   e0Wc, e0b, ec0, Te0[w], x, e0Wx, t);
        cell_mma_kernel<<<cgrid, cblk, SM_TOTAL>>>(Te0[w], W_e1x, Te1[r], W_e1h, 2,
                                                   e1Wc, e1b, ec1, Te1[w], nullptr, nullptr, 0);
    }
    // final encoder h1 in Te1[0] (t=9: w=0)

    // Decoder
    for (int t = 0; t < PRED; t++) {
        int r = t & 1, w = r ^ 1;
        const __half* Ts = (t == 0) ? Te1[0] : Td1[r];
        cell_mma_kernel<<<cgrid, cblk, SM_TOTAL>>>(Ts, W_d0x, Td0[r], W_d0h, 2,
                                                   d0Wc, d0b, dc0, Td0[w], nullptr, nullptr, 0);
        cell_mma_kernel<<<cgrid, cblk, SM_TOTAL>>>(Td0[w], W_d1x, Td1[r], W_d1h, 2,
                                                   d1Wc, d1b, dc1, Td1[w], nullptr, nullptr, 0);
        final_conv_kernel<<<dim3(16, BB), 256>>>(Td1[w], finw, finb, out, t);
    }
}

// round 9
// speedup vs baseline: 10.2274x; 1.1233x over previous
#include <cuda_runtime.h>
#include <cuda_fp16.h>
#include <math.h>
#include <stdint.h>

// Problem constants
#define BB   8
#define TT   10
#define HH   64
#define WW   64
#define HID  64
#define PRED 10
#define PIX  (HH*WW)              // 4096
#define NST  (BB*HID*PIX)
#define TROW 66
#define TSZ  ((size_t)BB*TROW*TROW*HID)   // elems of one transposed fp16 tensor
#define WSZ  (9*256*64)           // fp16 weights per tensor

// ---------------------------------------------------------------------------
// Static scratch
// ---------------------------------------------------------------------------
__device__ float g_c[4][NST];                                   // c states
__device__ __align__(16) __half g_T[4][2 * BB*TROW*TROW*HID];   // h, ping-pong
__device__ __align__(16) __half g_W[7][WSZ];

// ---------------------------------------------------------------------------
// Weight transform: w (256,64,3,3) -> wt[tap][m][k] fp16, m = co*4 + g
// ---------------------------------------------------------------------------
__global__ void wsplit_kernel(const float* __restrict__ w, __half* __restrict__ wt)
{
    int i = blockIdx.x * blockDim.x + threadIdx.x;
    if (i >= WSZ) return;
    int c   = i & 63;
    int m   = (i >> 6) & 255;
    int tap = i >> 14;
    int co = m >> 2, g = m & 3;
    wt[i] = __float2half_rn(w[((g * 64 + co) * 64 + c) * 9 + tap]);
}

// ---------------------------------------------------------------------------
// low-level helpers
// ---------------------------------------------------------------------------
__device__ __forceinline__ uint32_t smem_u32(const void* p) {
    uint32_t a;
    asm("{ .reg .u64 t; cvta.to.shared.u64 t, %1; cvt.u32.u64 %0, t; }" : "=r"(a) : "l"(p));
    return a;
}
__device__ __forceinline__ void cp16(uint32_t dst, const void* src) {
    asm volatile("cp.async.cg.shared.global [%0], [%1], 16;" :: "r"(dst), "l"(src));
}
#define CP_COMMIT() asm volatile("cp.async.commit_group;" ::: "memory")
#define CP_WAIT0()  asm volatile("cp.async.wait_group 0;" ::: "memory")

__device__ __forceinline__ void ldm_x4(unsigned* r, uint32_t addr) {
    asm volatile("ldmatrix.sync.aligned.m8n8.x4.shared.b16 {%0,%1,%2,%3}, [%4];"
        : "=r"(r[0]), "=r"(r[1]), "=r"(r[2]), "=r"(r[3]) : "r"(addr));
}
__device__ __forceinline__ void mma16816(float* d, const unsigned* a,
                                         unsigned b0, unsigned b1)
{
    asm("mma.sync.aligned.m16n8k16.row.col.f32.f16.f16.f32 "
        "{%0,%1,%2,%3}, {%4,%5,%6,%7}, {%8,%9}, {%0,%1,%2,%3};"
        : "+f"(d[0]), "+f"(d[1]), "+f"(d[2]), "+f"(d[3])
        : "r"(a[0]), "r"(a[1]), "r"(a[2]), "r"(a[3]), "r"(b0), "r"(b1));
}

// Fast activations: EX2/RCP based, ~1e-6 rel error (vs calibrated 2e-4/term
// noise floor of the fp16 mma path). No fp32 divides, no libm.
__device__ __forceinline__ float ex2f(float x) {
    float r;
    asm("ex2.approx.f32 %0, %1;" : "=f"(r) : "f"(x));
    return r;
}
__device__ __forceinline__ float rcpf(float x) {
    float r;
    asm("rcp.approx.f32 %0, %1;" : "=f"(r) : "f"(x));
    return r;
}
#define LOG2E 1.4426950408889634f
__device__ __forceinline__ float sigf(float v) {
    return rcpf(1.f + ex2f(-v * LOG2E));
}
__device__ __forceinline__ float tanhf_fast(float v) {
    return 1.f - 2.f * rcpf(1.f + ex2f(2.f * LOG2E * v));
}

// SMEM layout (bytes):
//   A tiles: 2 bufs x 128 rows x 144B = 36864
//   B tile : 396 rows x 144B         = 57024      (mma region total 93888)
//   sE (epilogue gates, 128 x 264 f32 = 135168) overlays the mma region
//   sH (epilogue h staging, 256 px x 40 fp16 = 20480) after sE
//   w9 (enc0 x-conv weights) after sH
#define SA_OFF   0
#define SA_BUF   18432
#define SB_OFF   36864
#define SH_OFF   135168
#define SW9_OFF  155648
#define SM_TOTAL (SW9_OFF + 9216)
#define ESTR     264
#define HSTR     40

// ---------------------------------------------------------------------------
// Fused ConvLSTM cell: fp16 mma, single product, fused transpose-out.
// CTA: M=128 gate-rows (mt half -> channels mt*32..mt*32+31), N=256 px.
// 8 warps: wm {0,1} x wn {0..3}; warp tile 64m x 64n.
// ---------------------------------------------------------------------------
__global__ void __launch_bounds__(256)
cell_mma_kernel(const __half* __restrict__ T0,   // x-src pixels
                const __half* __restrict__ W0,   // x weights
                const __half* __restrict__ T1,   // h-src pixels
                const __half* __restrict__ W1,   // h weights
                int nsrc,
                const float* __restrict__ Wc,
                const float* __restrict__ bias,
                float* __restrict__ cbuf,        // c state (in/out)
                __half* __restrict__ Tout,       // new h, transposed fp16
                const float* __restrict__ xp,    // enc0 only
                const float* __restrict__ wx9,   // enc0 only (256,1,3,3)
                int t)
{
    extern __shared__ __align__(16) char smc[];
    const uint32_t smb = smem_u32(smc);
    float*  sE   = (float*)smc;
    __half* sH   = (__half*)(smc + SH_OFF);
    float*  s_w9 = (float*)(smc + SW9_OFF);

    const int tid  = threadIdx.x;
    const int lane = tid & 31;
    const int warp = tid >> 5;
    const int wm   = warp >> 2;
    const int wn   = warp & 3;
    const int nt   = blockIdx.x;     // 0..127
    const int mt   = blockIdx.y;     // 0..1
    const int b    = nt >> 4;
    const int y0   = (nt & 15) << 2;

    const int a_row_l = lane & 15;
    const int a_col_l = (lane >> 4) * 8;
    const int b_row_l = (lane & 7) + ((lane >> 4) << 3);
    const int b_col_l = ((lane >> 3) & 1) * 8;

    if (xp) for (int i = tid; i < 2304; i += 256) s_w9[i] = wx9[i];

    float acc[4][8][4];
    #pragma unroll
    for (int mi = 0; mi < 4; mi++)
        #pragma unroll
        for (int ni = 0; ni < 8; ni++)
            #pragma unroll
            for (int r = 0; r < 4; r++) acc[mi][ni][r] = 0.f;

    for (int s = 0; s < nsrc; s++) {
        const __half* T = s ? T1 : T0;
        const __half* W = s ? W1 : W0;

        __syncthreads();
        // fill B: 396 rows x 8 vec16
        for (int i = tid; i < 3168; i += 256) {
            int p = i >> 3, v = i & 7;
            int r = p / TROW, px = p - r * TROW;
            const __half* src =
                T + (((size_t)b * TROW + (y0 + r)) * TROW + px) * 64 + v * 8;
            cp16(smb + SB_OFF + p * 144 + v * 16, src);
        }
        // fill A tap0
        for (int i = tid; i < 1024; i += 256) {
            int m = i >> 3, v = i & 7;
            const __half* src = W + (mt * 128 + m) * 64 + v * 8;
            cp16(smb + SA_OFF + m * 144 + v * 16, src);
        }
        CP_COMMIT();

        for (int tap = 0; tap < 9; tap++) {
            CP_WAIT0();
            __syncthreads();
            if (tap < 8) {
                const int nb = (tap + 1) & 1;
                for (int i = tid; i < 1024; i += 256) {
                    int m = i >> 3, v = i & 7;
                    const __half* src = W + (tap + 1) * 16384 + (mt * 128 + m) * 64 + v * 8;
                    cp16(smb + SA_OFF + nb * SA_BUF + m * 144 + v * 16, src);
                }
                CP_COMMIT();
            }

            const int dy = tap / 3, dx = tap - dy * 3;
            const int prow_base = (wn + dy) * TROW + dx;
            const uint32_t aBase = smb + SA_OFF + (tap & 1) * SA_BUF;
            const uint32_t bBase = smb + SB_OFF;

            #pragma unroll
            for (int ks = 0; ks < 4; ks++) {
                unsigned bfr[4][4];
                #pragma unroll
                for (int p2 = 0; p2 < 4; p2++)
                    ldm_x4(bfr[p2], bBase + (prow_base + p2 * 16 + b_row_l) * 144
                                          + (ks * 16 + b_col_l) * 2);
                unsigned afr[4][4];
                #pragma unroll
                for (int mi = 0; mi < 4; mi++)
                    ldm_x4(afr[mi], aBase + (wm * 64 + mi * 16 + a_row_l) * 144
                                          + (a_col_l + ks * 16) * 2);
                #pragma unroll
                for (int p2 = 0; p2 < 4; p2++)
                    #pragma unroll
                    for (int mi = 0; mi < 4; mi++) {
                        mma16816(acc[mi][2 * p2],     afr[mi], bfr[p2][0], bfr[p2][1]);
                        mma16816(acc[mi][2 * p2 + 1], afr[mi], bfr[p2][2], bfr[p2][3]);
                    }
            }
        }
    }

    // ---- epilogue ----
    __syncthreads();
    const int gr = lane >> 2, ci = lane & 3;
    #pragma unroll
    for (int mi = 0; mi < 4; mi++)
        #pragma unroll
        for (int ni = 0; ni < 8; ni++) {
            int r0 = wm * 64 + mi * 16 + gr;
            int n  = wn * 64 + ni * 8 + 2 * ci;
            *(float2*)(sE + r0 * ESTR + n)       = make_float2(acc[mi][ni][0], acc[mi][ni][1]);
            *(float2*)(sE + (r0 + 8) * ESTR + n) = make_float2(acc[mi][ni][2], acc[mi][ni][3]);
        }
    __syncthreads();

    #pragma unroll 1
    for (int ii = 0; ii < 8; ii++) {
        int pl  = lane + 32 * ii;
        int pix = y0 * 64 + pl;
        float xv[9];
        if (xp) {
            int y = pix >> 6, xx = pix & 63;
            #pragma unroll
            for (int tap = 0; tap < 9; tap++) {
                int gy = y + tap / 3 - 1, gx = xx + tap % 3 - 1;
                xv[tap] = ((unsigned)gy < 64u && (unsigned)gx < 64u)
                          ? xp[((size_t)b * TT + t) * 4096 + gy * 64 + gx] : 0.f;
            }
        }
        #pragma unroll 1
        for (int jj = 0; jj < 4; jj++) {
            int col = warp + 8 * jj;          // 0..31 local channel
            int co  = mt * 32 + col;
            int bb  = (b * 64 + co) * 4096 + pix;
            float cold = cbuf[bb];
            float pre[4];
            #pragma unroll
            for (int g = 0; g < 4; g++) {
                int base = (g * 64 + co) * 4096 + pix;
                pre[g] = sE[(col * 4 + g) * ESTR + pl] + Wc[base] * cold + bias[base];
            }
            if (xp) {
                #pragma unroll
                for (int g = 0; g < 4; g++) {
                    const float* w9 = s_w9 + (g * 64 + co) * 9;
                    float s0 = 0.f;
                    #pragma unroll
                    for (int tap = 0; tap < 9; tap++) s0 += w9[tap] * xv[tap];
                    pre[g] += s0;
                }
            }
            float ig = sigf(pre[0]);
            float fg = sigf(pre[1]);
            float gg = tanhf_fast(pre[2]);
            float og = sigf(pre[3]);
            float cn = fg * cold + ig * gg;
            cbuf[bb] = cn;
            sH[pl * HSTR + col] = __float2half_rn(og * tanhf_fast(cn));
        }
    }
    __syncthreads();

    // coalesced copy-out: sH [256 px][32 ch] -> Tout (padded transposed layout)
    for (int i = tid; i < 1024; i += 256) {
        int px = i >> 2, q = i & 3;
        int pix = y0 * 64 + px;
        int y = pix >> 6, x = pix & 63;
        __half* dst = Tout + (((size_t)b * TROW + (y + 1)) * TROW + (x + 1)) * 64
                      + mt * 32 + q * 8;
        *(uint4*)dst = *(const uint4*)(sH + px * HSTR + q * 8);
    }
}

// ---------------------------------------------------------------------------
// Final 3x3 conv (HID->1) + bias + sigmoid, reading haloed fp16 T
// ---------------------------------------------------------------------------
__global__ void __launch_bounds__(256)
final_conv_kernel(const __half* __restrict__ T,
                  const float* __restrict__ fw,
                  const float* __restrict__ fb,
                  float* __restrict__ out, int t)
{
    __shared__ float s_w[9 * 64];   // [tap][c]
    int tid = threadIdx.x;
    for (int i = tid; i < 576; i += 256) {
        int tap = i >> 6, c = i & 63;
        s_w[tap * 64 + c] = fw[c * 9 + tap];
    }
    __syncthreads();

    int pix = blockIdx.x * 256 + tid;
    int b   = blockIdx.y;
    int y = pix >> 6, x = pix & 63;
    float sum = fb[0];
    #pragma unroll
    for (int tap = 0; tap < 9; tap++) {
        int dy = tap / 3, dx = tap % 3;
        const __half* row =
            T + (((size_t)b * TROW + (y + dy)) * TROW + (x + dx)) * 64;
        const float* wt = s_w + tap * 64;
        #pragma unroll
        for (int c8 = 0; c8 < 8; c8++) {
            uint4 v = *(const uint4*)(row + c8 * 8);
            const __half* hv = (const __half*)&v;
            #pragma unroll
            for (int k = 0; k < 8; k++)
                sum += wt[c8 * 8 + k] * __half2float(hv[k]);
        }
    }
    out[(size_t)b * (PRED * PIX) + t * PIX + pix] = sigf(sum);
}

// ---------------------------------------------------------------------------
extern "C" void kernel_launch(void* const* d_in, const int* in_sizes, int n_in,
                              void* d_out, int out_size)
{
    const float* x    = (const float*)d_in[0];
    const float* e0Wx = (const float*)d_in[1];
    const float* e0Wh = (const float*)d_in[2];
    const float* e0Wc = (const float*)d_in[3];
    const float* e0b  = (const float*)d_in[4];
    const float* e1Wx = (const float*)d_in[5];
    const float* e1Wh = (const float*)d_in[6];
    const float* e1Wc = (const float*)d_in[7];
    const float* e1b  = (const float*)d_in[8];
    const float* d0Wx = (const float*)d_in[9];
    const float* d0Wh = (const float*)d_in[10];
    const float* d0Wc = (const float*)d_in[11];
    const float* d0b  = (const float*)d_in[12];
    const float* d1Wx = (const float*)d_in[13];
    const float* d1Wh = (const float*)d_in[14];
    const float* d1Wc = (const float*)d_in[15];
    const float* d1b  = (const float*)d_in[16];
    const float* finw = (const float*)d_in[17];
    const float* finb = (const float*)d_in[18];
    float* out = (float*)d_out;

    cudaFuncSetAttribute(cell_mma_kernel,
                         cudaFuncAttributeMaxDynamicSharedMemorySize, SM_TOTAL);

    float* cbuf;
    __half *Tbuf, *Wbuf;
    cudaGetSymbolAddress((void**)&cbuf, g_c);
    cudaGetSymbolAddress((void**)&Tbuf, g_T);
    cudaGetSymbolAddress((void**)&Wbuf, g_W);

    float* ec0 = cbuf + 0 * (size_t)NST;
    float* ec1 = cbuf + 1 * (size_t)NST;
    float* dc0 = cbuf + 2 * (size_t)NST;
    float* dc1 = cbuf + 3 * (size_t)NST;
    __half* Te0[2] = { Tbuf + 0 * TSZ, Tbuf + 1 * TSZ };
    __half* Te1[2] = { Tbuf + 2 * TSZ, Tbuf + 3 * TSZ };
    __half* Td0[2] = { Tbuf + 4 * TSZ, Tbuf + 5 * TSZ };
    __half* Td1[2] = { Tbuf + 6 * TSZ, Tbuf + 7 * TSZ };
    __half* W_e0h = Wbuf + 0 * (size_t)WSZ;
    __half* W_e1x = Wbuf + 1 * (size_t)WSZ;
    __half* W_e1h = Wbuf + 2 * (size_t)WSZ;
    __half* W_d0x = Wbuf + 3 * (size_t)WSZ;
    __half* W_d0h = Wbuf + 4 * (size_t)WSZ;
    __half* W_d1x = Wbuf + 5 * (size_t)WSZ;
    __half* W_d1h = Wbuf + 6 * (size_t)WSZ;

    int wg = (WSZ + 255) / 256;
    wsplit_kernel<<<wg, 256>>>(e0Wh, W_e0h);
    wsplit_kernel<<<wg, 256>>>(e1Wx, W_e1x);
    wsplit_kernel<<<wg, 256>>>(e1Wh, W_e1h);
    wsplit_kernel<<<wg, 256>>>(d0Wx, W_d0x);
    wsplit_kernel<<<wg, 256>>>(d0Wh, W_d0h);
    wsplit_kernel<<<wg, 256>>>(d1Wx, W_d1x);
    wsplit_kernel<<<wg, 256>>>(d1Wh, W_d1h);

    cudaMemsetAsync(cbuf, 0, (size_t)4 * NST * sizeof(float));
    cudaMemsetAsync(Tbuf, 0, (size_t)8 * TSZ * sizeof(__half));

    dim3 cgrid(128, 2), cblk(256);

    // Encoder
    for (int t = 0; t < TT; t++) {
        int r = t & 1, w = r ^ 1;
        cell_mma_kernel<<<cgrid, cblk, SM_TOTAL>>>(Te0[r], W_e0h, Te0[r], W_e0h, 1,
                                                   e0Wc, e0b, ec0, Te0[w], x, e0Wx, t);
        cell_mma_kernel<<<cgrid, cblk, SM_TOTAL>>>(Te0[w], W_e1x, Te1[r], W_e1h, 2,
                                                   e1Wc, e1b, ec1, Te1[w], nullptr, nullptr, 0);
    }
    // final encoder h1 in Te1[0] (t=9: w=0)

    // Decoder
    for (int t = 0; t < PRED; t++) {
        int r = t & 1, w = r ^ 1;
        const __half* Ts = (t == 0) ? Te1[0] : Td1[r];
        cell_mma_kernel<<<cgrid, cblk, SM_TOTAL>>>(Ts, W_d0x, Td0[r], W_d0h, 2,
                                                   d0Wc, d0b, dc0, Td0[w], nullptr, nullptr, 0);
        cell_mma_kernel<<<cgrid, cblk, SM_TOTAL>>>(Td0[w], W_d1x, Td1[r], W_d1h, 2,
                                                   d1Wc, d1b, dc1, Td1[w], nullptr, nullptr, 0);
        final_conv_kernel<<<dim3(16, BB), 256>>>(Td1[w], finw, finb, out, t);
    }
}

// round 11
// speedup vs baseline: 11.9019x; 1.1637x over previous
#include <cuda_runtime.h>
#include <cuda_fp16.h>
#include <math.h>
#include <stdint.h>

// Problem constants
#define BB   8
#define TT   10
#define HH   64
#define WW   64
#define HID  64
#define PRED 10
#define PIX  (HH*WW)              // 4096
#define NST  (BB*HID*PIX)
#define TROW 66
#define TSZ  ((size_t)BB*TROW*TROW*HID)   // elems of one transposed fp16 tensor
#define WSZ  (9*256*64)           // fp16 weights per tensor

// ---------------------------------------------------------------------------
// Static scratch
// ---------------------------------------------------------------------------
__device__ float g_c[4][NST];                                   // c states
__device__ __align__(16) __half g_T[4][2 * BB*TROW*TROW*HID];   // h, ping-pong
__device__ __align__(16) __half g_W[7][WSZ];

// ---------------------------------------------------------------------------
// Weight transform: w (256,64,3,3) -> wt[tap][m][k] fp16, m = co*4 + g
// ---------------------------------------------------------------------------
__global__ void wsplit_kernel(const float* __restrict__ w, __half* __restrict__ wt)
{
    int i = blockIdx.x * blockDim.x + threadIdx.x;
    if (i >= WSZ) return;
    int c   = i & 63;
    int m   = (i >> 6) & 255;
    int tap = i >> 14;
    int co = m >> 2, g = m & 3;
    wt[i] = __float2half_rn(w[((g * 64 + co) * 64 + c) * 9 + tap]);
}

// ---------------------------------------------------------------------------
// low-level helpers
// ---------------------------------------------------------------------------
__device__ __forceinline__ uint32_t smem_u32(const void* p) {
    uint32_t a;
    asm("{ .reg .u64 t; cvta.to.shared.u64 t, %1; cvt.u32.u64 %0, t; }" : "=r"(a) : "l"(p));
    return a;
}
__device__ __forceinline__ void cp16(uint32_t dst, const void* src) {
    asm volatile("cp.async.cg.shared.global [%0], [%1], 16;" :: "r"(dst), "l"(src));
}
#define CP_COMMIT() asm volatile("cp.async.commit_group;" ::: "memory")
#define CP_WAIT0()  asm volatile("cp.async.wait_group 0;" ::: "memory")

__device__ __forceinline__ void ldm_x4(unsigned* r, uint32_t addr) {
    asm volatile("ldmatrix.sync.aligned.m8n8.x4.shared.b16 {%0,%1,%2,%3}, [%4];"
        : "=r"(r[0]), "=r"(r[1]), "=r"(r[2]), "=r"(r[3]) : "r"(addr));
}
__device__ __forceinline__ void mma16816(float* d, const unsigned* a,
                                         unsigned b0, unsigned b1)
{
    asm("mma.sync.aligned.m16n8k16.row.col.f32.f16.f16.f32 "
        "{%0,%1,%2,%3}, {%4,%5,%6,%7}, {%8,%9}, {%0,%1,%2,%3};"
        : "+f"(d[0]), "+f"(d[1]), "+f"(d[2]), "+f"(d[3])
        : "r"(a[0]), "r"(a[1]), "r"(a[2]), "r"(a[3]), "r"(b0), "r"(b1));
}

// Fast activations (EX2/RCP; error « fp16 mma noise floor)
__device__ __forceinline__ float ex2f(float x) {
    float r; asm("ex2.approx.f32 %0, %1;" : "=f"(r) : "f"(x)); return r;
}
__device__ __forceinline__ float rcpf(float x) {
    float r; asm("rcp.approx.f32 %0, %1;" : "=f"(r) : "f"(x)); return r;
}
#define LOG2E 1.4426950408889634f
__device__ __forceinline__ float sigf(float v) {
    return rcpf(1.f + ex2f(-v * LOG2E));
}
__device__ __forceinline__ float tanhf_fast(float v) {
    return 1.f - 2.f * rcpf(1.f + ex2f(2.f * LOG2E * v));
}

// SMEM layout (bytes), sized for 2 CTAs/SM:
//   A tiles: 2 bufs x 128 rows x 144B      = 36864   [0 .. 36864)
//   B tile : 264 rows x 144B               = 38016   [36864 .. 74880)
//   sE (128 gate-rows x 136 f32 = 69632) overlays A+B
//   sH (128 px x 40 fp16 = 10240)          [74880 .. 85120)
//   NOTE: HSTR must keep 16B alignment of rows (40 halves = 80 B = 5x16B).
#define SA_OFF   0
#define SA_BUF   18432
#define SB_OFF   36864
#define SH_OFF   74880
#define SM_TOTAL 85120
#define ESTR     136
#define HSTR     40

// ---------------------------------------------------------------------------
// Fused ConvLSTM cell: fp16 mma, single product, fused transpose-out.
// CTA: M=128 gate-rows (mt half -> channels mt*32..mt*32+31), N=128 px
// (2 image rows of one batch). 8 warps: wm {0,1} x wn {0..3}; warp 64m x 32n.
// 2 CTAs/SM: co-resident CTA's mma hides this CTA's fills + epilogue.
// ---------------------------------------------------------------------------
__global__ void __launch_bounds__(256, 2)
cell_mma_kernel(const __half* __restrict__ T0,   // x-src pixels
                const __half* __restrict__ W0,   // x weights
                const __half* __restrict__ T1,   // h-src pixels
                const __half* __restrict__ W1,   // h weights
                int nsrc,
                const float* __restrict__ Wc,
                const float* __restrict__ bias,
                float* __restrict__ cbuf,        // c state (in/out)
                __half* __restrict__ Tout,       // new h, transposed fp16
                const float* __restrict__ xp,    // enc0 only
                const float* __restrict__ wx9,   // enc0 only (256,1,3,3)
                int t)
{
    extern __shared__ __align__(16) char smc[];
    const uint32_t smb = smem_u32(smc);
    float*  sE = (float*)smc;
    __half* sH = (__half*)(smc + SH_OFF);

    const int tid  = threadIdx.x;
    const int lane = tid & 31;
    const int warp = tid >> 5;
    const int wm   = warp >> 2;      // 0..1
    const int wn   = warp & 3;       // 0..3
    const int nt   = blockIdx.x;     // 0..255
    const int mt   = blockIdx.y;     // 0..1
    const int b    = nt >> 5;
    const int y0   = (nt & 31) << 1; // first of 2 image rows

    const int a_row_l = lane & 15;
    const int a_col_l = (lane >> 4) * 8;
    const int b_row_l = (lane & 7) + ((lane >> 4) << 3);
    const int b_col_l = ((lane >> 3) & 1) * 8;

    float acc[4][4][4];
    #pragma unroll
    for (int mi = 0; mi < 4; mi++)
        #pragma unroll
        for (int ni = 0; ni < 4; ni++)
            #pragma unroll
            for (int r = 0; r < 4; r++) acc[mi][ni][r] = 0.f;

    for (int s = 0; s < nsrc; s++) {
        const __half* T = s ? T1 : T0;
        const __half* W = s ? W1 : W0;

        __syncthreads();
        // fill B: 264 padded rows (4 rows x 66 px) x 8 vec16
        for (int i = tid; i < 2112; i += 256) {
            int p = i >> 3, v = i & 7;
            int r = p / TROW, px = p - r * TROW;
            const __half* src =
                T + (((size_t)b * TROW + (y0 + r)) * TROW + px) * 64 + v * 8;
            cp16(smb + SB_OFF + p * 144 + v * 16, src);
        }
        // fill A tap0
        for (int i = tid; i < 1024; i += 256) {
            int m = i >> 3, v = i & 7;
            const __half* src = W + (mt * 128 + m) * 64 + v * 8;
            cp16(smb + SA_OFF + m * 144 + v * 16, src);
        }
        CP_COMMIT();

        for (int tap = 0; tap < 9; tap++) {
            CP_WAIT0();
            __syncthreads();
            if (tap < 8) {
                const int nb = (tap + 1) & 1;
                for (int i = tid; i < 1024; i += 256) {
                    int m = i >> 3, v = i & 7;
                    const __half* src = W + (tap + 1) * 16384 + (mt * 128 + m) * 64 + v * 8;
                    cp16(smb + SA_OFF + nb * SA_BUF + m * 144 + v * 16, src);
                }
                CP_COMMIT();
            }

            const int dy = tap / 3, dx = tap - dy * 3;
            const int ylocal = wn >> 1, xlocal = (wn & 1) * 32;
            const int prow_base = (ylocal + dy) * TROW + xlocal + dx;
            const uint32_t aBase = smb + SA_OFF + (tap & 1) * SA_BUF;
            const uint32_t bBase = smb + SB_OFF;

            #pragma unroll
            for (int ks = 0; ks < 4; ks++) {
                unsigned bfr[2][4];
                #pragma unroll
                for (int p2 = 0; p2 < 2; p2++)
                    ldm_x4(bfr[p2], bBase + (prow_base + p2 * 16 + b_row_l) * 144
                                          + (ks * 16 + b_col_l) * 2);
                unsigned afr[4][4];
                #pragma unroll
                for (int mi = 0; mi < 4; mi++)
                    ldm_x4(afr[mi], aBase + (wm * 64 + mi * 16 + a_row_l) * 144
                                          + (a_col_l + ks * 16) * 2);
                #pragma unroll
                for (int p2 = 0; p2 < 2; p2++)
                    #pragma unroll
                    for (int mi = 0; mi < 4; mi++) {
                        mma16816(acc[mi][2 * p2],     afr[mi], bfr[p2][0], bfr[p2][1]);
                        mma16816(acc[mi][2 * p2 + 1], afr[mi], bfr[p2][2], bfr[p2][3]);
                    }
            }
        }
    }

    // ---- epilogue ----
    __syncthreads();   // all mma done; safe to overwrite A/B smem with sE
    const int gr = lane >> 2, ci = lane & 3;
    #pragma unroll
    for (int mi = 0; mi < 4; mi++)
        #pragma unroll
        for (int ni = 0; ni < 4; ni++) {
            int r0 = wm * 64 + mi * 16 + gr;
            int n  = wn * 32 + ni * 8 + 2 * ci;
            *(float2*)(sE + r0 * ESTR + n)       = make_float2(acc[mi][ni][0], acc[mi][ni][1]);
            *(float2*)(sE + (r0 + 8) * ESTR + n) = make_float2(acc[mi][ni][2], acc[mi][ni][3]);
        }
    __syncthreads();

    #pragma unroll 1
    for (int ii = 0; ii < 4; ii++) {
        int pl  = lane + 32 * ii;            // 0..127
        int pix = y0 * 64 + pl;
        float xv[9];
        if (xp) {
            int y = pix >> 6, xx = pix & 63;
            #pragma unroll
            for (int tap = 0; tap < 9; tap++) {
                int gy = y + tap / 3 - 1, gx = xx + tap % 3 - 1;
                xv[tap] = ((unsigned)gy < 64u && (unsigned)gx < 64u)
                          ? xp[((size_t)b * TT + t) * 4096 + gy * 64 + gx] : 0.f;
            }
        }
        #pragma unroll 1
        for (int jj = 0; jj < 4; jj++) {
            int col = warp + 8 * jj;          // 0..31 local channel
            int co  = mt * 32 + col;
            int bb  = (b * 64 + co) * 4096 + pix;
            float cold = cbuf[bb];
            float pre[4];
            #pragma unroll
            for (int g = 0; g < 4; g++) {
                int base = (g * 64 + co) * 4096 + pix;
                pre[g] = sE[(col * 4 + g) * ESTR + pl] + Wc[base] * cold + bias[base];
            }
            if (xp) {
                #pragma unroll
                for (int g = 0; g < 4; g++) {
                    const float* w9 = wx9 + (size_t)(g * 64 + co) * 9;  // warp-uniform
                    float s0 = 0.f;
                    #pragma unroll
                    for (int tap = 0; tap < 9; tap++) s0 += __ldg(w9 + tap) * xv[tap];
                    pre[g] += s0;
                }
            }
            float ig = sigf(pre[0]);
            float fg = sigf(pre[1]);
            float gg = tanhf_fast(pre[2]);
            float og = sigf(pre[3]);
            float cn = fg * cold + ig * gg;
            cbuf[bb] = cn;
            sH[pl * HSTR + col] = __float2half_rn(og * tanhf_fast(cn));
        }
    }
    __syncthreads();

    // coalesced copy-out: sH [128 px][32 ch] -> Tout (padded transposed layout)
    // sH row stride = 40 halves = 80 B (16B-aligned), so uint4 reads are legal.
    for (int i = tid; i < 512; i += 256) {
        int px = i >> 2, q = i & 3;
        int pix = y0 * 64 + px;
        int y = pix >> 6, x = pix & 63;
        __half* dst = Tout + (((size_t)b * TROW + (y + 1)) * TROW + (x + 1)) * 64
                      + mt * 32 + q * 8;
        *(uint4*)dst = *(const uint4*)(sH + px * HSTR + q * 8);
    }
}

// ---------------------------------------------------------------------------
// Final 3x3 conv (HID->1) + bias + sigmoid, reading haloed fp16 T
// ---------------------------------------------------------------------------
__global__ void __launch_bounds__(256)
final_conv_kernel(const __half* __restrict__ T,
                  const float* __restrict__ fw,
                  const float* __restrict__ fb,
                  float* __restrict__ out, int t)
{
    __shared__ float s_w[9 * 64];   // [tap][c]
    int tid = threadIdx.x;
    for (int i = tid; i < 576; i += 256) {
        int tap = i >> 6, c = i & 63;
        s_w[tap * 64 + c] = fw[c * 9 + tap];
    }
    __syncthreads();

    int pix = blockIdx.x * 256 + tid;
    int b   = blockIdx.y;
    int y = pix >> 6, x = pix & 63;
    float sum = fb[0];
    #pragma unroll
    for (int tap = 0; tap < 9; tap++) {
        int dy = tap / 3, dx = tap % 3;
        const __half* row =
            T + (((size_t)b * TROW + (y + dy)) * TROW + (x + dx)) * 64;
        const float* wt = s_w + tap * 64;
        #pragma unroll
        for (int c8 = 0; c8 < 8; c8++) {
            uint4 v = *(const uint4*)(row + c8 * 8);
            const __half* hv = (const __half*)&v;
            #pragma unroll
            for (int k = 0; k < 8; k++)
                sum += wt[c8 * 8 + k] * __half2float(hv[k]);
        }
    }
    out[(size_t)b * (PRED * PIX) + t * PIX + pix] = sigf(sum);
}

// ---------------------------------------------------------------------------
extern "C" void kernel_launch(void* const* d_in, const int* in_sizes, int n_in,
                              void* d_out, int out_size)
{
    const float* x    = (const float*)d_in[0];
    const float* e0Wx = (const float*)d_in[1];
    const float* e0Wh = (const float*)d_in[2];
    const float* e0Wc = (const float*)d_in[3];
    const float* e0b  = (const float*)d_in[4];
    const float* e1Wx = (const float*)d_in[5];
    const float* e1Wh = (const float*)d_in[6];
    const float* e1Wc = (const float*)d_in[7];
    const float* e1b  = (const float*)d_in[8];
    const float* d0Wx = (const float*)d_in[9];
    const float* d0Wh = (const float*)d_in[10];
    const float* d0Wc = (const float*)d_in[11];
    const float* d0b  = (const float*)d_in[12];
    const float* d1Wx = (const float*)d_in[13];
    const float* d1Wh = (const float*)d_in[14];
    const float* d1Wc = (const float*)d_in[15];
    const float* d1b  = (const float*)d_in[16];
    const float* finw = (const float*)d_in[17];
    const float* finb = (const float*)d_in[18];
    float* out = (float*)d_out;

    cudaFuncSetAttribute(cell_mma_kernel,
                         cudaFuncAttributeMaxDynamicSharedMemorySize, SM_TOTAL);

    float* cbuf;
    __half *Tbuf, *Wbuf;
    cudaGetSymbolAddress((void**)&cbuf, g_c);
    cudaGetSymbolAddress((void**)&Tbuf, g_T);
    cudaGetSymbolAddress((void**)&Wbuf, g_W);

    float* ec0 = cbuf + 0 * (size_t)NST;
    float* ec1 = cbuf + 1 * (size_t)NST;
    float* dc0 = cbuf + 2 * (size_t)NST;
    float* dc1 = cbuf + 3 * (size_t)NST;
    __half* Te0[2] = { Tbuf + 0 * TSZ, Tbuf + 1 * TSZ };
    __half* Te1[2] = { Tbuf + 2 * TSZ, Tbuf + 3 * TSZ };
    __half* Td0[2] = { Tbuf + 4 * TSZ, Tbuf + 5 * TSZ };
    __half* Td1[2] = { Tbuf + 6 * TSZ, Tbuf + 7 * TSZ };
    __half* W_e0h = Wbuf + 0 * (size_t)WSZ;
    __half* W_e1x = Wbuf + 1 * (size_t)WSZ;
    __half* W_e1h = Wbuf + 2 * (size_t)WSZ;
    __half* W_d0x = Wbuf + 3 * (size_t)WSZ;
    __half* W_d0h = Wbuf + 4 * (size_t)WSZ;
    __half* W_d1x = Wbuf + 5 * (size_t)WSZ;
    __half* W_d1h = Wbuf + 6 * (size_t)WSZ;

    int wg = (WSZ + 255) / 256;
    wsplit_kernel<<<wg, 256>>>(e0Wh, W_e0h);
    wsplit_kernel<<<wg, 256>>>(e1Wx, W_e1x);
    wsplit_kernel<<<wg, 256>>>(e1Wh, W_e1h);
    wsplit_kernel<<<wg, 256>>>(d0Wx, W_d0x);
    wsplit_kernel<<<wg, 256>>>(d0Wh, W_d0h);
    wsplit_kernel<<<wg, 256>>>(d1Wx, W_d1x);
    wsplit_kernel<<<wg, 256>>>(d1Wh, W_d1h);

    cudaMemsetAsync(cbuf, 0, (size_t)4 * NST * sizeof(float));
    cudaMemsetAsync(Tbuf, 0, (size_t)8 * TSZ * sizeof(__half));

    dim3 cgrid(256, 2), cblk(256);

    // Encoder
    for (int t = 0; t < TT; t++) {
        int r = t & 1, w = r ^ 1;
        cell_mma_kernel<<<cgrid, cblk, SM_TOTAL>>>(Te0[r], W_e0h, Te0[r], W_e0h, 1,
                                                   e0Wc, e0b, ec0, Te0[w], x, e0Wx, t);
        cell_mma_kernel<<<cgrid, cblk, SM_TOTAL>>>(Te0[w], W_e1x, Te1[r], W_e1h, 2,
                                                   e1Wc, e1b, ec1, Te1[w], nullptr, nullptr, 0);
    }
    // final encoder h1 in Te1[0] (t=9: w=0)

    // Decoder
    for (int t = 0; t < PRED; t++) {
        int r = t & 1, w = r ^ 1;
        const __half* Ts = (t == 0) ? Te1[0] : Td1[r];
        cell_mma_kernel<<<cgrid, cblk, SM_TOTAL>>>(Ts, W_d0x, Td0[r], W_d0h, 2,
                                                   d0Wc, d0b, dc0, Td0[w], nullptr, nullptr, 0);
        cell_mma_kernel<<<cgrid, cblk, SM_TOTAL>>>(Td0[w], W_d1x, Td1[r], W_d1h, 2,
                                                   d1Wc, d1b, dc1, Td1[w], nullptr, nullptr, 0);
        final_conv_kernel<<<dim3(16, BB), 256>>>(Td1[w], finw, finb, out, t);
    }
}

// round 12
// speedup vs baseline: 13.0653x; 1.0977x over previous
#include <cuda_runtime.h>
#include <cuda_fp16.h>
#include <math.h>
#include <stdint.h>

// Problem constants
#define BB   8
#define TT   10
#define HH   64
#define WW   64
#define HID  64
#define PRED 10
#define PIX  (HH*WW)              // 4096
#define NST  (BB*HID*PIX)
#define TROW 66
#define TSZ  ((size_t)BB*TROW*TROW*HID)   // elems of one transposed fp16 tensor
#define WSZ  (9*256*64)           // fp16 weights per tensor

// ---------------------------------------------------------------------------
// Static scratch
// ---------------------------------------------------------------------------
__device__ float g_c[4][NST];                                   // c states
__device__ __align__(16) __half g_T[4][2 * BB*TROW*TROW*HID];   // h, ping-pong
__device__ __align__(16) __half g_W[7][WSZ];

// ---------------------------------------------------------------------------
// Weight transform: w (256,64,3,3) -> wt[tap][m][k] fp16, m = co*4 + g.
// z selects which of the 7 weight tensors (merged launch).
// ---------------------------------------------------------------------------
__global__ void wsplit_kernel(const float* w0, const float* w1, const float* w2,
                              const float* w3, const float* w4, const float* w5,
                              const float* w6, __half* __restrict__ wt_base)
{
    int i = blockIdx.x * blockDim.x + threadIdx.x;
    if (i >= WSZ) return;
    int z = blockIdx.z;
    const float* w;
    switch (z) {
        case 0: w = w0; break;  case 1: w = w1; break;
        case 2: w = w2; break;  case 3: w = w3; break;
        case 4: w = w4; break;  case 5: w = w5; break;
        default: w = w6; break;
    }
    __half* wt = wt_base + (size_t)z * WSZ;
    int c   = i & 63;
    int m   = (i >> 6) & 255;
    int tap = i >> 14;
    int co = m >> 2, g = m & 3;
    wt[i] = __float2half_rn(w[((g * 64 + co) * 64 + c) * 9 + tap]);
}

// ---------------------------------------------------------------------------
// low-level helpers
// ---------------------------------------------------------------------------
__device__ __forceinline__ uint32_t smem_u32(const void* p) {
    uint32_t a;
    asm("{ .reg .u64 t; cvta.to.shared.u64 t, %1; cvt.u32.u64 %0, t; }" : "=r"(a) : "l"(p));
    return a;
}
__device__ __forceinline__ void cp16(uint32_t dst, const void* src) {
    asm volatile("cp.async.cg.shared.global [%0], [%1], 16;" :: "r"(dst), "l"(src));
}
#define CP_COMMIT() asm volatile("cp.async.commit_group;" ::: "memory")
#define CP_WAIT0()  asm volatile("cp.async.wait_group 0;" ::: "memory")

__device__ __forceinline__ void ldm_x4(unsigned* r, uint32_t addr) {
    asm volatile("ldmatrix.sync.aligned.m8n8.x4.shared.b16 {%0,%1,%2,%3}, [%4];"
        : "=r"(r[0]), "=r"(r[1]), "=r"(r[2]), "=r"(r[3]) : "r"(addr));
}
__device__ __forceinline__ void mma16816(float* d, const unsigned* a,
                                         unsigned b0, unsigned b1)
{
    asm("mma.sync.aligned.m16n8k16.row.col.f32.f16.f16.f32 "
        "{%0,%1,%2,%3}, {%4,%5,%6,%7}, {%8,%9}, {%0,%1,%2,%3};"
        : "+f"(d[0]), "+f"(d[1]), "+f"(d[2]), "+f"(d[3])
        : "r"(a[0]), "r"(a[1]), "r"(a[2]), "r"(a[3]), "r"(b0), "r"(b1));
}

// Fast activations (EX2/RCP; error « fp16 mma noise floor)
__device__ __forceinline__ float ex2f(float x) {
    float r; asm("ex2.approx.f32 %0, %1;" : "=f"(r) : "f"(x)); return r;
}
__device__ __forceinline__ float rcpf(float x) {
    float r; asm("rcp.approx.f32 %0, %1;" : "=f"(r) : "f"(x)); return r;
}
#define LOG2E 1.4426950408889634f
__device__ __forceinline__ float sigf(float v) {
    return rcpf(1.f + ex2f(-v * LOG2E));
}
__device__ __forceinline__ float tanhf_fast(float v) {
    return 1.f - 2.f * rcpf(1.f + ex2f(2.f * LOG2E * v));
}

// SMEM layout (bytes), 2 CTAs/SM:
//   A tiles: 2 bufs x 128 rows x 144B      = 36864   [0 .. 36864)
//   B tile : 264 rows x 144B               = 38016   [36864 .. 74880)
//   sE (128 gate-rows x 136 f32 = 69632) overlays A+B
//   sH (128 px x 40 fp16 = 10240)          [74880 .. 85120)   (80B rows, 16B-aligned)
#define SA_OFF   0
#define SA_BUF   18432
#define SB_OFF   36864
#define SH_OFF   74880
#define SM_TOTAL 85120
#define ESTR     136
#define HSTR     40

// ---------------------------------------------------------------------------
// Work descriptor: one cell OR one final-conv, selected per grid-z slice.
// ---------------------------------------------------------------------------
struct CellArgs {
    const __half* T0;   // cell: x-src pixels | final: input T
    const __half* W0;   // cell: x weights
    const __half* T1;   // cell: h-src pixels
    const __half* W1;   // cell: h weights
    int nsrc;
    const float*  Wc;   // cell: Wc          | final: fw
    const float*  bias; // cell: bias        | final: fb
    float*        cbuf; // cell: c state     | final: out
    __half*       Tout; // cell: h out
    const float*  xp;   // enc0 only
    const float*  wx9;  // enc0 only
    int t;
    int kind;           // 0 = cell, 1 = final conv, 2 = none
};

// ---------------------------------------------------------------------------
// Cell body (identical math to R11 kernel)
// ---------------------------------------------------------------------------
__device__ __forceinline__ void cell_body(const CellArgs& A, char* smc)
{
    const uint32_t smb = smem_u32(smc);
    float*  sE = (float*)smc;
    __half* sH = (__half*)(smc + SH_OFF);

    const int tid  = threadIdx.x;
    const int lane = tid & 31;
    const int warp = tid >> 5;
    const int wm   = warp >> 2;
    const int wn   = warp & 3;
    const int nt   = blockIdx.x;     // 0..255
    const int mt   = blockIdx.y;     // 0..1
    const int b    = nt >> 5;
    const int y0   = (nt & 31) << 1;

    const int a_row_l = lane & 15;
    const int a_col_l = (lane >> 4) * 8;
    const int b_row_l = (lane & 7) + ((lane >> 4) << 3);
    const int b_col_l = ((lane >> 3) & 1) * 8;

    float acc[4][4][4];
    #pragma unroll
    for (int mi = 0; mi < 4; mi++)
        #pragma unroll
        for (int ni = 0; ni < 4; ni++)
            #pragma unroll
            for (int r = 0; r < 4; r++) acc[mi][ni][r] = 0.f;

    for (int s = 0; s < A.nsrc; s++) {
        const __half* T = s ? A.T1 : A.T0;
        const __half* W = s ? A.W1 : A.W0;

        __syncthreads();
        for (int i = tid; i < 2112; i += 256) {
            int p = i >> 3, v = i & 7;
            int r = p / TROW, px = p - r * TROW;
            const __half* src =
                T + (((size_t)b * TROW + (y0 + r)) * TROW + px) * 64 + v * 8;
            cp16(smb + SB_OFF + p * 144 + v * 16, src);
        }
        for (int i = tid; i < 1024; i += 256) {
            int m = i >> 3, v = i & 7;
            const __half* src = W + (mt * 128 + m) * 64 + v * 8;
            cp16(smb + SA_OFF + m * 144 + v * 16, src);
        }
        CP_COMMIT();

        for (int tap = 0; tap < 9; tap++) {
            CP_WAIT0();
            __syncthreads();
            if (tap < 8) {
                const int nb = (tap + 1) & 1;
                for (int i = tid; i < 1024; i += 256) {
                    int m = i >> 3, v = i & 7;
                    const __half* src = W + (tap + 1) * 16384 + (mt * 128 + m) * 64 + v * 8;
                    cp16(smb + SA_OFF + nb * SA_BUF + m * 144 + v * 16, src);
                }
                CP_COMMIT();
            }

            const int dy = tap / 3, dx = tap - dy * 3;
            const int ylocal = wn >> 1, xlocal = (wn & 1) * 32;
            const int prow_base = (ylocal + dy) * TROW + xlocal + dx;
            const uint32_t aBase = smb + SA_OFF + (tap & 1) * SA_BUF;
            const uint32_t bBase = smb + SB_OFF;

            #pragma unroll
            for (int ks = 0; ks < 4; ks++) {
                unsigned bfr[2][4];
                #pragma unroll
                for (int p2 = 0; p2 < 2; p2++)
                    ldm_x4(bfr[p2], bBase + (prow_base + p2 * 16 + b_row_l) * 144
                                          + (ks * 16 + b_col_l) * 2);
                unsigned afr[4][4];
                #pragma unroll
                for (int mi = 0; mi < 4; mi++)
                    ldm_x4(afr[mi], aBase + (wm * 64 + mi * 16 + a_row_l) * 144
                                          + (a_col_l + ks * 16) * 2);
                #pragma unroll
                for (int p2 = 0; p2 < 2; p2++)
                    #pragma unroll
                    for (int mi = 0; mi < 4; mi++) {
                        mma16816(acc[mi][2 * p2],     afr[mi], bfr[p2][0], bfr[p2][1]);
                        mma16816(acc[mi][2 * p2 + 1], afr[mi], bfr[p2][2], bfr[p2][3]);
                    }
            }
        }
    }

    // ---- epilogue ----
    __syncthreads();
    const int gr = lane >> 2, ci = lane & 3;
    #pragma unroll
    for (int mi = 0; mi < 4; mi++)
        #pragma unroll
        for (int ni = 0; ni < 4; ni++) {
            int r0 = wm * 64 + mi * 16 + gr;
            int n  = wn * 32 + ni * 8 + 2 * ci;
            *(float2*)(sE + r0 * ESTR + n)       = make_float2(acc[mi][ni][0], acc[mi][ni][1]);
            *(float2*)(sE + (r0 + 8) * ESTR + n) = make_float2(acc[mi][ni][2], acc[mi][ni][3]);
        }
    __syncthreads();

    #pragma unroll 1
    for (int ii = 0; ii < 4; ii++) {
        int pl  = lane + 32 * ii;
        int pix = y0 * 64 + pl;
        float xv[9];
        if (A.xp) {
            int y = pix >> 6, xx = pix & 63;
            #pragma unroll
            for (int tap = 0; tap < 9; tap++) {
                int gy = y + tap / 3 - 1, gx = xx + tap % 3 - 1;
                xv[tap] = ((unsigned)gy < 64u && (unsigned)gx < 64u)
                          ? A.xp[((size_t)b * TT + A.t) * 4096 + gy * 64 + gx] : 0.f;
            }
        }
        #pragma unroll 1
        for (int jj = 0; jj < 4; jj++) {
            int col = warp + 8 * jj;
            int co  = mt * 32 + col;
            int bb  = (b * 64 + co) * 4096 + pix;
            float cold = A.cbuf[bb];
            float pre[4];
            #pragma unroll
            for (int g = 0; g < 4; g++) {
                int base = (g * 64 + co) * 4096 + pix;
                pre[g] = sE[(col * 4 + g) * ESTR + pl] + A.Wc[base] * cold + A.bias[base];
            }
            if (A.xp) {
                #pragma unroll
                for (int g = 0; g < 4; g++) {
                    const float* w9 = A.wx9 + (size_t)(g * 64 + co) * 9;
                    float s0 = 0.f;
                    #pragma unroll
                    for (int tap = 0; tap < 9; tap++) s0 += __ldg(w9 + tap) * xv[tap];
                    pre[g] += s0;
                }
            }
            float ig = sigf(pre[0]);
            float fg = sigf(pre[1]);
            float gg = tanhf_fast(pre[2]);
            float og = sigf(pre[3]);
            float cn = fg * cold + ig * gg;
            A.cbuf[bb] = cn;
            sH[pl * HSTR + col] = __float2half_rn(og * tanhf_fast(cn));
        }
    }
    __syncthreads();

    for (int i = tid; i < 512; i += 256) {
        int px = i >> 2, q = i & 3;
        int pix = y0 * 64 + px;
        int y = pix >> 6, x = pix & 63;
        __half* dst = A.Tout + (((size_t)b * TROW + (y + 1)) * TROW + (x + 1)) * 64
                      + mt * 32 + q * 8;
        *(uint4*)dst = *(const uint4*)(sH + px * HSTR + q * 8);
    }
}

// ---------------------------------------------------------------------------
// Final conv body: 3x3 (HID->1) + bias + sigmoid, reading haloed fp16 T.
// Active CTAs: mt==0 && nt<128 (maps to original (16,8) grid).
// ---------------------------------------------------------------------------
__device__ __forceinline__ void final_body(const CellArgs& A, char* smc)
{
    const int nt = blockIdx.x;
    const int mt = blockIdx.y;
    if (mt != 0 || nt >= 128) return;
    float* s_w = (float*)smc;   // 576 floats

    int tid = threadIdx.x;
    for (int i = tid; i < 576; i += 256) {
        int tap = i >> 6, c = i & 63;
        s_w[tap * 64 + c] = A.Wc[c * 9 + tap];
    }
    __syncthreads();

    int b  = nt >> 4;
    int pb = nt & 15;
    int pix = pb * 256 + tid;
    int y = pix >> 6, x = pix & 63;
    float sum = A.bias[0];
    #pragma unroll
    for (int tap = 0; tap < 9; tap++) {
        int dy = tap / 3, dx = tap % 3;
        const __half* row =
            A.T0 + (((size_t)b * TROW + (y + dy)) * TROW + (x + dx)) * 64;
        const float* wt = s_w + tap * 64;
        #pragma unroll
        for (int c8 = 0; c8 < 8; c8++) {
            uint4 v = *(const uint4*)(row + c8 * 8);
            const __half* hv = (const __half*)&v;
            #pragma unroll
            for (int k = 0; k < 8; k++)
                sum += wt[c8 * 8 + k] * __half2float(hv[k]);
        }
    }
    A.cbuf[(size_t)b * (PRED * PIX) + A.t * PIX + pix] = sigf(sum);
}

// ---------------------------------------------------------------------------
// Fused dispatcher: grid (256, 2, nz). Slice z=0 runs `a`, z=1 runs `b`.
// ---------------------------------------------------------------------------
__global__ void __launch_bounds__(256, 2)
fused_kernel(CellArgs a, CellArgs b)
{
    extern __shared__ __align__(16) char smc[];
    if (blockIdx.z == 0) {
        if (a.kind == 0)      cell_body(a, smc);
        else if (a.kind == 1) final_body(a, smc);
    } else {
        if (b.kind == 0)      cell_body(b, smc);
        else if (b.kind == 1) final_body(b, smc);
    }
}

// ---------------------------------------------------------------------------
extern "C" void kernel_launch(void* const* d_in, const int* in_sizes, int n_in,
                              void* d_out, int out_size)
{
    const float* x    = (const float*)d_in[0];
    const float* e0Wx = (const float*)d_in[1];
    const float* e0Wh = (const float*)d_in[2];
    const float* e0Wc = (const float*)d_in[3];
    const float* e0b  = (const float*)d_in[4];
    const float* e1Wx = (const float*)d_in[5];
    const float* e1Wh = (const float*)d_in[6];
    const float* e1Wc = (const float*)d_in[7];
    const float* e1b  = (const float*)d_in[8];
    const float* d0Wx = (const float*)d_in[9];
    const float* d0Wh = (const float*)d_in[10];
    const float* d0Wc = (const float*)d_in[11];
    const float* d0b  = (const float*)d_in[12];
    const float* d1Wx = (const float*)d_in[13];
    const float* d1Wh = (const float*)d_in[14];
    const float* d1Wc = (const float*)d_in[15];
    const float* d1b  = (const float*)d_in[16];
    const float* finw = (const float*)d_in[17];
    const float* finb = (const float*)d_in[18];
    float* out = (float*)d_out;

    cudaFuncSetAttribute(fused_kernel,
                         cudaFuncAttributeMaxDynamicSharedMemorySize, SM_TOTAL);

    float* cbuf;
    __half *Tbuf, *Wbuf;
    cudaGetSymbolAddress((void**)&cbuf, g_c);
    cudaGetSymbolAddress((void**)&Tbuf, g_T);
    cudaGetSymbolAddress((void**)&Wbuf, g_W);

    float* ec0 = cbuf + 0 * (size_t)NST;
    float* ec1 = cbuf + 1 * (size_t)NST;
    float* dc0 = cbuf + 2 * (size_t)NST;
    float* dc1 = cbuf + 3 * (size_t)NST;
    __half* Te0[2] = { Tbuf + 0 * TSZ, Tbuf + 1 * TSZ };
    __half* Te1[2] = { Tbuf + 2 * TSZ, Tbuf + 3 * TSZ };
    __half* Td0[2] = { Tbuf + 4 * TSZ, Tbuf + 5 * TSZ };
    __half* Td1[2] = { Tbuf + 6 * TSZ, Tbuf + 7 * TSZ };
    __half* W_e0h = Wbuf + 0 * (size_t)WSZ;
    __half* W_e1x = Wbuf + 1 * (size_t)WSZ;
    __half* W_e1h = Wbuf + 2 * (size_t)WSZ;
    __half* W_d0x = Wbuf + 3 * (size_t)WSZ;
    __half* W_d0h = Wbuf + 4 * (size_t)WSZ;
    __half* W_d1x = Wbuf + 5 * (size_t)WSZ;
    __half* W_d1h = Wbuf + 6 * (size_t)WSZ;

    // merged weight transform (7 tensors in one launch)
    {
        dim3 wgrid((WSZ + 255) / 256, 1, 7);
        wsplit_kernel<<<wgrid, 256>>>(e0Wh, e1Wx, e1Wh, d0Wx, d0Wh, d1Wx, d1Wh, Wbuf);
    }
    cudaMemsetAsync(cbuf, 0, (size_t)4 * NST * sizeof(float));
    cudaMemsetAsync(Tbuf, 0, (size_t)8 * TSZ * sizeof(__half));

    auto cellArgs = [](const __half* T0, const __half* W0, const __half* T1,
                       const __half* W1, int nsrc, const float* Wc, const float* bias,
                       float* cb, __half* To, const float* xp, const float* wx9, int t) {
        CellArgs a;
        a.T0 = T0; a.W0 = W0; a.T1 = T1; a.W1 = W1; a.nsrc = nsrc;
        a.Wc = Wc; a.bias = bias; a.cbuf = cb; a.Tout = To;
        a.xp = xp; a.wx9 = wx9; a.t = t; a.kind = 0;
        return a;
    };
    auto finalArgs = [&](const __half* T, int t) {
        CellArgs a;
        a.T0 = T; a.W0 = nullptr; a.T1 = nullptr; a.W1 = nullptr; a.nsrc = 0;
        a.Wc = finw; a.bias = finb; a.cbuf = out; a.Tout = nullptr;
        a.xp = nullptr; a.wx9 = nullptr; a.t = t; a.kind = 1;
        return a;
    };
    CellArgs none; none.kind = 2;
    none.T0 = none.T1 = nullptr; none.W0 = none.W1 = nullptr; none.nsrc = 0;
    none.Wc = none.bias = nullptr; none.cbuf = nullptr; none.Tout = nullptr;
    none.xp = none.wx9 = nullptr; none.t = 0;

    dim3 g1(256, 2, 1), g2(256, 2, 2), gf(128, 1, 1), blk(256);

    auto enc0 = [&](int t) {
        int r = t & 1, w = r ^ 1;
        return cellArgs(Te0[r], W_e0h, Te0[r], W_e0h, 1, e0Wc, e0b, ec0, Te0[w], x, e0Wx, t);
    };
    auto enc1 = [&](int t) {
        int r = t & 1, w = r ^ 1;
        return cellArgs(Te0[w], W_e1x, Te1[r], W_e1h, 2, e1Wc, e1b, ec1, Te1[w], nullptr, nullptr, 0);
    };
    auto dec0 = [&](int t) {
        int r = t & 1, w = r ^ 1;
        const __half* Ts = (t == 0) ? Te1[0] : Td1[r];
        return cellArgs(Ts, W_d0x, Td0[r], W_d0h, 2, d0Wc, d0b, dc0, Td0[w], nullptr, nullptr, 0);
    };
    auto dec1 = [&](int t) {
        int r = t & 1, w = r ^ 1;
        return cellArgs(Td0[w], W_d1x, Td1[r], W_d1h, 2, d1Wc, d1b, dc1, Td1[w], nullptr, nullptr, 0);
    };

    // ---- Encoder ----
    fused_kernel<<<g1, blk, SM_TOTAL>>>(enc0(0), none);
    for (int t = 0; t < TT - 1; t++)
        fused_kernel<<<g2, blk, SM_TOTAL>>>(enc1(t), enc0(t + 1));   // independent pair
    fused_kernel<<<g1, blk, SM_TOTAL>>>(enc1(TT - 1), none);
    // final encoder h1 in Te1[0] (t=9: w=0)

    // ---- Decoder ----
    fused_kernel<<<g1, blk, SM_TOTAL>>>(dec0(0), none);
    for (int t = 0; t < PRED; t++) {
        int w = (t & 1) ^ 1;
        fused_kernel<<<g1, blk, SM_TOTAL>>>(dec1(t), none);
        if (t < PRED - 1)
            fused_kernel<<<g2, blk, SM_TOTAL>>>(dec0(t + 1), finalArgs(Td1[w], t)); // read-read on Td1[w]
        else
            fused_kernel<<<gf, blk, SM_TOTAL>>>(finalArgs(Td1[w], t), none);
    }
}

// round 13
// speedup vs baseline: 13.2956x; 1.0176x over previous
#include <cuda_runtime.h>
#include <cuda_fp16.h>
#include <math.h>
#include <stdint.h>

// Problem constants
#define BB   8
#define TT   10
#define HH   64
#define WW   64
#define HID  64
#define PRED 10
#define PIX  (HH*WW)              // 4096
#define NST  (BB*HID*PIX)
#define TROW 66
#define TSZ  ((size_t)BB*TROW*TROW*HID)   // elems of one transposed fp16 tensor
#define WSZ  (9*256*64)           // fp16 weights per tensor
#define WBSZ (64*4096*8)          // packed Wc+bias per cell: [co][px][wc0..3,b0..3]

// ---------------------------------------------------------------------------
// Static scratch
// ---------------------------------------------------------------------------
__device__ float g_c[4][NST];                                   // c states
__device__ __align__(16) __half g_T[4][2 * BB*TROW*TROW*HID];   // h, ping-pong
__device__ __align__(16) __half g_W[7][WSZ];
__device__ __align__(16) __half g_WB[4][WBSZ];                  // packed Wc|bias

// ---------------------------------------------------------------------------
// Weight transform: w (256,64,3,3) -> wt[tap][m][k] fp16, m = co*4 + g.
// z selects which of the 7 weight tensors (merged launch).
// ---------------------------------------------------------------------------
__global__ void wsplit_kernel(const float* w0, const float* w1, const float* w2,
                              const float* w3, const float* w4, const float* w5,
                              const float* w6, __half* __restrict__ wt_base)
{
    int i = blockIdx.x * blockDim.x + threadIdx.x;
    if (i >= WSZ) return;
    int z = blockIdx.z;
    const float* w;
    switch (z) {
        case 0: w = w0; break;  case 1: w = w1; break;
        case 2: w = w2; break;  case 3: w = w3; break;
        case 4: w = w4; break;  case 5: w = w5; break;
        default: w = w6; break;
    }
    __half* wt = wt_base + (size_t)z * WSZ;
    int c   = i & 63;
    int m   = (i >> 6) & 255;
    int tap = i >> 14;
    int co = m >> 2, g = m & 3;
    wt[i] = __float2half_rn(w[((g * 64 + co) * 64 + c) * 9 + tap]);
}

// ---------------------------------------------------------------------------
// Pack Wc (4,64,64,64) + bias (4,64,64,64) -> [co][px][wc0..3,b0..3] fp16.
// One LDG.128 in the cell epilogue replaces 8 scalar LDG.32.
// ---------------------------------------------------------------------------
__global__ void wcpack_kernel(const float* wc0, const float* b0,
                              const float* wc1, const float* b1,
                              const float* wc2, const float* b2,
                              const float* wc3, const float* b3,
                              __half* __restrict__ out_base)
{
    int i = blockIdx.x * blockDim.x + threadIdx.x;   // over 64*4096
    if (i >= 64 * 4096) return;
    int z = blockIdx.z;
    const float *wc, *bi;
    switch (z) {
        case 0: wc = wc0; bi = b0; break;
        case 1: wc = wc1; bi = b1; break;
        case 2: wc = wc2; bi = b2; break;
        default: wc = wc3; bi = b3; break;
    }
    __half* out = out_base + (size_t)z * WBSZ;
    int px = i & 4095;
    int co = i >> 12;
    __half* dst = out + (size_t)i * 8;
    #pragma unroll
    for (int g = 0; g < 4; g++) {
        dst[g]     = __float2half_rn(wc[(g * 64 + co) * 4096 + px]);
        dst[4 + g] = __float2half_rn(bi[(g * 64 + co) * 4096 + px]);
    }
}

// ---------------------------------------------------------------------------
// low-level helpers
// ---------------------------------------------------------------------------
__device__ __forceinline__ uint32_t smem_u32(const void* p) {
    uint32_t a;
    asm("{ .reg .u64 t; cvta.to.shared.u64 t, %1; cvt.u32.u64 %0, t; }" : "=r"(a) : "l"(p));
    return a;
}
__device__ __forceinline__ void cp16(uint32_t dst, const void* src) {
    asm volatile("cp.async.cg.shared.global [%0], [%1], 16;" :: "r"(dst), "l"(src));
}
#define CP_COMMIT() asm volatile("cp.async.commit_group;" ::: "memory")
#define CP_WAIT0()  asm volatile("cp.async.wait_group 0;" ::: "memory")

__device__ __forceinline__ void ldm_x4(unsigned* r, uint32_t addr) {
    asm volatile("ldmatrix.sync.aligned.m8n8.x4.shared.b16 {%0,%1,%2,%3}, [%4];"
        : "=r"(r[0]), "=r"(r[1]), "=r"(r[2]), "=r"(r[3]) : "r"(addr));
}
__device__ __forceinline__ void mma16816(float* d, const unsigned* a,
                                         unsigned b0, unsigned b1)
{
    asm("mma.sync.aligned.m16n8k16.row.col.f32.f16.f16.f32 "
        "{%0,%1,%2,%3}, {%4,%5,%6,%7}, {%8,%9}, {%0,%1,%2,%3};"
        : "+f"(d[0]), "+f"(d[1]), "+f"(d[2]), "+f"(d[3])
        : "r"(a[0]), "r"(a[1]), "r"(a[2]), "r"(a[3]), "r"(b0), "r"(b1));
}

// Fast activations (EX2/RCP; error « fp16 mma noise floor)
__device__ __forceinline__ float ex2f(float x) {
    float r; asm("ex2.approx.f32 %0, %1;" : "=f"(r) : "f"(x)); return r;
}
__device__ __forceinline__ float rcpf(float x) {
    float r; asm("rcp.approx.f32 %0, %1;" : "=f"(r) : "f"(x)); return r;
}
#define LOG2E 1.4426950408889634f
__device__ __forceinline__ float sigf(float v) {
    return rcpf(1.f + ex2f(-v * LOG2E));
}
__device__ __forceinline__ float tanhf_fast(float v) {
    return 1.f - 2.f * rcpf(1.f + ex2f(2.f * LOG2E * v));
}

// SMEM layout (bytes), 2 CTAs/SM:
//   A tiles: 2 bufs x 128 rows x 144B      = 36864   [0 .. 36864)
//   B tile : 264 rows x 144B               = 38016   [36864 .. 74880)
//   sE (128 gate-rows x 136 f32 = 69632) overlays A+B
//   sH (128 px x 40 fp16 = 10240)          [74880 .. 85120)   (80B rows, 16B-aligned)
#define SA_OFF   0
#define SA_BUF   18432
#define SB_OFF   36864
#define SH_OFF   74880
#define SM_TOTAL 85120
#define ESTR     136
#define HSTR     40

// ---------------------------------------------------------------------------
// Work descriptor: one cell OR one final-conv, selected per grid-z slice.
// ---------------------------------------------------------------------------
struct CellArgs {
    const __half* T0;   // cell: x-src pixels | final: input T
    const __half* W0;   // cell: x weights
    const __half* T1;   // cell: h-src pixels
    const __half* W1;   // cell: h weights
    int nsrc;
    const __half* wcb;  // cell: packed Wc|bias
    const float*  fw;   // final: weights
    const float*  fb;   // final: bias
    float*        cbuf; // cell: c state     | final: out
    __half*       Tout; // cell: h out
    const float*  xp;   // enc0 only
    const float*  wx9;  // enc0 only
    int t;
    int kind;           // 0 = cell, 1 = final conv, 2 = none
};

// ---------------------------------------------------------------------------
// Cell body
// ---------------------------------------------------------------------------
__device__ __forceinline__ void cell_body(const CellArgs& A, char* smc)
{
    const uint32_t smb = smem_u32(smc);
    float*  sE = (float*)smc;
    __half* sH = (__half*)(smc + SH_OFF);

    const int tid  = threadIdx.x;
    const int lane = tid & 31;
    const int warp = tid >> 5;
    const int wm   = warp >> 2;
    const int wn   = warp & 3;
    const int nt   = blockIdx.x;     // 0..255
    const int mt   = blockIdx.y;     // 0..1
    const int b    = nt >> 5;
    const int y0   = (nt & 31) << 1;

    const int a_row_l = lane & 15;
    const int a_col_l = (lane >> 4) * 8;
    const int b_row_l = (lane & 7) + ((lane >> 4) << 3);
    const int b_col_l = ((lane >> 3) & 1) * 8;

    float acc[4][4][4];
    #pragma unroll
    for (int mi = 0; mi < 4; mi++)
        #pragma unroll
        for (int ni = 0; ni < 4; ni++)
            #pragma unroll
            for (int r = 0; r < 4; r++) acc[mi][ni][r] = 0.f;

    for (int s = 0; s < A.nsrc; s++) {
        const __half* T = s ? A.T1 : A.T0;
        const __half* W = s ? A.W1 : A.W0;

        __syncthreads();
        for (int i = tid; i < 2112; i += 256) {
            int p = i >> 3, v = i & 7;
            int r = p / TROW, px = p - r * TROW;
            const __half* src =
                T + (((size_t)b * TROW + (y0 + r)) * TROW + px) * 64 + v * 8;
            cp16(smb + SB_OFF + p * 144 + v * 16, src);
        }
        for (int i = tid; i < 1024; i += 256) {
            int m = i >> 3, v = i & 7;
            const __half* src = W + (mt * 128 + m) * 64 + v * 8;
            cp16(smb + SA_OFF + m * 144 + v * 16, src);
        }
        CP_COMMIT();

        for (int tap = 0; tap < 9; tap++) {
            CP_WAIT0();
            __syncthreads();
            if (tap < 8) {
                const int nb = (tap + 1) & 1;
                for (int i = tid; i < 1024; i += 256) {
                    int m = i >> 3, v = i & 7;
                    const __half* src = W + (tap + 1) * 16384 + (mt * 128 + m) * 64 + v * 8;
                    cp16(smb + SA_OFF + nb * SA_BUF + m * 144 + v * 16, src);
                }
                CP_COMMIT();
            }

            const int dy = tap / 3, dx = tap - dy * 3;
            const int ylocal = wn >> 1, xlocal = (wn & 1) * 32;
            const int prow_base = (ylocal + dy) * TROW + xlocal + dx;
            const uint32_t aBase = smb + SA_OFF + (tap & 1) * SA_BUF;
            const uint32_t bBase = smb + SB_OFF;

            #pragma unroll
            for (int ks = 0; ks < 4; ks++) {
                unsigned bfr[2][4];
                #pragma unroll
                for (int p2 = 0; p2 < 2; p2++)
                    ldm_x4(bfr[p2], bBase + (prow_base + p2 * 16 + b_row_l) * 144
                                          + (ks * 16 + b_col_l) * 2);
                unsigned afr[4][4];
                #pragma unroll
                for (int mi = 0; mi < 4; mi++)
                    ldm_x4(afr[mi], aBase + (wm * 64 + mi * 16 + a_row_l) * 144
                                          + (a_col_l + ks * 16) * 2);
                #pragma unroll
                for (int p2 = 0; p2 < 2; p2++)
                    #pragma unroll
                    for (int mi = 0; mi < 4; mi++) {
                        mma16816(acc[mi][2 * p2],     afr[mi], bfr[p2][0], bfr[p2][1]);
                        mma16816(acc[mi][2 * p2 + 1], afr[mi], bfr[p2][2], bfr[p2][3]);
                    }
            }
        }
    }

    // ---- epilogue ----
    __syncthreads();
    const int gr = lane >> 2, ci = lane & 3;
    #pragma unroll
    for (int mi = 0; mi < 4; mi++)
        #pragma unroll
        for (int ni = 0; ni < 4; ni++) {
            int r0 = wm * 64 + mi * 16 + gr;
            int n  = wn * 32 + ni * 8 + 2 * ci;
            *(float2*)(sE + r0 * ESTR + n)       = make_float2(acc[mi][ni][0], acc[mi][ni][1]);
            *(float2*)(sE + (r0 + 8) * ESTR + n) = make_float2(acc[mi][ni][2], acc[mi][ni][3]);
        }
    __syncthreads();

    #pragma unroll 1
    for (int ii = 0; ii < 4; ii++) {
        int pl  = lane + 32 * ii;
        int pix = y0 * 64 + pl;
        float xv[9];
        if (A.xp) {
            int y = pix >> 6, xx = pix & 63;
            #pragma unroll
            for (int tap = 0; tap < 9; tap++) {
                int gy = y + tap / 3 - 1, gx = xx + tap % 3 - 1;
                xv[tap] = ((unsigned)gy < 64u && (unsigned)gx < 64u)
                          ? A.xp[((size_t)b * TT + A.t) * 4096 + gy * 64 + gx] : 0.f;
            }
        }
        #pragma unroll 1
        for (int jj = 0; jj < 4; jj++) {
            int col = warp + 8 * jj;
            int co  = mt * 32 + col;
            int bb  = (b * 64 + co) * 4096 + pix;
            float cold = A.cbuf[bb];
            // packed Wc|bias: one LDG.128 -> wc0..3, b0..3 (fp16)
            uint4 v = *(const uint4*)(A.wcb + (((size_t)co << 12) + pix) * 8);
            const __half2* hv = (const __half2*)&v;
            float2 wc01 = __half22float2(hv[0]);
            float2 wc23 = __half22float2(hv[1]);
            float2 bb01 = __half22float2(hv[2]);
            float2 bb23 = __half22float2(hv[3]);
            float pre[4];
            pre[0] = sE[(col * 4 + 0) * ESTR + pl] + wc01.x * cold + bb01.x;
            pre[1] = sE[(col * 4 + 1) * ESTR + pl] + wc01.y * cold + bb01.y;
            pre[2] = sE[(col * 4 + 2) * ESTR + pl] + wc23.x * cold + bb23.x;
            pre[3] = sE[(col * 4 + 3) * ESTR + pl] + wc23.y * cold + bb23.y;
            if (A.xp) {
                #pragma unroll
                for (int g = 0; g < 4; g++) {
                    const float* w9 = A.wx9 + (size_t)(g * 64 + co) * 9;
                    float s0 = 0.f;
                    #pragma unroll
                    for (int tap = 0; tap < 9; tap++) s0 += __ldg(w9 + tap) * xv[tap];
                    pre[g] += s0;
                }
            }
            float ig = sigf(pre[0]);
            float fg = sigf(pre[1]);
            float gg = tanhf_fast(pre[2]);
            float og = sigf(pre[3]);
            float cn = fg * cold + ig * gg;
            A.cbuf[bb] = cn;
            sH[pl * HSTR + col] = __float2half_rn(og * tanhf_fast(cn));
        }
    }
    __syncthreads();

    for (int i = tid; i < 512; i += 256) {
        int px = i >> 2, q = i & 3;
        int pix = y0 * 64 + px;
        int y = pix >> 6, x = pix & 63;
        __half* dst = A.Tout + (((size_t)b * TROW + (y + 1)) * TROW + (x + 1)) * 64
                      + mt * 32 + q * 8;
        *(uint4*)dst = *(const uint4*)(sH + px * HSTR + q * 8);
    }
}

// ---------------------------------------------------------------------------
// Final conv body: 3x3 (HID->1) + bias + sigmoid, reading haloed fp16 T.
// Active CTAs: mt==0 && nt<128.
// ---------------------------------------------------------------------------
__device__ __forceinline__ void final_body(const CellArgs& A, char* smc)
{
    const int nt = blockIdx.x;
    const int mt = blockIdx.y;
    if (mt != 0 || nt >= 128) return;
    float* s_w = (float*)smc;   // 576 floats

    int tid = threadIdx.x;
    for (int i = tid; i < 576; i += 256) {
        int tap = i >> 6, c = i & 63;
        s_w[tap * 64 + c] = A.fw[c * 9 + tap];
    }
    __syncthreads();

    int b  = nt >> 4;
    int pb = nt & 15;
    int pix = pb * 256 + tid;
    int y = pix >> 6, x = pix & 63;
    float sum = A.fb[0];
    #pragma unroll
    for (int tap = 0; tap < 9; tap++) {
        int dy = tap / 3, dx = tap % 3;
        const __half* row =
            A.T0 + (((size_t)b * TROW + (y + dy)) * TROW + (x + dx)) * 64;
        const float* wt = s_w + tap * 64;
        #pragma unroll
        for (int c8 = 0; c8 < 8; c8++) {
            uint4 v = *(const uint4*)(row + c8 * 8);
            const __half* hv = (const __half*)&v;
            #pragma unroll
            for (int k = 0; k < 8; k++)
                sum += wt[c8 * 8 + k] * __half2float(hv[k]);
        }
    }
    A.cbuf[(size_t)b * (PRED * PIX) + A.t * PIX + pix] = sigf(sum);
}

// ---------------------------------------------------------------------------
// Fused dispatcher: grid (256, 2, nz). Slice z=0 runs `a`, z=1 runs `b`.
// ---------------------------------------------------------------------------
__global__ void __launch_bounds__(256, 2)
fused_kernel(CellArgs a, CellArgs b)
{
    extern __shared__ __align__(16) char smc[];
    if (blockIdx.z == 0) {
        if (a.kind == 0)      cell_body(a, smc);
        else if (a.kind == 1) final_body(a, smc);
    } else {
        if (b.kind == 0)      cell_body(b, smc);
        else if (b.kind == 1) final_body(b, smc);
    }
}

// ---------------------------------------------------------------------------
extern "C" void kernel_launch(void* const* d_in, const int* in_sizes, int n_in,
                              void* d_out, int out_size)
{
    const float* x    = (const float*)d_in[0];
    const float* e0Wx = (const float*)d_in[1];
    const float* e0Wh = (const float*)d_in[2];
    const float* e0Wc = (const float*)d_in[3];
    const float* e0b  = (const float*)d_in[4];
    const float* e1Wx = (const float*)d_in[5];
    const float* e1Wh = (const float*)d_in[6];
    const float* e1Wc = (const float*)d_in[7];
    const float* e1b  = (const float*)d_in[8];
    const float* d0Wx = (const float*)d_in[9];
    const float* d0Wh = (const float*)d_in[10];
    const float* d0Wc = (const float*)d_in[11];
    const float* d0b  = (const float*)d_in[12];
    const float* d1Wx = (const float*)d_in[13];
    const float* d1Wh = (const float*)d_in[14];
    const float* d1Wc = (const float*)d_in[15];
    const float* d1b  = (const float*)d_in[16];
    const float* finw = (const float*)d_in[17];
    const float* finb = (const float*)d_in[18];
    float* out = (float*)d_out;

    cudaFuncSetAttribute(fused_kernel,
                         cudaFuncAttributeMaxDynamicSharedMemorySize, SM_TOTAL);

    float* cbuf;
    __half *Tbuf, *Wbuf, *WBbuf;
    cudaGetSymbolAddress((void**)&cbuf, g_c);
    cudaGetSymbolAddress((void**)&Tbuf, g_T);
    cudaGetSymbolAddress((void**)&Wbuf, g_W);
    cudaGetSymbolAddress((void**)&WBbuf, g_WB);

    float* ec0 = cbuf + 0 * (size_t)NST;
    float* ec1 = cbuf + 1 * (size_t)NST;
    float* dc0 = cbuf + 2 * (size_t)NST;
    float* dc1 = cbuf + 3 * (size_t)NST;
    __half* Te0[2] = { Tbuf + 0 * TSZ, Tbuf + 1 * TSZ };
    __half* Te1[2] = { Tbuf + 2 * TSZ, Tbuf + 3 * TSZ };
    __half* Td0[2] = { Tbuf + 4 * TSZ, Tbuf + 5 * TSZ };
    __half* Td1[2] = { Tbuf + 6 * TSZ, Tbuf + 7 * TSZ };
    __half* W_e0h = Wbuf + 0 * (size_t)WSZ;
    __half* W_e1x = Wbuf + 1 * (size_t)WSZ;
    __half* W_e1h = Wbuf + 2 * (size_t)WSZ;
    __half* W_d0x = Wbuf + 3 * (size_t)WSZ;
    __half* W_d0h = Wbuf + 4 * (size_t)WSZ;
    __half* W_d1x = Wbuf + 5 * (size_t)WSZ;
    __half* W_d1h = Wbuf + 6 * (size_t)WSZ;
    __half* WB_e0 = WBbuf + 0 * (size_t)WBSZ;
    __half* WB_e1 = WBbuf + 1 * (size_t)WBSZ;
    __half* WB_d0 = WBbuf + 2 * (size_t)WBSZ;
    __half* WB_d1 = WBbuf + 3 * (size_t)WBSZ;

    // merged weight transform + Wc/bias pack
    {
        dim3 wgrid((WSZ + 255) / 256, 1, 7);
        wsplit_kernel<<<wgrid, 256>>>(e0Wh, e1Wx, e1Wh, d0Wx, d0Wh, d1Wx, d1Wh, Wbuf);
        dim3 pgrid((64 * 4096 + 255) / 256, 1, 4);
        wcpack_kernel<<<pgrid, 256>>>(e0Wc, e0b, e1Wc, e1b, d0Wc, d0b, d1Wc, d1b, WBbuf);
    }
    cudaMemsetAsync(cbuf, 0, (size_t)4 * NST * sizeof(float));
    cudaMemsetAsync(Tbuf, 0, (size_t)8 * TSZ * sizeof(__half));

    auto cellArgs = [&](const __half* T0, const __half* W0, const __half* T1,
                        const __half* W1, int nsrc, const __half* wcb,
                        float* cb, __half* To, const float* xp, const float* wx9, int t) {
        CellArgs a;
        a.T0 = T0; a.W0 = W0; a.T1 = T1; a.W1 = W1; a.nsrc = nsrc;
        a.wcb = wcb; a.fw = nullptr; a.fb = nullptr; a.cbuf = cb; a.Tout = To;
        a.xp = xp; a.wx9 = wx9; a.t = t; a.kind = 0;
        return a;
    };
    auto finalArgs = [&](const __half* T, int t) {
        CellArgs a;
        a.T0 = T; a.W0 = nullptr; a.T1 = nullptr; a.W1 = nullptr; a.nsrc = 0;
        a.wcb = nullptr; a.fw = finw; a.fb = finb; a.cbuf = out; a.Tout = nullptr;
        a.xp = nullptr; a.wx9 = nullptr; a.t = t; a.kind = 1;
        return a;
    };
    CellArgs none; none.kind = 2;
    none.T0 = none.T1 = nullptr; none.W0 = none.W1 = nullptr; none.nsrc = 0;
    none.wcb = nullptr; none.fw = none.fb = nullptr; none.cbuf = nullptr;
    none.Tout = nullptr; none.xp = none.wx9 = nullptr; none.t = 0;

    dim3 g1(256, 2, 1), g2(256, 2, 2), gf(128, 1, 1), blk(256);

    auto enc0 = [&](int t) {
        int r = t & 1, w = r ^ 1;
        return cellArgs(Te0[r], W_e0h, Te0[r], W_e0h, 1, WB_e0, ec0, Te0[w], x, e0Wx, t);
    };
    auto enc1 = [&](int t) {
        int r = t & 1, w = r ^ 1;
        return cellArgs(Te0[w], W_e1x, Te1[r], W_e1h, 2, WB_e1, ec1, Te1[w], nullptr, nullptr, 0);
    };
    auto dec0 = [&](int t) {
        int r = t & 1, w = r ^ 1;
        const __half* Ts = (t == 0) ? Te1[0] : Td1[r];
        return cellArgs(Ts, W_d0x, Td0[r], W_d0h, 2, WB_d0, dc0, Td0[w], nullptr, nullptr, 0);
    };
    auto dec1 = [&](int t) {
        int r = t & 1, w = r ^ 1;
        return cellArgs(Td0[w], W_d1x, Td1[r], W_d1h, 2, WB_d1, dc1, Td1[w], nullptr, nullptr, 0);
    };

    // ---- Encoder ----
    fused_kernel<<<g1, blk, SM_TOTAL>>>(enc0(0), none);
    for (int t = 0; t < TT - 1; t++)
        fused_kernel<<<g2, blk, SM_TOTAL>>>(enc1(t), enc0(t + 1));   // independent pair
    fused_kernel<<<g1, blk, SM_TOTAL>>>(enc1(TT - 1), none);
    // final encoder h1 in Te1[0] (t=9: w=0)

    // ---- Decoder ----
    fused_kernel<<<g1, blk, SM_TOTAL>>>(dec0(0), none);
    for (int t = 0; t < PRED; t++) {
        int w = (t & 1) ^ 1;
        fused_kernel<<<g1, blk, SM_TOTAL>>>(dec1(t), none);
        if (t < PRED - 1)
            fused_kernel<<<g2, blk, SM_TOTAL>>>(dec0(t + 1), finalArgs(Td1[w], t)); // read-read on Td1[w]
        else
            fused_kernel<<<gf, blk, SM_TOTAL>>>(finalArgs(Td1[w], t), none);
    }
}

// round 14
// speedup vs baseline: 13.8521x; 1.0419x over previous
#include <cuda_runtime.h>
#include <cuda_fp16.h>
#include <math.h>
#include <stdint.h>

// Problem constants
#define BB   8
#define TT   10
#define HH   64
#define WW   64
#define HID  64
#define PRED 10
#define PIX  (HH*WW)              // 4096
#define NST  (BB*HID*PIX)
#define TROW 66
#define TSZ  ((size_t)BB*TROW*TROW*HID)   // elems of one transposed fp16 tensor
#define WSZ  (9*256*64)           // fp16 weights per tensor
#define WBSZ (64*4096*8)          // packed Wc+bias per cell: [co][px][wc0..3,b0..3]

// ---------------------------------------------------------------------------
// Static scratch
// ---------------------------------------------------------------------------
__device__ float g_c[4][NST];                                   // c states
__device__ __align__(16) __half g_T[4][2 * BB*TROW*TROW*HID];   // h, ping-pong
__device__ __align__(16) __half g_W[7][WSZ];
__device__ __align__(16) __half g_WB[4][WBSZ];                  // packed Wc|bias

// ---------------------------------------------------------------------------
// Weight transform: w (256,64,3,3) -> wt[tap][m][k] fp16, m = co*4 + g.
// ---------------------------------------------------------------------------
__global__ void wsplit_kernel(const float* w0, const float* w1, const float* w2,
                              const float* w3, const float* w4, const float* w5,
                              const float* w6, __half* __restrict__ wt_base)
{
    int i = blockIdx.x * blockDim.x + threadIdx.x;
    if (i >= WSZ) return;
    int z = blockIdx.z;
    const float* w;
    switch (z) {
        case 0: w = w0; break;  case 1: w = w1; break;
        case 2: w = w2; break;  case 3: w = w3; break;
        case 4: w = w4; break;  case 5: w = w5; break;
        default: w = w6; break;
    }
    __half* wt = wt_base + (size_t)z * WSZ;
    int c   = i & 63;
    int m   = (i >> 6) & 255;
    int tap = i >> 14;
    int co = m >> 2, g = m & 3;
    wt[i] = __float2half_rn(w[((g * 64 + co) * 64 + c) * 9 + tap]);
}

// ---------------------------------------------------------------------------
// Pack Wc + bias -> [co][px][wc0..3,b0..3] fp16 (one LDG.128 in epilogue)
// ---------------------------------------------------------------------------
__global__ void wcpack_kernel(const float* wc0, const float* b0,
                              const float* wc1, const float* b1,
                              const float* wc2, const float* b2,
                              const float* wc3, const float* b3,
                              __half* __restrict__ out_base)
{
    int i = blockIdx.x * blockDim.x + threadIdx.x;   // over 64*4096
    if (i >= 64 * 4096) return;
    int z = blockIdx.z;
    const float *wc, *bi;
    switch (z) {
        case 0: wc = wc0; bi = b0; break;
        case 1: wc = wc1; bi = b1; break;
        case 2: wc = wc2; bi = b2; break;
        default: wc = wc3; bi = b3; break;
    }
    __half* out = out_base + (size_t)z * WBSZ;
    int px = i & 4095;
    int co = i >> 12;
    __half* dst = out + (size_t)i * 8;
    #pragma unroll
    for (int g = 0; g < 4; g++) {
        dst[g]     = __float2half_rn(wc[(g * 64 + co) * 4096 + px]);
        dst[4 + g] = __float2half_rn(bi[(g * 64 + co) * 4096 + px]);
    }
}

// ---------------------------------------------------------------------------
// low-level helpers
// ---------------------------------------------------------------------------
__device__ __forceinline__ uint32_t smem_u32(const void* p) {
    uint32_t a;
    asm("{ .reg .u64 t; cvta.to.shared.u64 t, %1; cvt.u32.u64 %0, t; }" : "=r"(a) : "l"(p));
    return a;
}
__device__ __forceinline__ void cp16(uint32_t dst, const void* src) {
    asm volatile("cp.async.cg.shared.global [%0], [%1], 16;" :: "r"(dst), "l"(src));
}
#define CP_COMMIT() asm volatile("cp.async.commit_group;" ::: "memory")
#define CP_WAIT0()  asm volatile("cp.async.wait_group 0;" ::: "memory")

__device__ __forceinline__ void ldm_x4(unsigned* r, uint32_t addr) {
    asm volatile("ldmatrix.sync.aligned.m8n8.x4.shared.b16 {%0,%1,%2,%3}, [%4];"
        : "=r"(r[0]), "=r"(r[1]), "=r"(r[2]), "=r"(r[3]) : "r"(addr));
}
__device__ __forceinline__ void mma16816(float* d, const unsigned* a,
                                         unsigned b0, unsigned b1)
{
    asm("mma.sync.aligned.m16n8k16.row.col.f32.f16.f16.f32 "
        "{%0,%1,%2,%3}, {%4,%5,%6,%7}, {%8,%9}, {%0,%1,%2,%3};"
        : "+f"(d[0]), "+f"(d[1]), "+f"(d[2]), "+f"(d[3])
        : "r"(a[0]), "r"(a[1]), "r"(a[2]), "r"(a[3]), "r"(b0), "r"(b1));
}

// Fast activations (EX2/RCP)
__device__ __forceinline__ float ex2f(float x) {
    float r; asm("ex2.approx.f32 %0, %1;" : "=f"(r) : "f"(x)); return r;
}
__device__ __forceinline__ float rcpf(float x) {
    float r; asm("rcp.approx.f32 %0, %1;" : "=f"(r) : "f"(x)); return r;
}
#define LOG2E 1.4426950408889634f
__device__ __forceinline__ float sigf(float v) {
    return rcpf(1.f + ex2f(-v * LOG2E));
}
__device__ __forceinline__ float tanhf_fast(float v) {
    return 1.f - 2.f * rcpf(1.f + ex2f(2.f * LOG2E * v));
}

// SMEM layout (bytes), sized for 3 CTAs/SM (M=64 tile):
//   A tiles: 2 bufs x 64 rows x 144B = 18432   [0 .. 18432)
//   B tile : 264 rows x 144B         = 38016   [18432 .. 56448)
//   sE (64 gate-rows x 136 f32 = 34816) overlays A+B
//   sH (128 px x 24 fp16 = 6144)     [56448 .. 62592)  (48B rows, 16B-aligned)
#define SA_OFF   0
#define SA_BUF   9216
#define SB_OFF   18432
#define SH_OFF   56448
#define SM_TOTAL 62592
#define ESTR     136
#define HSTR     24

// ---------------------------------------------------------------------------
// Work descriptor
// ---------------------------------------------------------------------------
struct CellArgs {
    const __half* T0;
    const __half* W0;
    const __half* T1;
    const __half* W1;
    int nsrc;
    const __half* wcb;
    const float*  fw;
    const float*  fb;
    float*        cbuf;
    __half*       Tout;
    const float*  xp;
    const float*  wx9;
    int t;
    int kind;           // 0 = cell, 1 = final conv, 2 = none
};

// ---------------------------------------------------------------------------
// Cell body. CTA: M=64 gate-rows (mt in 0..3 -> channels mt*16..mt*16+15),
// N=128 px (2 image rows of one batch). 8 warps: wm {0,1} x wn {0..3};
// warp tile 32m x 32n. 3 CTAs/SM.
// ---------------------------------------------------------------------------
__device__ __forceinline__ void cell_body(const CellArgs& A, char* smc)
{
    const uint32_t smb = smem_u32(smc);
    float*  sE = (float*)smc;
    __half* sH = (__half*)(smc + SH_OFF);

    const int tid  = threadIdx.x;
    const int lane = tid & 31;
    const int warp = tid >> 5;
    const int wm   = warp >> 2;      // 0..1 (m half: wm*32)
    const int wn   = warp & 3;       // 0..3
    const int nt   = blockIdx.x;     // 0..255
    const int mt   = blockIdx.y;     // 0..3
    const int b    = nt >> 5;
    const int y0   = (nt & 31) << 1; // first of 2 image rows

    const int a_row_l = lane & 15;
    const int a_col_l = (lane >> 4) * 8;
    const int b_row_l = (lane & 7) + ((lane >> 4) << 3);
    const int b_col_l = ((lane >> 3) & 1) * 8;

    float acc[2][4][4];
    #pragma unroll
    for (int mi = 0; mi < 2; mi++)
        #pragma unroll
        for (int ni = 0; ni < 4; ni++)
            #pragma unroll
            for (int r = 0; r < 4; r++) acc[mi][ni][r] = 0.f;

    for (int s = 0; s < A.nsrc; s++) {
        const __half* T = s ? A.T1 : A.T0;
        const __half* W = s ? A.W1 : A.W0;

        __syncthreads();
        // fill B: 264 padded rows x 8 vec16
        for (int i = tid; i < 2112; i += 256) {
            int p = i >> 3, v = i & 7;
            int r = p / TROW, px = p - r * TROW;
            const __half* src =
                T + (((size_t)b * TROW + (y0 + r)) * TROW + px) * 64 + v * 8;
            cp16(smb + SB_OFF + p * 144 + v * 16, src);
        }
        // fill A tap0: 64 rows x 8 vec16
        for (int i = tid; i < 512; i += 256) {
            int m = i >> 3, v = i & 7;
            const __half* src = W + (mt * 64 + m) * 64 + v * 8;
            cp16(smb + SA_OFF + m * 144 + v * 16, src);
        }
        CP_COMMIT();

        for (int tap = 0; tap < 9; tap++) {
            CP_WAIT0();
            __syncthreads();
            if (tap < 8) {
                const int nb = (tap + 1) & 1;
                for (int i = tid; i < 512; i += 256) {
                    int m = i >> 3, v = i & 7;
                    const __half* src = W + (tap + 1) * 16384 + (mt * 64 + m) * 64 + v * 8;
                    cp16(smb + SA_OFF + nb * SA_BUF + m * 144 + v * 16, src);
                }
                CP_COMMIT();
            }

            const int dy = tap / 3, dx = tap - dy * 3;
            const int ylocal = wn >> 1, xlocal = (wn & 1) * 32;
            const int prow_base = (ylocal + dy) * TROW + xlocal + dx;
            const uint32_t aBase = smb + SA_OFF + (tap & 1) * SA_BUF;
            const uint32_t bBase = smb + SB_OFF;

            #pragma unroll
            for (int ks = 0; ks < 4; ks++) {
                unsigned bfr[2][4];
                #pragma unroll
                for (int p2 = 0; p2 < 2; p2++)
                    ldm_x4(bfr[p2], bBase + (prow_base + p2 * 16 + b_row_l) * 144
                                          + (ks * 16 + b_col_l) * 2);
                unsigned afr[2][4];
                #pragma unroll
                for (int mi = 0; mi < 2; mi++)
                    ldm_x4(afr[mi], aBase + (wm * 32 + mi * 16 + a_row_l) * 144
                                          + (a_col_l + ks * 16) * 2);
                #pragma unroll
                for (int p2 = 0; p2 < 2; p2++)
                    #pragma unroll
                    for (int mi = 0; mi < 2; mi++) {
                        mma16816(acc[mi][2 * p2],     afr[mi], bfr[p2][0], bfr[p2][1]);
                        mma16816(acc[mi][2 * p2 + 1], afr[mi], bfr[p2][2], bfr[p2][3]);
                    }
            }
        }
    }

    // ---- epilogue ----
    __syncthreads();   // all mma done; safe to overwrite A/B smem with sE
    const int gr = lane >> 2, ci = lane & 3;
    #pragma unroll
    for (int mi = 0; mi < 2; mi++)
        #pragma unroll
        for (int ni = 0; ni < 4; ni++) {
            int r0 = wm * 32 + mi * 16 + gr;
            int n  = wn * 32 + ni * 8 + 2 * ci;
            *(float2*)(sE + r0 * ESTR + n)       = make_float2(acc[mi][ni][0], acc[mi][ni][1]);
            *(float2*)(sE + (r0 + 8) * ESTR + n) = make_float2(acc[mi][ni][2], acc[mi][ni][3]);
        }
    __syncthreads();

    #pragma unroll 1
    for (int ii = 0; ii < 4; ii++) {
        int pl  = lane + 32 * ii;            // 0..127
        int pix = y0 * 64 + pl;
        float xv[9];
        if (A.xp) {
            int y = pix >> 6, xx = pix & 63;
            #pragma unroll
            for (int tap = 0; tap < 9; tap++) {
                int gy = y + tap / 3 - 1, gx = xx + tap % 3 - 1;
                xv[tap] = ((unsigned)gy < 64u && (unsigned)gx < 64u)
                          ? A.xp[((size_t)b * TT + A.t) * 4096 + gy * 64 + gx] : 0.f;
            }
        }
        #pragma unroll 1
        for (int jj = 0; jj < 2; jj++) {
            int col = warp + 8 * jj;          // 0..15 local channel
            int co  = mt * 16 + col;
            int bb  = (b * 64 + co) * 4096 + pix;
            float cold = A.cbuf[bb];
            uint4 v = *(const uint4*)(A.wcb + (((size_t)co << 12) + pix) * 8);
            const __half2* hv = (const __half2*)&v;
            float2 wc01 = __half22float2(hv[0]);
            float2 wc23 = __half22float2(hv[1]);
            float2 bb01 = __half22float2(hv[2]);
            float2 bb23 = __half22float2(hv[3]);
            float pre[4];
            pre[0] = sE[(col * 4 + 0) * ESTR + pl] + wc01.x * cold + bb01.x;
            pre[1] = sE[(col * 4 + 1) * ESTR + pl] + wc01.y * cold + bb01.y;
            pre[2] = sE[(col * 4 + 2) * ESTR + pl] + wc23.x * cold + bb23.x;
            pre[3] = sE[(col * 4 + 3) * ESTR + pl] + wc23.y * cold + bb23.y;
            if (A.xp) {
                #pragma unroll
                for (int g = 0; g < 4; g++) {
                    const float* w9 = A.wx9 + (size_t)(g * 64 + co) * 9;
                    float s0 = 0.f;
                    #pragma unroll
                    for (int tap = 0; tap < 9; tap++) s0 += __ldg(w9 + tap) * xv[tap];
                    pre[g] += s0;
                }
            }
            float ig = sigf(pre[0]);
            float fg = sigf(pre[1]);
            float gg = tanhf_fast(pre[2]);
            float og = sigf(pre[3]);
            float cn = fg * cold + ig * gg;
            A.cbuf[bb] = cn;
            sH[pl * HSTR + col] = __float2half_rn(og * tanhf_fast(cn));
        }
    }
    __syncthreads();

    // copy-out: sH [128 px][16 ch] -> Tout (padded transposed layout)
    // sH row stride = 24 halves = 48 B (16B-aligned) -> uint4 reads legal.
    for (int i = tid; i < 256; i += 256) {
        int px = i >> 1, q = i & 1;
        int pix = y0 * 64 + px;
        int y = pix >> 6, x = pix & 63;
        __half* dst = A.Tout + (((size_t)b * TROW + (y + 1)) * TROW + (x + 1)) * 64
                      + mt * 16 + q * 8;
        *(uint4*)dst = *(const uint4*)(sH + px * HSTR + q * 8);
    }
}

// ---------------------------------------------------------------------------
// Final conv body: active CTAs mt==0 && nt<128.
// ---------------------------------------------------------------------------
__device__ __forceinline__ void final_body(const CellArgs& A, char* smc)
{
    const int nt = blockIdx.x;
    const int mt = blockIdx.y;
    if (mt != 0 || nt >= 128) return;
    float* s_w = (float*)smc;   // 576 floats

    int tid = threadIdx.x;
    for (int i = tid; i < 576; i += 256) {
        int tap = i >> 6, c = i & 63;
        s_w[tap * 64 + c] = A.fw[c * 9 + tap];
    }
    __syncthreads();

    int b  = nt >> 4;
    int pb = nt & 15;
    int pix = pb * 256 + tid;
    int y = pix >> 6, x = pix & 63;
    float sum = A.fb[0];
    #pragma unroll
    for (int tap = 0; tap < 9; tap++) {
        int dy = tap / 3, dx = tap % 3;
        const __half* row =
            A.T0 + (((size_t)b * TROW + (y + dy)) * TROW + (x + dx)) * 64;
        const float* wt = s_w + tap * 64;
        #pragma unroll
        for (int c8 = 0; c8 < 8; c8++) {
            uint4 v = *(const uint4*)(row + c8 * 8);
            const __half* hv = (const __half*)&v;
            #pragma unroll
            for (int k = 0; k < 8; k++)
                sum += wt[c8 * 8 + k] * __half2float(hv[k]);
        }
    }
    A.cbuf[(size_t)b * (PRED * PIX) + A.t * PIX + pix] = sigf(sum);
}

// ---------------------------------------------------------------------------
// Fused dispatcher: grid (256, 4, nz). Slice z=0 runs `a`, z=1 runs `b`.
// ---------------------------------------------------------------------------
__global__ void __launch_bounds__(256, 3)
fused_kernel(CellArgs a, CellArgs b)
{
    extern __shared__ __align__(16) char smc[];
    if (blockIdx.z == 0) {
        if (a.kind == 0)      cell_body(a, smc);
        else if (a.kind == 1) final_body(a, smc);
    } else {
        if (b.kind == 0)      cell_body(b, smc);
        else if (b.kind == 1) final_body(b, smc);
    }
}

// ---------------------------------------------------------------------------
extern "C" void kernel_launch(void* const* d_in, const int* in_sizes, int n_in,
                              void* d_out, int out_size)
{
    const float* x    = (const float*)d_in[0];
    const float* e0Wx = (const float*)d_in[1];
    const float* e0Wh = (const float*)d_in[2];
    const float* e0Wc = (const float*)d_in[3];
    const float* e0b  = (const float*)d_in[4];
    const float* e1Wx = (const float*)d_in[5];
    const float* e1Wh = (const float*)d_in[6];
    const float* e1Wc = (const float*)d_in[7];
    const float* e1b  = (const float*)d_in[8];
    const float* d0Wx = (const float*)d_in[9];
    const float* d0Wh = (const float*)d_in[10];
    const float* d0Wc = (const float*)d_in[11];
    const float* d0b  = (const float*)d_in[12];
    const float* d1Wx = (const float*)d_in[13];
    const float* d1Wh = (const float*)d_in[14];
    const float* d1Wc = (const float*)d_in[15];
    const float* d1b  = (const float*)d_in[16];
    const float* finw = (const float*)d_in[17];
    const float* finb = (const float*)d_in[18];
    float* out = (float*)d_out;

    cudaFuncSetAttribute(fused_kernel,
                         cudaFuncAttributeMaxDynamicSharedMemorySize, SM_TOTAL);

    float* cbuf;
    __half *Tbuf, *Wbuf, *WBbuf;
    cudaGetSymbolAddress((void**)&cbuf, g_c);
    cudaGetSymbolAddress((void**)&Tbuf, g_T);
    cudaGetSymbolAddress((void**)&Wbuf, g_W);
    cudaGetSymbolAddress((void**)&WBbuf, g_WB);

    float* ec0 = cbuf + 0 * (size_t)NST;
    float* ec1 = cbuf + 1 * (size_t)NST;
    float* dc0 = cbuf + 2 * (size_t)NST;
    float* dc1 = cbuf + 3 * (size_t)NST;
    __half* Te0[2] = { Tbuf + 0 * TSZ, Tbuf + 1 * TSZ };
    __half* Te1[2] = { Tbuf + 2 * TSZ, Tbuf + 3 * TSZ };
    __half* Td0[2] = { Tbuf + 4 * TSZ, Tbuf + 5 * TSZ };
    __half* Td1[2] = { Tbuf + 6 * TSZ, Tbuf + 7 * TSZ };
    __half* W_e0h = Wbuf + 0 * (size_t)WSZ;
    __half* W_e1x = Wbuf + 1 * (size_t)WSZ;
    __half* W_e1h = Wbuf + 2 * (size_t)WSZ;
    __half* W_d0x = Wbuf + 3 * (size_t)WSZ;
    __half* W_d0h = Wbuf + 4 * (size_t)WSZ;
    __half* W_d1x = Wbuf + 5 * (size_t)WSZ;
    __half* W_d1h = Wbuf + 6 * (size_t)WSZ;
    __half* WB_e0 = WBbuf + 0 * (size_t)WBSZ;
    __half* WB_e1 = WBbuf + 1 * (size_t)WBSZ;
    __half* WB_d0 = WBbuf + 2 * (size_t)WBSZ;
    __half* WB_d1 = WBbuf + 3 * (size_t)WBSZ;

    {
        dim3 wgrid((WSZ + 255) / 256, 1, 7);
        wsplit_kernel<<<wgrid, 256>>>(e0Wh, e1Wx, e1Wh, d0Wx, d0Wh, d1Wx, d1Wh, Wbuf);
        dim3 pgrid((64 * 4096 + 255) / 256, 1, 4);
        wcpack_kernel<<<pgrid, 256>>>(e0Wc, e0b, e1Wc, e1b, d0Wc, d0b, d1Wc, d1b, WBbuf);
    }
    cudaMemsetAsync(cbuf, 0, (size_t)4 * NST * sizeof(float));
    cudaMemsetAsync(Tbuf, 0, (size_t)8 * TSZ * sizeof(__half));

    auto cellArgs = [&](const __half* T0, const __half* W0, const __half* T1,
                        const __half* W1, int nsrc, const __half* wcb,
                        float* cb, __half* To, const float* xp, const float* wx9, int t) {
        CellArgs a;
        a.T0 = T0; a.W0 = W0; a.T1 = T1; a.W1 = W1; a.nsrc = nsrc;
        a.wcb = wcb; a.fw = nullptr; a.fb = nullptr; a.cbuf = cb; a.Tout = To;
        a.xp = xp; a.wx9 = wx9; a.t = t; a.kind = 0;
        return a;
    };
    auto finalArgs = [&](const __half* T, int t) {
        CellArgs a;
        a.T0 = T; a.W0 = nullptr; a.T1 = nullptr; a.W1 = nullptr; a.nsrc = 0;
        a.wcb = nullptr; a.fw = finw; a.fb = finb; a.cbuf = out; a.Tout = nullptr;
        a.xp = nullptr; a.wx9 = nullptr; a.t = t; a.kind = 1;
        return a;
    };
    CellArgs none; none.kind = 2;
    none.T0 = none.T1 = nullptr; none.W0 = none.W1 = nullptr; none.nsrc = 0;
    none.wcb = nullptr; none.fw = none.fb = nullptr; none.cbuf = nullptr;
    none.Tout = nullptr; none.xp = none.wx9 = nullptr; none.t = 0;

    dim3 g1(256, 4, 1), g2(256, 4, 2), gf(128, 1, 1), blk(256);

    auto enc0 = [&](int t) {
        int r = t & 1, w = r ^ 1;
        return cellArgs(Te0[r], W_e0h, Te0[r], W_e0h, 1, WB_e0, ec0, Te0[w], x, e0Wx, t);
    };
    auto enc1 = [&](int t) {
        int r = t & 1, w = r ^ 1;
        return cellArgs(Te0[w], W_e1x, Te1[r], W_e1h, 2, WB_e1, ec1, Te1[w], nullptr, nullptr, 0);
    };
    auto dec0 = [&](int t) {
        int r = t & 1, w = r ^ 1;
        const __half* Ts = (t == 0) ? Te1[0] : Td1[r];
        return cellArgs(Ts, W_d0x, Td0[r], W_d0h, 2, WB_d0, dc0, Td0[w], nullptr, nullptr, 0);
    };
    auto dec1 = [&](int t) {
        int r = t & 1, w = r ^ 1;
        return cellArgs(Td0[w], W_d1x, Td1[r], W_d1h, 2, WB_d1, dc1, Td1[w], nullptr, nullptr, 0);
    };

    // ---- Encoder ----
    fused_kernel<<<g1, blk, SM_TOTAL>>>(enc0(0), none);
    for (int t = 0; t < TT - 1; t++)
        fused_kernel<<<g2, blk, SM_TOTAL>>>(enc1(t), enc0(t + 1));   // independent pair
    fused_kernel<<<g1, blk, SM_TOTAL>>>(enc1(TT - 1), none);
    // final encoder h1 in Te1[0] (t=9: w=0)

    // ---- Decoder ----
    fused_kernel<<<g1, blk, SM_TOTAL>>>(dec0(0), none);
    for (int t = 0; t < PRED; t++) {
        int w = (t & 1) ^ 1;
        fused_kernel<<<g1, blk, SM_TOTAL>>>(dec1(t), none);
        if (t < PRED - 1)
            fused_kernel<<<g2, blk, SM_TOTAL>>>(dec0(t + 1), finalArgs(Td1[w], t)); // read-read on Td1[w]
        else
            fused_kernel<<<gf, blk, SM_TOTAL>>>(finalArgs(Td1[w], t), none);
    }
}

// round 15
// speedup vs baseline: 14.0882x; 1.0170x over previous
#include <cuda_runtime.h>
#include <cuda_fp16.h>
#include <math.h>
#include <stdint.h>

// Problem constants
#define BB   8
#define TT   10
#define HH   64
#define WW   64
#define HID  64
#define PRED 10
#define PIX  (HH*WW)              // 4096
#define NST  (BB*HID*PIX)
#define TROW 66
#define TSZ  ((size_t)BB*TROW*TROW*HID)   // elems of one transposed fp16 tensor
#define WSZ  (9*256*64)           // fp16 weights per tensor
#define WBSZ (64*4096*8)          // packed Wc+bias per cell: [co][px][wc0..3,b0..3]

// ---------------------------------------------------------------------------
// Static scratch
// ---------------------------------------------------------------------------
__device__ float g_c[4][NST];                                   // c states
__device__ __align__(16) __half g_T[4][2 * BB*TROW*TROW*HID];   // h, ping-pong
__device__ __align__(16) __half g_W[7][WSZ];
__device__ __align__(16) __half g_WB[4][WBSZ];                  // packed Wc|bias

// ---------------------------------------------------------------------------
// Weight transform: w (256,64,3,3) -> wt[tap][m][k] fp16, m = co*4 + g.
// ---------------------------------------------------------------------------
__global__ void wsplit_kernel(const float* w0, const float* w1, const float* w2,
                              const float* w3, const float* w4, const float* w5,
                              const float* w6, __half* __restrict__ wt_base)
{
    int i = blockIdx.x * blockDim.x + threadIdx.x;
    if (i >= WSZ) return;
    int z = blockIdx.z;
    const float* w;
    switch (z) {
        case 0: w = w0; break;  case 1: w = w1; break;
        case 2: w = w2; break;  case 3: w = w3; break;
        case 4: w = w4; break;  case 5: w = w5; break;
        default: w = w6; break;
    }
    __half* wt = wt_base + (size_t)z * WSZ;
    int c   = i & 63;
    int m   = (i >> 6) & 255;
    int tap = i >> 14;
    int co = m >> 2, g = m & 3;
    wt[i] = __float2half_rn(w[((g * 64 + co) * 64 + c) * 9 + tap]);
}

// ---------------------------------------------------------------------------
// Pack Wc + bias -> [co][px][wc0..3,b0..3] fp16 (one LDG.128 in epilogue)
// ---------------------------------------------------------------------------
__global__ void wcpack_kernel(const float* wc0, const float* b0,
                              const float* wc1, const float* b1,
                              const float* wc2, const float* b2,
                              const float* wc3, const float* b3,
                              __half* __restrict__ out_base)
{
    int i = blockIdx.x * blockDim.x + threadIdx.x;   // over 64*4096
    if (i >= 64 * 4096) return;
    int z = blockIdx.z;
    const float *wc, *bi;
    switch (z) {
        case 0: wc = wc0; bi = b0; break;
        case 1: wc = wc1; bi = b1; break;
        case 2: wc = wc2; bi = b2; break;
        default: wc = wc3; bi = b3; break;
    }
    __half* out = out_base + (size_t)z * WBSZ;
    int px = i & 4095;
    int co = i >> 12;
    __half* dst = out + (size_t)i * 8;
    #pragma unroll
    for (int g = 0; g < 4; g++) {
        dst[g]     = __float2half_rn(wc[(g * 64 + co) * 4096 + px]);
        dst[4 + g] = __float2half_rn(bi[(g * 64 + co) * 4096 + px]);
    }
}

// ---------------------------------------------------------------------------
// low-level helpers
// ---------------------------------------------------------------------------
__device__ __forceinline__ uint32_t smem_u32(const void* p) {
    uint32_t a;
    asm("{ .reg .u64 t; cvta.to.shared.u64 t, %1; cvt.u32.u64 %0, t; }" : "=r"(a) : "l"(p));
    return a;
}
__device__ __forceinline__ void cp16(uint32_t dst, const void* src) {
    asm volatile("cp.async.cg.shared.global [%0], [%1], 16;" :: "r"(dst), "l"(src));
}
#define CP_COMMIT() asm volatile("cp.async.commit_group;" ::: "memory")
#define CP_WAIT0()  asm volatile("cp.async.wait_group 0;" ::: "memory")

__device__ __forceinline__ void ldm_x4(unsigned* r, uint32_t addr) {
    asm volatile("ldmatrix.sync.aligned.m8n8.x4.shared.b16 {%0,%1,%2,%3}, [%4];"
        : "=r"(r[0]), "=r"(r[1]), "=r"(r[2]), "=r"(r[3]) : "r"(addr));
}
__device__ __forceinline__ void mma16816(float* d, const unsigned* a,
                                         unsigned b0, unsigned b1)
{
    asm("mma.sync.aligned.m16n8k16.row.col.f32.f16.f16.f32 "
        "{%0,%1,%2,%3}, {%4,%5,%6,%7}, {%8,%9}, {%0,%1,%2,%3};"
        : "+f"(d[0]), "+f"(d[1]), "+f"(d[2]), "+f"(d[3])
        : "r"(a[0]), "r"(a[1]), "r"(a[2]), "r"(a[3]), "r"(b0), "r"(b1));
}

// Fast activations (EX2/RCP)
__device__ __forceinline__ float ex2f(float x) {
    float r; asm("ex2.approx.f32 %0, %1;" : "=f"(r) : "f"(x)); return r;
}
__device__ __forceinline__ float rcpf(float x) {
    float r; asm("rcp.approx.f32 %0, %1;" : "=f"(r) : "f"(x)); return r;
}
#define LOG2E 1.4426950408889634f
__device__ __forceinline__ float sigf(float v) {
    return rcpf(1.f + ex2f(-v * LOG2E));
}
__device__ __forceinline__ float tanhf_fast(float v) {
    return 1.f - 2.f * rcpf(1.f + ex2f(2.f * LOG2E * v));
}

// SMEM layout (bytes), sized for 4 CTAs/SM (M=64 tile):
//   A tiles: 2 bufs x 64 rows x 144B = 18432   [0 .. 18432)
//   B tile : 264 rows x 144B         = 38016   [18432 .. 56448)
//   Epilogue OVERLAYS the A+B region (all mma reads done by then):
//     sE: 64 gate-rows x 136 f32 = 34816      [0 .. 34816)
//     sH: 128 px x 24 fp16 = 6144             [34816 .. 40960)
#define SA_OFF   0
#define SA_BUF   9216
#define SB_OFF   18432
#define SH_OFF   34816
#define SM_TOTAL 56448
#define ESTR     136
#define HSTR     24

// ---------------------------------------------------------------------------
// Work descriptor
// ---------------------------------------------------------------------------
struct CellArgs {
    const __half* T0;
    const __half* W0;
    const __half* T1;
    const __half* W1;
    int nsrc;
    const __half* wcb;
    const float*  fw;
    const float*  fb;
    float*        cbuf;
    __half*       Tout;
    const float*  xp;
    const float*  wx9;
    int t;
    int kind;           // 0 = cell, 1 = final conv, 2 = none
};

// ---------------------------------------------------------------------------
// Cell body. CTA: M=64 gate-rows (mt 0..3 -> channels mt*16..mt*16+15),
// N=128 px (2 image rows of one batch). 8 warps: wm {0,1} x wn {0..3};
// warp tile 32m x 32n. 4 CTAs/SM.
// ---------------------------------------------------------------------------
__device__ __forceinline__ void cell_body(const CellArgs& A, char* smc)
{
    const uint32_t smb = smem_u32(smc);
    float*  sE = (float*)smc;
    __half* sH = (__half*)(smc + SH_OFF);

    const int tid  = threadIdx.x;
    const int lane = tid & 31;
    const int warp = tid >> 5;
    const int wm   = warp >> 2;      // 0..1 (m half: wm*32)
    const int wn   = warp & 3;       // 0..3
    const int nt   = blockIdx.x;     // 0..255
    const int mt   = blockIdx.y;     // 0..3
    const int b    = nt >> 5;
    const int y0   = (nt & 31) << 1; // first of 2 image rows

    const int a_row_l = lane & 15;
    const int a_col_l = (lane >> 4) * 8;
    const int b_row_l = (lane & 7) + ((lane >> 4) << 3);
    const int b_col_l = ((lane >> 3) & 1) * 8;

    float acc[2][4][4];
    #pragma unroll
    for (int mi = 0; mi < 2; mi++)
        #pragma unroll
        for (int ni = 0; ni < 4; ni++)
            #pragma unroll
            for (int r = 0; r < 4; r++) acc[mi][ni][r] = 0.f;

    for (int s = 0; s < A.nsrc; s++) {
        const __half* T = s ? A.T1 : A.T0;
        const __half* W = s ? A.W1 : A.W0;

        __syncthreads();
        // fill B: 264 padded rows x 8 vec16
        for (int i = tid; i < 2112; i += 256) {
            int p = i >> 3, v = i & 7;
            int r = p / TROW, px = p - r * TROW;
            const __half* src =
                T + (((size_t)b * TROW + (y0 + r)) * TROW + px) * 64 + v * 8;
            cp16(smb + SB_OFF + p * 144 + v * 16, src);
        }
        // fill A tap0: 64 rows x 8 vec16
        for (int i = tid; i < 512; i += 256) {
            int m = i >> 3, v = i & 7;
            const __half* src = W + (mt * 64 + m) * 64 + v * 8;
            cp16(smb + SA_OFF + m * 144 + v * 16, src);
        }
        CP_COMMIT();

        for (int tap = 0; tap < 9; tap++) {
            CP_WAIT0();
            __syncthreads();
            if (tap < 8) {
                const int nb = (tap + 1) & 1;
                for (int i = tid; i < 512; i += 256) {
                    int m = i >> 3, v = i & 7;
                    const __half* src = W + (tap + 1) * 16384 + (mt * 64 + m) * 64 + v * 8;
                    cp16(smb + SA_OFF + nb * SA_BUF + m * 144 + v * 16, src);
                }
                CP_COMMIT();
            }

            const int dy = tap / 3, dx = tap - dy * 3;
            const int ylocal = wn >> 1, xlocal = (wn & 1) * 32;
            const int prow_base = (ylocal + dy) * TROW + xlocal + dx;
            const uint32_t aBase = smb + SA_OFF + (tap & 1) * SA_BUF;
            const uint32_t bBase = smb + SB_OFF;

            #pragma unroll
            for (int ks = 0; ks < 4; ks++) {
                unsigned bfr[2][4];
                #pragma unroll
                for (int p2 = 0; p2 < 2; p2++)
                    ldm_x4(bfr[p2], bBase + (prow_base + p2 * 16 + b_row_l) * 144
                                          + (ks * 16 + b_col_l) * 2);
                unsigned afr[2][4];
                #pragma unroll
                for (int mi = 0; mi < 2; mi++)
                    ldm_x4(afr[mi], aBase + (wm * 32 + mi * 16 + a_row_l) * 144
                                          + (a_col_l + ks * 16) * 2);
                #pragma unroll
                for (int p2 = 0; p2 < 2; p2++)
                    #pragma unroll
                    for (int mi = 0; mi < 2; mi++) {
                        mma16816(acc[mi][2 * p2],     afr[mi], bfr[p2][0], bfr[p2][1]);
                        mma16816(acc[mi][2 * p2 + 1], afr[mi], bfr[p2][2], bfr[p2][3]);
                    }
            }
        }
    }

    // ---- epilogue (sE and sH both overlay the A+B region; mma is done) ----
    __syncthreads();
    const int gr = lane >> 2, ci = lane & 3;
    #pragma unroll
    for (int mi = 0; mi < 2; mi++)
        #pragma unroll
        for (int ni = 0; ni < 4; ni++) {
            int r0 = wm * 32 + mi * 16 + gr;
            int n  = wn * 32 + ni * 8 + 2 * ci;
            *(float2*)(sE + r0 * ESTR + n)       = make_float2(acc[mi][ni][0], acc[mi][ni][1]);
            *(float2*)(sE + (r0 + 8) * ESTR + n) = make_float2(acc[mi][ni][2], acc[mi][ni][3]);
        }
    __syncthreads();

    #pragma unroll 1
    for (int ii = 0; ii < 4; ii++) {
        int pl  = lane + 32 * ii;            // 0..127
        int pix = y0 * 64 + pl;
        float xv[9];
        if (A.xp) {
            int y = pix >> 6, xx = pix & 63;
            #pragma unroll
            for (int tap = 0; tap < 9; tap++) {
                int gy = y + tap / 3 - 1, gx = xx + tap % 3 - 1;
                xv[tap] = ((unsigned)gy < 64u && (unsigned)gx < 64u)
                          ? A.xp[((size_t)b * TT + A.t) * 4096 + gy * 64 + gx] : 0.f;
            }
        }
        #pragma unroll 1
        for (int jj = 0; jj < 2; jj++) {
            int col = warp + 8 * jj;          // 0..15 local channel
            int co  = mt * 16 + col;
            int bb  = (b * 64 + co) * 4096 + pix;
            float cold = A.cbuf[bb];
            uint4 v = *(const uint4*)(A.wcb + (((size_t)co << 12) + pix) * 8);
            const __half2* hv = (const __half2*)&v;
            float2 wc01 = __half22float2(hv[0]);
            float2 wc23 = __half22float2(hv[1]);
            float2 bb01 = __half22float2(hv[2]);
            float2 bb23 = __half22float2(hv[3]);
            float pre[4];
            pre[0] = sE[(col * 4 + 0) * ESTR + pl] + wc01.x * cold + bb01.x;
            pre[1] = sE[(col * 4 + 1) * ESTR + pl] + wc01.y * cold + bb01.y;
            pre[2] = sE[(col * 4 + 2) * ESTR + pl] + wc23.x * cold + bb23.x;
            pre[3] = sE[(col * 4 + 3) * ESTR + pl] + wc23.y * cold + bb23.y;
            if (A.xp) {
                #pragma unroll
                for (int g = 0; g < 4; g++) {
                    const float* w9 = A.wx9 + (size_t)(g * 64 + co) * 9;
                    float s0 = 0.f;
                    #pragma unroll
                    for (int tap = 0; tap < 9; tap++) s0 += __ldg(w9 + tap) * xv[tap];
                    pre[g] += s0;
                }
            }
            float ig = sigf(pre[0]);
            float fg = sigf(pre[1]);
            float gg = tanhf_fast(pre[2]);
            float og = sigf(pre[3]);
            float cn = fg * cold + ig * gg;
            A.cbuf[bb] = cn;
            sH[pl * HSTR + col] = __float2half_rn(og * tanhf_fast(cn));
        }
    }
    __syncthreads();

    // copy-out: sH [128 px][16 ch] -> Tout (padded transposed layout)
    // sH row stride = 24 halves = 48 B (16B-aligned) -> uint4 reads legal.
    for (int i = tid; i < 256; i += 256) {
        int px = i >> 1, q = i & 1;
        int pix = y0 * 64 + px;
        int y = pix >> 6, x = pix & 63;
        __half* dst = A.Tout + (((size_t)b * TROW + (y + 1)) * TROW + (x + 1)) * 64
                      + mt * 16 + q * 8;
        *(uint4*)dst = *(const uint4*)(sH + px * HSTR + q * 8);
    }
}

// ---------------------------------------------------------------------------
// Final conv body: active CTAs mt==0 && nt<128.
// ---------------------------------------------------------------------------
__device__ __forceinline__ void final_body(const CellArgs& A, char* smc)
{
    const int nt = blockIdx.x;
    const int mt = blockIdx.y;
    if (mt != 0 || nt >= 128) return;
    float* s_w = (float*)smc;   // 576 floats

    int tid = threadIdx.x;
    for (int i = tid; i < 576; i += 256) {
        int tap = i >> 6, c = i & 63;
        s_w[tap * 64 + c] = A.fw[c * 9 + tap];
    }
    __syncthreads();

    int b  = nt >> 4;
    int pb = nt & 15;
    int pix = pb * 256 + tid;
    int y = pix >> 6, x = pix & 63;
    float sum = A.fb[0];
    #pragma unroll
    for (int tap = 0; tap < 9; tap++) {
        int dy = tap / 3, dx = tap % 3;
        const __half* row =
            A.T0 + (((size_t)b * TROW + (y + dy)) * TROW + (x + dx)) * 64;
        const float* wt = s_w + tap * 64;
        #pragma unroll
        for (int c8 = 0; c8 < 8; c8++) {
            uint4 v = *(const uint4*)(row + c8 * 8);
            const __half* hv = (const __half*)&v;
            #pragma unroll
            for (int k = 0; k < 8; k++)
                sum += wt[c8 * 8 + k] * __half2float(hv[k]);
        }
    }
    A.cbuf[(size_t)b * (PRED * PIX) + A.t * PIX + pix] = sigf(sum);
}

// ---------------------------------------------------------------------------
// Fused dispatcher: grid (256, 4, nz). Slice z=0 runs `a`, z=1 runs `b`.
// ---------------------------------------------------------------------------
__global__ void __launch_bounds__(256, 4)
fused_kernel(CellArgs a, CellArgs b)
{
    extern __shared__ __align__(16) char smc[];
    if (blockIdx.z == 0) {
        if (a.kind == 0)      cell_body(a, smc);
        else if (a.kind == 1) final_body(a, smc);
    } else {
        if (b.kind == 0)      cell_body(b, smc);
        else if (b.kind == 1) final_body(b, smc);
    }
}

// ---------------------------------------------------------------------------
extern "C" void kernel_launch(void* const* d_in, const int* in_sizes, int n_in,
                              void* d_out, int out_size)
{
    const float* x    = (const float*)d_in[0];
    const float* e0Wx = (const float*)d_in[1];
    const float* e0Wh = (const float*)d_in[2];
    const float* e0Wc = (const float*)d_in[3];
    const float* e0b  = (const float*)d_in[4];
    const float* e1Wx = (const float*)d_in[5];
    const float* e1Wh = (const float*)d_in[6];
    const float* e1Wc = (const float*)d_in[7];
    const float* e1b  = (const float*)d_in[8];
    const float* d0Wx = (const float*)d_in[9];
    const float* d0Wh = (const float*)d_in[10];
    const float* d0Wc = (const float*)d_in[11];
    const float* d0b  = (const float*)d_in[12];
    const float* d1Wx = (const float*)d_in[13];
    const float* d1Wh = (const float*)d_in[14];
    const float* d1Wc = (const float*)d_in[15];
    const float* d1b  = (const float*)d_in[16];
    const float* finw = (const float*)d_in[17];
    const float* finb = (const float*)d_in[18];
    float* out = (float*)d_out;

    cudaFuncSetAttribute(fused_kernel,
                         cudaFuncAttributeMaxDynamicSharedMemorySize, SM_TOTAL);

    float* cbuf;
    __half *Tbuf, *Wbuf, *WBbuf;
    cudaGetSymbolAddress((void**)&cbuf, g_c);
    cudaGetSymbolAddress((void**)&Tbuf, g_T);
    cudaGetSymbolAddress((void**)&Wbuf, g_W);
    cudaGetSymbolAddress((void**)&WBbuf, g_WB);

    float* ec0 = cbuf + 0 * (size_t)NST;
    float* ec1 = cbuf + 1 * (size_t)NST;
    float* dc0 = cbuf + 2 * (size_t)NST;
    float* dc1 = cbuf + 3 * (size_t)NST;
    __half* Te0[2] = { Tbuf + 0 * TSZ, Tbuf + 1 * TSZ };
    __half* Te1[2] = { Tbuf + 2 * TSZ, Tbuf + 3 * TSZ };
    __half* Td0[2] = { Tbuf + 4 * TSZ, Tbuf + 5 * TSZ };
    __half* Td1[2] = { Tbuf + 6 * TSZ, Tbuf + 7 * TSZ };
    __half* W_e0h = Wbuf + 0 * (size_t)WSZ;
    __half* W_e1x = Wbuf + 1 * (size_t)WSZ;
    __half* W_e1h = Wbuf + 2 * (size_t)WSZ;
    __half* W_d0x = Wbuf + 3 * (size_t)WSZ;
    __half* W_d0h = Wbuf + 4 * (size_t)WSZ;
    __half* W_d1x = Wbuf + 5 * (size_t)WSZ;
    __half* W_d1h = Wbuf + 6 * (size_t)WSZ;
    __half* WB_e0 = WBbuf + 0 * (size_t)WBSZ;
    __half* WB_e1 = WBbuf + 1 * (size_t)WBSZ;
    __half* WB_d0 = WBbuf + 2 * (size_t)WBSZ;
    __half* WB_d1 = WBbuf + 3 * (size_t)WBSZ;

    {
        dim3 wgrid((WSZ + 255) / 256, 1, 7);
        wsplit_kernel<<<wgrid, 256>>>(e0Wh, e1Wx, e1Wh, d0Wx, d0Wh, d1Wx, d1Wh, Wbuf);
        dim3 pgrid((64 * 4096 + 255) / 256, 1, 4);
        wcpack_kernel<<<pgrid, 256>>>(e0Wc, e0b, e1Wc, e1b, d0Wc, d0b, d1Wc, d1b, WBbuf);
    }
    cudaMemsetAsync(cbuf, 0, (size_t)4 * NST * sizeof(float));
    cudaMemsetAsync(Tbuf, 0, (size_t)8 * TSZ * sizeof(__half));

    auto cellArgs = [&](const __half* T0, const __half* W0, const __half* T1,
                        const __half* W1, int nsrc, const __half* wcb,
                        float* cb, __half* To, const float* xp, const float* wx9, int t) {
        CellArgs a;
        a.T0 = T0; a.W0 = W0; a.T1 = T1; a.W1 = W1; a.nsrc = nsrc;
        a.wcb = wcb; a.fw = nullptr; a.fb = nullptr; a.cbuf = cb; a.Tout = To;
        a.xp = xp; a.wx9 = wx9; a.t = t; a.kind = 0;
        return a;
    };
    auto finalArgs = [&](const __half* T, int t) {
        CellArgs a;
        a.T0 = T; a.W0 = nullptr; a.T1 = nullptr; a.W1 = nullptr; a.nsrc = 0;
        a.wcb = nullptr; a.fw = finw; a.fb = finb; a.cbuf = out; a.Tout = nullptr;
        a.xp = nullptr; a.wx9 = nullptr; a.t = t; a.kind = 1;
        return a;
    };
    CellArgs none; none.kind = 2;
    none.T0 = none.T1 = nullptr; none.W0 = none.W1 = nullptr; none.nsrc = 0;
    none.wcb = nullptr; none.fw = none.fb = nullptr; none.cbuf = nullptr;
    none.Tout = nullptr; none.xp = none.wx9 = nullptr; none.t = 0;

    dim3 g1(256, 4, 1), g2(256, 4, 2), gf(128, 1, 1), blk(256);

    auto enc0 = [&](int t) {
        int r = t & 1, w = r ^ 1;
        return cellArgs(Te0[r], W_e0h, Te0[r], W_e0h, 1, WB_e0, ec0, Te0[w], x, e0Wx, t);
    };
    auto enc1 = [&](int t) {
        int r = t & 1, w = r ^ 1;
        return cellArgs(Te0[w], W_e1x, Te1[r], W_e1h, 2, WB_e1, ec1, Te1[w], nullptr, nullptr, 0);
    };
    auto dec0 = [&](int t) {
        int r = t & 1, w = r ^ 1;
        const __half* Ts = (t == 0) ? Te1[0] : Td1[r];
        return cellArgs(Ts, W_d0x, Td0[r], W_d0h, 2, WB_d0, dc0, Td0[w], nullptr, nullptr, 0);
    };
    auto dec1 = [&](int t) {
        int r = t & 1, w = r ^ 1;
        return cellArgs(Td0[w], W_d1x, Td1[r], W_d1h, 2, WB_d1, dc1, Td1[w], nullptr, nullptr, 0);
    };

    // ---- Encoder ----
    fused_kernel<<<g1, blk, SM_TOTAL>>>(enc0(0), none);
    for (int t = 0; t < TT - 1; t++)
        fused_kernel<<<g2, blk, SM_TOTAL>>>(enc1(t), enc0(t + 1));   // independent pair
    fused_kernel<<<g1, blk, SM_TOTAL>>>(enc1(TT - 1), none);
    // final encoder h1 in Te1[0] (t=9: w=0)

    // ---- Decoder ----
    fused_kernel<<<g1, blk, SM_TOTAL>>>(dec0(0), none);
    for (int t = 0; t < PRED; t++) {
        int w = (t & 1) ^ 1;
        fused_kernel<<<g1, blk, SM_TOTAL>>>(dec1(t), none);
        if (t < PRED - 1)
            fused_kernel<<<g2, blk, SM_TOTAL>>>(dec0(t + 1), finalArgs(Td1[w], t)); // read-read on Td1[w]
        else
            fused_kernel<<<gf, blk, SM_TOTAL>>>(finalArgs(Td1[w], t), none);
    }
}